// round 3
// baseline (speedup 1.0000x reference)
#include <cuda_runtime.h>
#include <math_constants.h>
#include <cstdint>

#define SEQ   2048
#define DMODEL 1024
#define NH    16
#define DH    64
#define BATCH 2
#define MTOT  (BATCH*SEQ)   // 4096 rows total

// Scratch (device globals: allocation-free rule)
__device__ float g_Q[(size_t)MTOT*DMODEL];
__device__ float g_K[(size_t)MTOT*DMODEL];
__device__ float g_V[(size_t)MTOT*DMODEL];
__device__ float g_O[(size_t)MTOT*DMODEL];

// ---------------------------------------------------------------------------
// Fast exp: FFMA-only (avoids MUFU.EX2 throughput wall: 134M exps in softmax)
// exp(x) = 2^(x*log2e); args are always <= 0 here.
// ---------------------------------------------------------------------------
__device__ __forceinline__ float fexp(float x) {
    float y = x * 1.4426950408889634f;
    y = fmaxf(y, -126.0f);                 // flush to ~0 for very negative
    int   e = __float2int_rn(y);
    float f = y - (float)e;                // f in [-0.5, 0.5]
    float p = 1.3333558146e-3f;
    p = fmaf(p, f, 9.6181298421e-3f);
    p = fmaf(p, f, 5.5504108664e-2f);
    p = fmaf(p, f, 2.4022650696e-1f);
    p = fmaf(p, f, 6.9314718056e-1f);
    p = fmaf(p, f, 1.0f);
    return p * __int_as_float((e + 127) << 23);
}

// ---------------------------------------------------------------------------
// SGEMM: C[M,N] = A[M,K] * B[K,N], row-major. K=N=1024 fixed, M=4096.
// 128x128 block tile, BK=16, 256 threads, 8x8 micro-tile, 2-stage smem
// double buffering (one barrier per K-tile, loads overlap compute).
// ---------------------------------------------------------------------------
#define BM 128
#define BN 128
#define BK 16
#define TM 8
#define TN 8

__global__ __launch_bounds__(256) void sgemm_kernel(const float* __restrict__ A,
                                                    const float* __restrict__ B,
                                                    float* __restrict__ C) {
    const int K = 1024, N = 1024;
    __shared__ float As[2][BK][BM + 4];   // transposed A tile, padded
    __shared__ float Bs[2][BK][BN];

    const int t  = threadIdx.x;
    const int tx = t & 15;
    const int ty = t >> 4;
    const int m0 = blockIdx.y * BM;
    const int n0 = blockIdx.x * BN;

    // Per-thread load coordinates (2 float4 each for A and B)
    const int aRow0 = t >> 2,        aC4_0 = t & 3;
    const int aRow1 = (t + 256) >> 2, aC4_1 = (t + 256) & 3;
    const int bRow0 = t >> 5,        bC4_0 = t & 31;
    const int bRow1 = (t + 256) >> 5, bC4_1 = (t + 256) & 31;

    float acc[TM][TN];
    #pragma unroll
    for (int i = 0; i < TM; i++)
        #pragma unroll
        for (int j = 0; j < TN; j++) acc[i][j] = 0.f;

    auto load_tile = [&](int kt, int buf) {
        float4 va0 = *(const float4*)(A + (size_t)(m0 + aRow0) * K + kt + aC4_0 * 4);
        float4 va1 = *(const float4*)(A + (size_t)(m0 + aRow1) * K + kt + aC4_1 * 4);
        float4 vb0 = *(const float4*)(B + (size_t)(kt + bRow0) * N + n0 + bC4_0 * 4);
        float4 vb1 = *(const float4*)(B + (size_t)(kt + bRow1) * N + n0 + bC4_1 * 4);
        As[buf][aC4_0 * 4 + 0][aRow0] = va0.x;
        As[buf][aC4_0 * 4 + 1][aRow0] = va0.y;
        As[buf][aC4_0 * 4 + 2][aRow0] = va0.z;
        As[buf][aC4_0 * 4 + 3][aRow0] = va0.w;
        As[buf][aC4_1 * 4 + 0][aRow1] = va1.x;
        As[buf][aC4_1 * 4 + 1][aRow1] = va1.y;
        As[buf][aC4_1 * 4 + 2][aRow1] = va1.z;
        As[buf][aC4_1 * 4 + 3][aRow1] = va1.w;
        *(float4*)(&Bs[buf][bRow0][bC4_0 * 4]) = vb0;
        *(float4*)(&Bs[buf][bRow1][bC4_1 * 4]) = vb1;
    };

    int buf = 0;
    load_tile(0, buf);
    __syncthreads();

    for (int kt = 0; kt < K; kt += BK) {
        if (kt + BK < K) load_tile(kt + BK, buf ^ 1);   // overlaps compute below

        #pragma unroll
        for (int k = 0; k < BK; k++) {
            float a[TM], b[TN];
            #pragma unroll
            for (int i = 0; i < TM; i += 4)
                *(float4*)(a + i) = *(const float4*)(&As[buf][k][ty * TM + i]);
            #pragma unroll
            for (int j = 0; j < TN; j += 4)
                *(float4*)(b + j) = *(const float4*)(&Bs[buf][k][tx * TN + j]);
            #pragma unroll
            for (int i = 0; i < TM; i++)
                #pragma unroll
                for (int j = 0; j < TN; j++)
                    acc[i][j] = fmaf(a[i], b[j], acc[i][j]);
        }
        __syncthreads();
        buf ^= 1;
    }

    #pragma unroll
    for (int i = 0; i < TM; i++) {
        #pragma unroll
        for (int j = 0; j < TN; j += 4) {
            float4 v = make_float4(acc[i][j], acc[i][j+1], acc[i][j+2], acc[i][j+3]);
            *(float4*)(C + (size_t)(m0 + ty * TM + i) * N + n0 + tx * TN + j) = v;
        }
    }
}

// ---------------------------------------------------------------------------
// Flash-style attention: one thread per query row. Block = 128 q-rows.
// K/V tiles of 64 keys in shared memory. Online softmax with conditional
// (rare) O-rescale; masked keys get -1e30 additive bias.
// ---------------------------------------------------------------------------
#define QT 128
#define KT 64

__global__ __launch_bounds__(128) void attn_kernel(const int* __restrict__ masks) {
    __shared__ float Ks[KT][DH];
    __shared__ float Vs[KT][DH];
    __shared__ float msf[KT];

    const int t = threadIdx.x;
    const int b = blockIdx.z;
    const int h = blockIdx.y;
    const int r = blockIdx.x * QT + t;     // query row within sequence

    const float* Qp = g_Q + ((size_t)(b * SEQ + r)) * DMODEL + h * DH;

    float q[DH], o[DH];
    #pragma unroll
    for (int i = 0; i < DH; i += 4)
        *(float4*)(q + i) = *(const float4*)(Qp + i);
    #pragma unroll
    for (int i = 0; i < DH; i++) o[i] = 0.f;

    float m = -CUDART_INF_F;
    float l = 0.f;

    for (int kt = 0; kt < SEQ; kt += KT) {
        __syncthreads();   // previous tile fully consumed
        const float* Kp = g_K + ((size_t)(b * SEQ + kt)) * DMODEL + h * DH;
        const float* Vp = g_V + ((size_t)(b * SEQ + kt)) * DMODEL + h * DH;
        // 64x64 floats = 1024 float4 per tensor; 8 per thread
        #pragma unroll
        for (int l2 = 0; l2 < 8; l2++) {
            int idx = l2 * 128 + t;
            int row = idx >> 4;
            int c4  = idx & 15;
            *(float4*)(&Ks[row][c4 * 4]) = *(const float4*)(Kp + (size_t)row * DMODEL + c4 * 4);
            *(float4*)(&Vs[row][c4 * 4]) = *(const float4*)(Vp + (size_t)row * DMODEL + c4 * 4);
        }
        if (t < KT) msf[t] = masks[b * SEQ + kt + t] ? 0.f : -1e30f;
        __syncthreads();

        for (int k = 0; k < KT; k++) {
            float s0 = 0.f, s1 = 0.f, s2 = 0.f, s3 = 0.f;
            #pragma unroll
            for (int i = 0; i < DH; i += 4) {
                s0 = fmaf(q[i    ], Ks[k][i    ], s0);
                s1 = fmaf(q[i + 1], Ks[k][i + 1], s1);
                s2 = fmaf(q[i + 2], Ks[k][i + 2], s2);
                s3 = fmaf(q[i + 3], Ks[k][i + 3], s3);
            }
            float s = (s0 + s1) + (s2 + s3);
            s = fmaf(s, 0.125f, msf[k]);          // * 1/sqrt(64) + mask bias

            if (s > m) {                           // rare after warmup
                float c = fexp(m - s);
                m = s;
                l *= c;
                #pragma unroll
                for (int i = 0; i < DH; i++) o[i] *= c;
            }
            float p = fexp(s - m);
            l += p;
            #pragma unroll
            for (int i = 0; i < DH; i++)
                o[i] = fmaf(p, Vs[k][i], o[i]);
        }
    }

    float inv = 1.0f / l;
    float* Op = g_O + ((size_t)(b * SEQ + r)) * DMODEL + h * DH;
    #pragma unroll
    for (int i = 0; i < DH; i += 4) {
        float4 v = make_float4(o[i] * inv, o[i+1] * inv, o[i+2] * inv, o[i+3] * inv);
        *(float4*)(Op + i) = v;
    }
}

// ---------------------------------------------------------------------------
// Launch
// inputs: 0=queries 1=keys 2=values 3=masks 4=Wq 5=Wk 6=Wv 7=Wo
// ---------------------------------------------------------------------------
extern "C" void kernel_launch(void* const* d_in, const int* in_sizes, int n_in,
                              void* d_out, int out_size) {
    const float* qin   = (const float*)d_in[0];
    const float* kin   = (const float*)d_in[1];
    const float* vin   = (const float*)d_in[2];
    const int*   masks = (const int*)  d_in[3];
    const float* Wq    = (const float*)d_in[4];
    const float* Wk    = (const float*)d_in[5];
    const float* Wv    = (const float*)d_in[6];
    const float* Wo    = (const float*)d_in[7];
    float* out = (float*)d_out;

    float *gq, *gk, *gv, *go;
    cudaGetSymbolAddress((void**)&gq, g_Q);
    cudaGetSymbolAddress((void**)&gk, g_K);
    cudaGetSymbolAddress((void**)&gv, g_V);
    cudaGetSymbolAddress((void**)&go, g_O);

    dim3 gg(DMODEL / BN, MTOT / BM);   // (8, 32)
    sgemm_kernel<<<gg, 256>>>(qin, Wq, gq);
    sgemm_kernel<<<gg, 256>>>(kin, Wk, gk);
    sgemm_kernel<<<gg, 256>>>(vin, Wv, gv);

    dim3 ga(SEQ / QT, NH, BATCH);      // (16, 16, 2)
    attn_kernel<<<ga, 128>>>(masks);

    sgemm_kernel<<<gg, 256>>>(go, Wo, out);
}

// round 6
// speedup vs baseline: 1.1486x; 1.1486x over previous
#include <cuda_runtime.h>
#include <math_constants.h>
#include <cstdint>

#define SEQ    2048
#define DMODEL 1024
#define NH     16
#define DH     64
#define BATCH  2
#define MTOT   (BATCH*SEQ)   // 4096 rows

// ---------------------------------------------------------------------------
// Device scratch (allocation-free rule)
// ---------------------------------------------------------------------------
__device__ float g_Q[(size_t)MTOT*DMODEL];
__device__ float g_K[(size_t)MTOT*DMODEL];
__device__ float g_V[(size_t)MTOT*DMODEL];
__device__ float g_O[(size_t)MTOT*DMODEL];
__device__ float g_Wt[4][(size_t)DMODEL*DMODEL];   // transposed weights [N][K]

// ---------------------------------------------------------------------------
// Helpers
// ---------------------------------------------------------------------------
__device__ __forceinline__ float to_tf32_rn(float x) {
    uint32_t r;                                     // tf32 cvt needs .b32 dst
    asm("cvt.rna.tf32.f32 %0, %1;" : "=r"(r) : "f"(x));
    return __uint_as_float(r);
}

// m16n8k8 tf32 mma (baseline PTX, sm_80+; runs on tensor cores)
__device__ __forceinline__ void mma_tf32(float* c, const uint32_t* a, const uint32_t* b) {
    asm volatile(
        "mma.sync.aligned.m16n8k8.row.col.f32.tf32.tf32.f32 "
        "{%0,%1,%2,%3}, {%4,%5,%6,%7}, {%8,%9}, {%0,%1,%2,%3};"
        : "+f"(c[0]), "+f"(c[1]), "+f"(c[2]), "+f"(c[3])
        : "r"(a[0]), "r"(a[1]), "r"(a[2]), "r"(a[3]), "r"(b[0]), "r"(b[1]));
}

// ---------------------------------------------------------------------------
// Weight transpose: Wt[n][k] = W[k][n] (1024x1024), 4 matrices via blockIdx.z
// ---------------------------------------------------------------------------
struct WPtrs { const float* s[4]; float* d[4]; };

__global__ __launch_bounds__(256) void transpose_k(WPtrs p) {
    __shared__ float tile[32][33];
    const float* S = p.s[blockIdx.z];
    float*       D = p.d[blockIdx.z];
    int x0 = blockIdx.x * 32, y0 = blockIdx.y * 32;
    int tx = threadIdx.x, ty = threadIdx.y;          // (32, 8)
    #pragma unroll
    for (int j = 0; j < 32; j += 8)
        tile[ty + j][tx] = S[(size_t)(y0 + ty + j) * DMODEL + x0 + tx];
    __syncthreads();
    #pragma unroll
    for (int j = 0; j < 32; j += 8)
        D[(size_t)(x0 + ty + j) * DMODEL + y0 + tx] = tile[tx][ty + j];
}

// ---------------------------------------------------------------------------
// tf32 tensor-core GEMM: C[M,N=1024] = A[M,K=1024] * Bt[N,K]^T
// CTA: 128x128, BK=32, 256 threads (8 warps, 2m x 4n, warp tile 64x32).
// Double-buffered smem, rows padded to 36 floats (conflict-free fragments).
// ---------------------------------------------------------------------------
#define BM 128
#define BN 128
#define BK 32
#define KT_GEMM (DMODEL / BK)          // 32
#define ROWP 36                        // padded row stride (floats)
#define STG_F (128 * ROWP)             // floats per tile stage
#define SM_GEMM_BYTES (4 * STG_F * 4 * 2)  // A+B, 2 stages = 73728 B

__global__ __launch_bounds__(256) void gemm_tf32_kernel(const float* __restrict__ A,
                                                        const float* __restrict__ Bt,
                                                        float* __restrict__ C) {
    extern __shared__ float sm[];
    float* As = sm;                    // [2][128][36]
    float* Bs = sm + 2 * STG_F;        // [2][128][36]

    const int t    = threadIdx.x;
    const int wid  = t >> 5;
    const int lane = t & 31;
    const int wm   = wid & 1;          // 0..1  (64-row block)
    const int wn   = wid >> 1;         // 0..3  (32-col block)
    const int lane4 = lane >> 2;       // 0..7
    const int lanek = lane & 3;        // 0..3
    const int m0 = blockIdx.y * BM;
    const int n0 = blockIdx.x * BN;

    float acc[4][4][4];
    #pragma unroll
    for (int mi = 0; mi < 4; mi++)
        #pragma unroll
        for (int ni = 0; ni < 4; ni++)
            #pragma unroll
            for (int f = 0; f < 4; f++) acc[mi][ni][f] = 0.f;

    auto load_tile = [&](int kt, int s) {
        const float* Ap = A + (size_t)m0 * DMODEL + kt * BK;
        const float* Bp = Bt + (size_t)n0 * DMODEL + kt * BK;
        #pragma unroll
        for (int i = 0; i < 4; i++) {
            int idx = i * 256 + t;
            int row = idx >> 3, c4 = idx & 7;
            float4 v = *(const float4*)(Ap + (size_t)row * DMODEL + c4 * 4);
            v.x = to_tf32_rn(v.x); v.y = to_tf32_rn(v.y);
            v.z = to_tf32_rn(v.z); v.w = to_tf32_rn(v.w);
            *(float4*)(As + s * STG_F + row * ROWP + c4 * 4) = v;
        }
        #pragma unroll
        for (int i = 0; i < 4; i++) {
            int idx = i * 256 + t;
            int row = idx >> 3, c4 = idx & 7;
            float4 v = *(const float4*)(Bp + (size_t)row * DMODEL + c4 * 4);
            v.x = to_tf32_rn(v.x); v.y = to_tf32_rn(v.y);
            v.z = to_tf32_rn(v.z); v.w = to_tf32_rn(v.w);
            *(float4*)(Bs + s * STG_F + row * ROWP + c4 * 4) = v;
        }
    };

    load_tile(0, 0);
    __syncthreads();

    for (int kt = 0; kt < KT_GEMM; kt++) {
        const int s = kt & 1;
        if (kt + 1 < KT_GEMM) load_tile(kt + 1, s ^ 1);

        const float* Atile = As + s * STG_F;
        const float* Btile = Bs + s * STG_F;
        #pragma unroll
        for (int ks = 0; ks < 4; ks++) {
            const int kc = ks * 8 + lanek;
            uint32_t a[4][4], b[4][2];
            #pragma unroll
            for (int mi = 0; mi < 4; mi++) {
                int r = wm * 64 + mi * 16 + lane4;
                a[mi][0] = __float_as_uint(Atile[(r    ) * ROWP + kc    ]);
                a[mi][1] = __float_as_uint(Atile[(r + 8) * ROWP + kc    ]);
                a[mi][2] = __float_as_uint(Atile[(r    ) * ROWP + kc + 4]);
                a[mi][3] = __float_as_uint(Atile[(r + 8) * ROWP + kc + 4]);
            }
            #pragma unroll
            for (int ni = 0; ni < 4; ni++) {
                int r = wn * 32 + ni * 8 + lane4;
                b[ni][0] = __float_as_uint(Btile[r * ROWP + kc    ]);
                b[ni][1] = __float_as_uint(Btile[r * ROWP + kc + 4]);
            }
            #pragma unroll
            for (int mi = 0; mi < 4; mi++)
                #pragma unroll
                for (int ni = 0; ni < 4; ni++)
                    mma_tf32(acc[mi][ni], a[mi], b[ni]);
        }
        __syncthreads();
    }

    // Epilogue: c0,c1 -> (row, col..col+1); c2,c3 -> (row+8, ...)
    #pragma unroll
    for (int mi = 0; mi < 4; mi++) {
        #pragma unroll
        for (int ni = 0; ni < 4; ni++) {
            int row = m0 + wm * 64 + mi * 16 + lane4;
            int col = n0 + wn * 32 + ni * 8 + 2 * lanek;
            *(float2*)(C + (size_t)row * DMODEL + col) =
                make_float2(acc[mi][ni][0], acc[mi][ni][1]);
            *(float2*)(C + (size_t)(row + 8) * DMODEL + col) =
                make_float2(acc[mi][ni][2], acc[mi][ni][3]);
        }
    }
}

// ---------------------------------------------------------------------------
// Fast exp (FFMA-only); args <= 0
// ---------------------------------------------------------------------------
__device__ __forceinline__ float fexp(float x) {
    float y = x * 1.4426950408889634f;
    y = fmaxf(y, -126.0f);
    int   e = __float2int_rn(y);
    float f = y - (float)e;
    float p = 1.3333558146e-3f;
    p = fmaf(p, f, 9.6181298421e-3f);
    p = fmaf(p, f, 5.5504108664e-2f);
    p = fmaf(p, f, 2.4022650696e-1f);
    p = fmaf(p, f, 6.9314718056e-1f);
    p = fmaf(p, f, 1.0f);
    return p * __int_as_float((e + 127) << 23);
}

// ---------------------------------------------------------------------------
// Flash-style attention: one thread per query row (unchanged; R2-verified)
// ---------------------------------------------------------------------------
#define QT 128
#define KT 64

__global__ __launch_bounds__(128) void attn_kernel(const int* __restrict__ masks) {
    __shared__ float Ks[KT][DH];
    __shared__ float Vs[KT][DH];
    __shared__ float msf[KT];

    const int t = threadIdx.x;
    const int b = blockIdx.z;
    const int h = blockIdx.y;
    const int r = blockIdx.x * QT + t;

    const float* Qp = g_Q + ((size_t)(b * SEQ + r)) * DMODEL + h * DH;

    float q[DH], o[DH];
    #pragma unroll
    for (int i = 0; i < DH; i += 4)
        *(float4*)(q + i) = *(const float4*)(Qp + i);
    #pragma unroll
    for (int i = 0; i < DH; i++) o[i] = 0.f;

    float m = -CUDART_INF_F;
    float l = 0.f;

    for (int kt = 0; kt < SEQ; kt += KT) {
        __syncthreads();
        const float* Kp = g_K + ((size_t)(b * SEQ + kt)) * DMODEL + h * DH;
        const float* Vp = g_V + ((size_t)(b * SEQ + kt)) * DMODEL + h * DH;
        #pragma unroll
        for (int l2 = 0; l2 < 8; l2++) {
            int idx = l2 * 128 + t;
            int row = idx >> 4;
            int c4  = idx & 15;
            *(float4*)(&Ks[row][c4 * 4]) = *(const float4*)(Kp + (size_t)row * DMODEL + c4 * 4);
            *(float4*)(&Vs[row][c4 * 4]) = *(const float4*)(Vp + (size_t)row * DMODEL + c4 * 4);
        }
        if (t < KT) msf[t] = masks[b * SEQ + kt + t] ? 0.f : -1e30f;
        __syncthreads();

        for (int k = 0; k < KT; k++) {
            float s0 = 0.f, s1 = 0.f, s2 = 0.f, s3 = 0.f;
            #pragma unroll
            for (int i = 0; i < DH; i += 4) {
                s0 = fmaf(q[i    ], Ks[k][i    ], s0);
                s1 = fmaf(q[i + 1], Ks[k][i + 1], s1);
                s2 = fmaf(q[i + 2], Ks[k][i + 2], s2);
                s3 = fmaf(q[i + 3], Ks[k][i + 3], s3);
            }
            float s = (s0 + s1) + (s2 + s3);
            s = fmaf(s, 0.125f, msf[k]);

            if (s > m) {
                float c = fexp(m - s);
                m = s;
                l *= c;
                #pragma unroll
                for (int i = 0; i < DH; i++) o[i] *= c;
            }
            float p = fexp(s - m);
            l += p;
            #pragma unroll
            for (int i = 0; i < DH; i++)
                o[i] = fmaf(p, Vs[k][i], o[i]);
        }
    }

    float inv = 1.0f / l;
    float* Op = g_O + ((size_t)(b * SEQ + r)) * DMODEL + h * DH;
    #pragma unroll
    for (int i = 0; i < DH; i += 4) {
        float4 v = make_float4(o[i] * inv, o[i+1] * inv, o[i+2] * inv, o[i+3] * inv);
        *(float4*)(Op + i) = v;
    }
}

// ---------------------------------------------------------------------------
// Launch:  inputs 0=queries 1=keys 2=values 3=masks 4=Wq 5=Wk 6=Wv 7=Wo
// ---------------------------------------------------------------------------
extern "C" void kernel_launch(void* const* d_in, const int* in_sizes, int n_in,
                              void* d_out, int out_size) {
    const float* qin   = (const float*)d_in[0];
    const float* kin   = (const float*)d_in[1];
    const float* vin   = (const float*)d_in[2];
    const int*   masks = (const int*)  d_in[3];
    float* out = (float*)d_out;

    float *gq, *gk, *gv, *go, *gwt;
    cudaGetSymbolAddress((void**)&gq,  g_Q);
    cudaGetSymbolAddress((void**)&gk,  g_K);
    cudaGetSymbolAddress((void**)&gv,  g_V);
    cudaGetSymbolAddress((void**)&go,  g_O);
    cudaGetSymbolAddress((void**)&gwt, g_Wt);

    cudaFuncSetAttribute(gemm_tf32_kernel,
                         cudaFuncAttributeMaxDynamicSharedMemorySize, SM_GEMM_BYTES);

    // Transpose the 4 weight matrices: W[k][n] -> Wt[n][k]
    WPtrs wp;
    for (int i = 0; i < 4; i++) {
        wp.s[i] = (const float*)d_in[4 + i];
        wp.d[i] = gwt + (size_t)i * DMODEL * DMODEL;
    }
    transpose_k<<<dim3(32, 32, 4), dim3(32, 8)>>>(wp);

    dim3 gg(DMODEL / BN, MTOT / BM);   // (8, 32) = 256 CTAs
    gemm_tf32_kernel<<<gg, 256, SM_GEMM_BYTES>>>(qin, gwt + 0 * (size_t)DMODEL * DMODEL, gq);
    gemm_tf32_kernel<<<gg, 256, SM_GEMM_BYTES>>>(kin, gwt + 1 * (size_t)DMODEL * DMODEL, gk);
    gemm_tf32_kernel<<<gg, 256, SM_GEMM_BYTES>>>(vin, gwt + 2 * (size_t)DMODEL * DMODEL, gv);

    dim3 ga(SEQ / QT, NH, BATCH);      // (16, 16, 2)
    attn_kernel<<<ga, 128>>>(masks);

    gemm_tf32_kernel<<<gg, 256, SM_GEMM_BYTES>>>(go, gwt + 3 * (size_t)DMODEL * DMODEL, out);
}

// round 7
// speedup vs baseline: 2.3226x; 2.0221x over previous
#include <cuda_runtime.h>
#include <math_constants.h>
#include <cstdint>

#define SEQ    2048
#define DMODEL 1024
#define NH     16
#define DH     64
#define BATCH  2
#define MTOT   (BATCH*SEQ)   // 4096 rows

// ---------------------------------------------------------------------------
// Device scratch (allocation-free rule)
// ---------------------------------------------------------------------------
__device__ float g_Q[(size_t)MTOT*DMODEL];
__device__ float g_K[(size_t)MTOT*DMODEL];
__device__ float g_V[(size_t)MTOT*DMODEL];
__device__ float g_O[(size_t)MTOT*DMODEL];
__device__ float g_Wt[4][(size_t)DMODEL*DMODEL];   // transposed weights [N][K]

// ---------------------------------------------------------------------------
// Helpers
// ---------------------------------------------------------------------------
__device__ __forceinline__ float to_tf32_rn(float x) {
    uint32_t r;                                     // tf32 cvt needs .b32 dst
    asm("cvt.rna.tf32.f32 %0, %1;" : "=r"(r) : "f"(x));
    return __uint_as_float(r);
}

// m16n8k8 tf32 mma (baseline PTX, sm_80+; runs on tensor cores)
__device__ __forceinline__ void mma_tf32(float* c, const uint32_t* a, const uint32_t* b) {
    asm volatile(
        "mma.sync.aligned.m16n8k8.row.col.f32.tf32.tf32.f32 "
        "{%0,%1,%2,%3}, {%4,%5,%6,%7}, {%8,%9}, {%0,%1,%2,%3};"
        : "+f"(c[0]), "+f"(c[1]), "+f"(c[2]), "+f"(c[3])
        : "r"(a[0]), "r"(a[1]), "r"(a[2]), "r"(a[3]), "r"(b[0]), "r"(b[1]));
}

// Fast exp (FFMA-only); args <= 0 (or ~0 for the masked-all path)
__device__ __forceinline__ float fexp(float x) {
    float y = x * 1.4426950408889634f;
    y = fmaxf(y, -126.0f);
    int   e = __float2int_rn(y);
    float f = y - (float)e;
    float p = 1.3333558146e-3f;
    p = fmaf(p, f, 9.6181298421e-3f);
    p = fmaf(p, f, 5.5504108664e-2f);
    p = fmaf(p, f, 2.4022650696e-1f);
    p = fmaf(p, f, 6.9314718056e-1f);
    p = fmaf(p, f, 1.0f);
    return p * __int_as_float((e + 127) << 23);
}

// ---------------------------------------------------------------------------
// Weight transpose: Wt[n][k] = W[k][n] (1024x1024), 4 matrices via blockIdx.z
// ---------------------------------------------------------------------------
struct WPtrs { const float* s[4]; float* d[4]; };

__global__ __launch_bounds__(256) void transpose_k(WPtrs p) {
    __shared__ float tile[32][33];
    const float* S = p.s[blockIdx.z];
    float*       D = p.d[blockIdx.z];
    int x0 = blockIdx.x * 32, y0 = blockIdx.y * 32;
    int tx = threadIdx.x, ty = threadIdx.y;          // (32, 8)
    #pragma unroll
    for (int j = 0; j < 32; j += 8)
        tile[ty + j][tx] = S[(size_t)(y0 + ty + j) * DMODEL + x0 + tx];
    __syncthreads();
    #pragma unroll
    for (int j = 0; j < 32; j += 8)
        D[(size_t)(x0 + ty + j) * DMODEL + y0 + tx] = tile[tx][ty + j];
}

// ---------------------------------------------------------------------------
// tf32 tensor-core GEMM: C[M,N=1024] = A[M,K=1024] * Bt[N,K]^T  (unchanged R5)
// ---------------------------------------------------------------------------
#define BM 128
#define BN 128
#define BK 32
#define KT_GEMM (DMODEL / BK)          // 32
#define ROWP 36
#define STG_F (128 * ROWP)
#define SM_GEMM_BYTES (4 * STG_F * 4 * 2)  // 73728 B

__global__ __launch_bounds__(256) void gemm_tf32_kernel(const float* __restrict__ A,
                                                        const float* __restrict__ Bt,
                                                        float* __restrict__ C) {
    extern __shared__ float sm[];
    float* As = sm;                    // [2][128][36]
    float* Bs = sm + 2 * STG_F;        // [2][128][36]

    const int t    = threadIdx.x;
    const int wid  = t >> 5;
    const int lane = t & 31;
    const int wm   = wid & 1;
    const int wn   = wid >> 1;
    const int lane4 = lane >> 2;
    const int lanek = lane & 3;
    const int m0 = blockIdx.y * BM;
    const int n0 = blockIdx.x * BN;

    float acc[4][4][4];
    #pragma unroll
    for (int mi = 0; mi < 4; mi++)
        #pragma unroll
        for (int ni = 0; ni < 4; ni++)
            #pragma unroll
            for (int f = 0; f < 4; f++) acc[mi][ni][f] = 0.f;

    auto load_tile = [&](int kt, int s) {
        const float* Ap = A + (size_t)m0 * DMODEL + kt * BK;
        const float* Bp = Bt + (size_t)n0 * DMODEL + kt * BK;
        #pragma unroll
        for (int i = 0; i < 4; i++) {
            int idx = i * 256 + t;
            int row = idx >> 3, c4 = idx & 7;
            float4 v = *(const float4*)(Ap + (size_t)row * DMODEL + c4 * 4);
            v.x = to_tf32_rn(v.x); v.y = to_tf32_rn(v.y);
            v.z = to_tf32_rn(v.z); v.w = to_tf32_rn(v.w);
            *(float4*)(As + s * STG_F + row * ROWP + c4 * 4) = v;
        }
        #pragma unroll
        for (int i = 0; i < 4; i++) {
            int idx = i * 256 + t;
            int row = idx >> 3, c4 = idx & 7;
            float4 v = *(const float4*)(Bp + (size_t)row * DMODEL + c4 * 4);
            v.x = to_tf32_rn(v.x); v.y = to_tf32_rn(v.y);
            v.z = to_tf32_rn(v.z); v.w = to_tf32_rn(v.w);
            *(float4*)(Bs + s * STG_F + row * ROWP + c4 * 4) = v;
        }
    };

    load_tile(0, 0);
    __syncthreads();

    for (int kt = 0; kt < KT_GEMM; kt++) {
        const int s = kt & 1;
        if (kt + 1 < KT_GEMM) load_tile(kt + 1, s ^ 1);

        const float* Atile = As + s * STG_F;
        const float* Btile = Bs + s * STG_F;
        #pragma unroll
        for (int ks = 0; ks < 4; ks++) {
            const int kc = ks * 8 + lanek;
            uint32_t a[4][4], b[4][2];
            #pragma unroll
            for (int mi = 0; mi < 4; mi++) {
                int r = wm * 64 + mi * 16 + lane4;
                a[mi][0] = __float_as_uint(Atile[(r    ) * ROWP + kc    ]);
                a[mi][1] = __float_as_uint(Atile[(r + 8) * ROWP + kc    ]);
                a[mi][2] = __float_as_uint(Atile[(r    ) * ROWP + kc + 4]);
                a[mi][3] = __float_as_uint(Atile[(r + 8) * ROWP + kc + 4]);
            }
            #pragma unroll
            for (int ni = 0; ni < 4; ni++) {
                int r = wn * 32 + ni * 8 + lane4;
                b[ni][0] = __float_as_uint(Btile[r * ROWP + kc    ]);
                b[ni][1] = __float_as_uint(Btile[r * ROWP + kc + 4]);
            }
            #pragma unroll
            for (int mi = 0; mi < 4; mi++)
                #pragma unroll
                for (int ni = 0; ni < 4; ni++)
                    mma_tf32(acc[mi][ni], a[mi], b[ni]);
        }
        __syncthreads();
    }

    #pragma unroll
    for (int mi = 0; mi < 4; mi++) {
        #pragma unroll
        for (int ni = 0; ni < 4; ni++) {
            int row = m0 + wm * 64 + mi * 16 + lane4;
            int col = n0 + wn * 32 + ni * 8 + 2 * lanek;
            *(float2*)(C + (size_t)row * DMODEL + col) =
                make_float2(acc[mi][ni][0], acc[mi][ni][1]);
            *(float2*)(C + (size_t)(row + 8) * DMODEL + col) =
                make_float2(acc[mi][ni][2], acc[mi][ni][3]);
        }
    }
}

// ---------------------------------------------------------------------------
// Tensor-core flash attention.
// CTA: 128 q-rows of one (b,h); 8 warps x 16 rows. KV tiles of 64.
// QK^T and P*V via m16n8k8 tf32 mma; online softmax in fragments with
// quad-shuffle row reductions; P bridged C->A through warp-private smem.
// ---------------------------------------------------------------------------
#define ATT_BQ   128
#define ATT_BKV  64
#define ATT_PAD  68
#define ATT_SMEM ((2 * ATT_BKV * ATT_PAD + 8 * 16 * ATT_PAD + ATT_BKV) * 4)  // 69888 B

__global__ __launch_bounds__(256) void attn_mma_kernel(const int* __restrict__ masks) {
    extern __shared__ float smf[];
    float* Ks  = smf;                                   // [64][68]
    float* Vs  = smf + ATT_BKV * ATT_PAD;               // [64][68]
    float* Ps  = smf + 2 * ATT_BKV * ATT_PAD;           // [8][16][68]
    float* msf = smf + 2 * ATT_BKV * ATT_PAD + 8 * 16 * ATT_PAD;  // [64]

    const int t    = threadIdx.x;
    const int w    = t >> 5;
    const int lane = t & 31;
    const int gid  = lane >> 2;    // 0..7  (row within mma tile)
    const int tid4 = lane & 3;     // 0..3
    const int b  = blockIdx.z;
    const int h  = blockIdx.y;
    const int q0 = blockIdx.x * ATT_BQ;

    // Q fragments: rows q0+w*16+gid(+8), all 8 k-chunks; prescaled by 1/8.
    uint32_t aQ[8][4];
    {
        const float* Qb = g_Q + ((size_t)(b * SEQ + q0 + w * 16)) * DMODEL + h * DH;
        #pragma unroll
        for (int kk = 0; kk < 8; kk++) {
            int c = kk * 8 + tid4;
            aQ[kk][0] = __float_as_uint(to_tf32_rn(0.125f * Qb[(size_t)gid       * DMODEL + c    ]));
            aQ[kk][1] = __float_as_uint(to_tf32_rn(0.125f * Qb[(size_t)(gid + 8) * DMODEL + c    ]));
            aQ[kk][2] = __float_as_uint(to_tf32_rn(0.125f * Qb[(size_t)gid       * DMODEL + c + 4]));
            aQ[kk][3] = __float_as_uint(to_tf32_rn(0.125f * Qb[(size_t)(gid + 8) * DMODEL + c + 4]));
        }
    }

    float Oa[8][4];
    #pragma unroll
    for (int nb = 0; nb < 8; nb++)
        #pragma unroll
        for (int f = 0; f < 4; f++) Oa[nb][f] = 0.f;
    float m0 = -1e30f, m1 = -1e30f, l0 = 0.f, l1 = 0.f;

    float* Pw = Ps + w * 16 * ATT_PAD;

    for (int kv0 = 0; kv0 < SEQ; kv0 += ATT_BKV) {
        __syncthreads();
        // Stage K/V tile (tf32-rounded) + mask biases
        {
            const float* Kb = g_K + ((size_t)(b * SEQ + kv0)) * DMODEL + h * DH;
            const float* Vb = g_V + ((size_t)(b * SEQ + kv0)) * DMODEL + h * DH;
            #pragma unroll
            for (int i = 0; i < 4; i++) {
                int idx = i * 256 + t;
                int row = idx >> 4, c4 = (idx & 15) * 4;
                float4 kv = *(const float4*)(Kb + (size_t)row * DMODEL + c4);
                kv.x = to_tf32_rn(kv.x); kv.y = to_tf32_rn(kv.y);
                kv.z = to_tf32_rn(kv.z); kv.w = to_tf32_rn(kv.w);
                *(float4*)(Ks + row * ATT_PAD + c4) = kv;
                float4 vv = *(const float4*)(Vb + (size_t)row * DMODEL + c4);
                vv.x = to_tf32_rn(vv.x); vv.y = to_tf32_rn(vv.y);
                vv.z = to_tf32_rn(vv.z); vv.w = to_tf32_rn(vv.w);
                *(float4*)(Vs + row * ATT_PAD + c4) = vv;
            }
            if (t < ATT_BKV) msf[t] = masks[b * SEQ + kv0 + t] ? 0.f : -1e30f;
        }
        __syncthreads();

        // S = (Q/8) . K^T  -- 8 n-blocks x 8 k-chunks of m16n8k8
        float sc[8][4];
        #pragma unroll
        for (int nb = 0; nb < 8; nb++) {
            sc[nb][0] = sc[nb][1] = sc[nb][2] = sc[nb][3] = 0.f;
            const float* Kr = Ks + (nb * 8 + gid) * ATT_PAD + tid4;
            #pragma unroll
            for (int kk = 0; kk < 8; kk++) {
                uint32_t bk[2];
                bk[0] = __float_as_uint(Kr[kk * 8    ]);
                bk[1] = __float_as_uint(Kr[kk * 8 + 4]);
                mma_tf32(sc[nb], aQ[kk], bk);
            }
        }

        // Mask bias + tile row max
        float tm0 = -1e30f, tm1 = -1e30f;
        #pragma unroll
        for (int nb = 0; nb < 8; nb++) {
            float2 mm = *(const float2*)(msf + nb * 8 + 2 * tid4);
            sc[nb][0] += mm.x; sc[nb][1] += mm.y;
            sc[nb][2] += mm.x; sc[nb][3] += mm.y;
            tm0 = fmaxf(tm0, fmaxf(sc[nb][0], sc[nb][1]));
            tm1 = fmaxf(tm1, fmaxf(sc[nb][2], sc[nb][3]));
        }
        tm0 = fmaxf(tm0, __shfl_xor_sync(0xffffffffu, tm0, 1));
        tm0 = fmaxf(tm0, __shfl_xor_sync(0xffffffffu, tm0, 2));
        tm1 = fmaxf(tm1, __shfl_xor_sync(0xffffffffu, tm1, 1));
        tm1 = fmaxf(tm1, __shfl_xor_sync(0xffffffffu, tm1, 2));

        float mn0 = fmaxf(m0, tm0), mn1 = fmaxf(m1, tm1);
        float al0 = fexp(m0 - mn0), al1 = fexp(m1 - mn1);
        m0 = mn0; m1 = mn1;

        // P = exp(S - m); store tf32 P to warp-private smem; partial row sums
        float lp0 = 0.f, lp1 = 0.f;
        #pragma unroll
        for (int nb = 0; nb < 8; nb++) {
            float p0 = fexp(sc[nb][0] - m0);
            float p1 = fexp(sc[nb][1] - m0);
            float p2 = fexp(sc[nb][2] - m1);
            float p3 = fexp(sc[nb][3] - m1);
            lp0 += p0 + p1; lp1 += p2 + p3;
            *(float2*)(Pw + gid * ATT_PAD + nb * 8 + 2 * tid4) =
                make_float2(to_tf32_rn(p0), to_tf32_rn(p1));
            *(float2*)(Pw + (gid + 8) * ATT_PAD + nb * 8 + 2 * tid4) =
                make_float2(to_tf32_rn(p2), to_tf32_rn(p3));
        }
        l0 = l0 * al0 + lp0;
        l1 = l1 * al1 + lp1;
        #pragma unroll
        for (int nb = 0; nb < 8; nb++) {
            Oa[nb][0] *= al0; Oa[nb][1] *= al0;
            Oa[nb][2] *= al1; Oa[nb][3] *= al1;
        }
        __syncwarp();

        // O += P . V  -- 8 k-chunks(kv) x 8 n-blocks(d)
        #pragma unroll
        for (int kk = 0; kk < 8; kk++) {
            uint32_t aP[4];
            const float* Pr = Pw + gid * ATT_PAD + kk * 8 + tid4;
            aP[0] = __float_as_uint(Pr[0]);
            aP[1] = __float_as_uint(Pr[8 * ATT_PAD]);
            aP[2] = __float_as_uint(Pr[4]);
            aP[3] = __float_as_uint(Pr[8 * ATT_PAD + 4]);
            const float* Vr = Vs + (kk * 8 + tid4) * ATT_PAD + gid;
            #pragma unroll
            for (int nb = 0; nb < 8; nb++) {
                uint32_t bv[2];
                bv[0] = __float_as_uint(Vr[nb * 8]);
                bv[1] = __float_as_uint(Vr[4 * ATT_PAD + nb * 8]);
                mma_tf32(Oa[nb], aP, bv);
            }
        }
        __syncwarp();
    }

    // Finalize: full row sums, normalize, store
    l0 += __shfl_xor_sync(0xffffffffu, l0, 1);
    l0 += __shfl_xor_sync(0xffffffffu, l0, 2);
    l1 += __shfl_xor_sync(0xffffffffu, l1, 1);
    l1 += __shfl_xor_sync(0xffffffffu, l1, 2);
    float inv0 = 1.f / l0, inv1 = 1.f / l1;

    float* Ob = g_O + ((size_t)(b * SEQ + q0 + w * 16)) * DMODEL + h * DH;
    #pragma unroll
    for (int nb = 0; nb < 8; nb++) {
        *(float2*)(Ob + (size_t)gid * DMODEL + nb * 8 + 2 * tid4) =
            make_float2(Oa[nb][0] * inv0, Oa[nb][1] * inv0);
        *(float2*)(Ob + (size_t)(gid + 8) * DMODEL + nb * 8 + 2 * tid4) =
            make_float2(Oa[nb][2] * inv1, Oa[nb][3] * inv1);
    }
}

// ---------------------------------------------------------------------------
// Launch:  inputs 0=queries 1=keys 2=values 3=masks 4=Wq 5=Wk 6=Wv 7=Wo
// ---------------------------------------------------------------------------
extern "C" void kernel_launch(void* const* d_in, const int* in_sizes, int n_in,
                              void* d_out, int out_size) {
    const float* qin   = (const float*)d_in[0];
    const float* kin   = (const float*)d_in[1];
    const float* vin   = (const float*)d_in[2];
    const int*   masks = (const int*)  d_in[3];
    float* out = (float*)d_out;

    float *gq, *gk, *gv, *go, *gwt;
    cudaGetSymbolAddress((void**)&gq,  g_Q);
    cudaGetSymbolAddress((void**)&gk,  g_K);
    cudaGetSymbolAddress((void**)&gv,  g_V);
    cudaGetSymbolAddress((void**)&go,  g_O);
    cudaGetSymbolAddress((void**)&gwt, g_Wt);

    cudaFuncSetAttribute(gemm_tf32_kernel,
                         cudaFuncAttributeMaxDynamicSharedMemorySize, SM_GEMM_BYTES);
    cudaFuncSetAttribute(gemm_tf32_kernel,
                         cudaFuncAttributePreferredSharedMemoryCarveout, 100);
    cudaFuncSetAttribute(attn_mma_kernel,
                         cudaFuncAttributeMaxDynamicSharedMemorySize, ATT_SMEM);

    // Transpose the 4 weight matrices: W[k][n] -> Wt[n][k]
    WPtrs wp;
    for (int i = 0; i < 4; i++) {
        wp.s[i] = (const float*)d_in[4 + i];
        wp.d[i] = gwt + (size_t)i * DMODEL * DMODEL;
    }
    transpose_k<<<dim3(32, 32, 4), dim3(32, 8)>>>(wp);

    dim3 gg(DMODEL / BN, MTOT / BM);   // (8, 32) = 256 CTAs
    gemm_tf32_kernel<<<gg, 256, SM_GEMM_BYTES>>>(qin, gwt + 0 * (size_t)DMODEL * DMODEL, gq);
    gemm_tf32_kernel<<<gg, 256, SM_GEMM_BYTES>>>(kin, gwt + 1 * (size_t)DMODEL * DMODEL, gk);
    gemm_tf32_kernel<<<gg, 256, SM_GEMM_BYTES>>>(vin, gwt + 2 * (size_t)DMODEL * DMODEL, gv);

    dim3 ga(SEQ / ATT_BQ, NH, BATCH);  // (16, 16, 2) = 512 CTAs
    attn_mma_kernel<<<ga, 256, ATT_SMEM>>>(masks);

    gemm_tf32_kernel<<<gg, 256, SM_GEMM_BYTES>>>(go, gwt + 3 * (size_t)DMODEL * DMODEL, out);
}

// round 8
// speedup vs baseline: 3.3443x; 1.4399x over previous
#include <cuda_runtime.h>
#include <math_constants.h>
#include <cstdint>

#define SEQ    2048
#define DMODEL 1024
#define NH     16
#define DH     64
#define BATCH  2
#define MTOT   (BATCH*SEQ)   // 4096 rows

// ---------------------------------------------------------------------------
// Device scratch (allocation-free rule)
// ---------------------------------------------------------------------------
__device__ float g_Q[(size_t)MTOT*DMODEL];
__device__ float g_K[(size_t)MTOT*DMODEL];
__device__ float g_V[(size_t)MTOT*DMODEL];
__device__ float g_O[(size_t)MTOT*DMODEL];
__device__ float g_Wt[4][(size_t)DMODEL*DMODEL];   // transposed+rounded weights [N][K]
__device__ float g_R[3][(size_t)MTOT*DMODEL];      // rounded inputs (q,k,v)

// ---------------------------------------------------------------------------
// Helpers
// ---------------------------------------------------------------------------
__device__ __forceinline__ uint32_t smem_u32(const void* p) {
    uint32_t a;
    asm("{ .reg .u64 t; cvta.to.shared.u64 t, %1; cvt.u32.u64 %0, t; }" : "=r"(a) : "l"(p));
    return a;
}
__device__ __forceinline__ float to_tf32_rn(float x) {
    uint32_t r;
    asm("cvt.rna.tf32.f32 %0, %1;" : "=r"(r) : "f"(x));
    return __uint_as_float(r);
}
__device__ __forceinline__ void cp16(uint32_t dst, const void* src) {
    asm volatile("cp.async.cg.shared.global [%0], [%1], 16;" :: "r"(dst), "l"(src));
}
#define CP_COMMIT() asm volatile("cp.async.commit_group;" ::: "memory")
#define CP_WAIT0()  asm volatile("cp.async.wait_group 0;" ::: "memory")
#define CP_WAIT1()  asm volatile("cp.async.wait_group 1;" ::: "memory")

// m16n8k8 tf32 mma (baseline PTX, sm_80+)
__device__ __forceinline__ void mma_tf32(float* c, const uint32_t* a, const uint32_t* b) {
    asm volatile(
        "mma.sync.aligned.m16n8k8.row.col.f32.tf32.tf32.f32 "
        "{%0,%1,%2,%3}, {%4,%5,%6,%7}, {%8,%9}, {%0,%1,%2,%3};"
        : "+f"(c[0]), "+f"(c[1]), "+f"(c[2]), "+f"(c[3])
        : "r"(a[0]), "r"(a[1]), "r"(a[2]), "r"(a[3]), "r"(b[0]), "r"(b[1]));
}

// Fast exp (FFMA-only); args <= 0
__device__ __forceinline__ float fexp(float x) {
    float y = x * 1.4426950408889634f;
    y = fmaxf(y, -126.0f);
    int   e = __float2int_rn(y);
    float f = y - (float)e;
    float p = 1.3333558146e-3f;
    p = fmaf(p, f, 9.6181298421e-3f);
    p = fmaf(p, f, 5.5504108664e-2f);
    p = fmaf(p, f, 2.4022650696e-1f);
    p = fmaf(p, f, 6.9314718056e-1f);
    p = fmaf(p, f, 1.0f);
    return p * __int_as_float((e + 127) << 23);
}

// ---------------------------------------------------------------------------
// Round queries/keys/values to tf32 (removes truncation bias from cp.async path)
// ---------------------------------------------------------------------------
struct R3 { const float4* s[3]; };

__global__ __launch_bounds__(256) void round3_kernel(R3 p) {
    const int z = blockIdx.z;
    const float4* S = p.s[z];
    float4* D = (float4*)(g_R[z]);
    const int n4 = MTOT * DMODEL / 4;
    for (int i = blockIdx.x * 256 + threadIdx.x; i < n4; i += gridDim.x * 256) {
        float4 v = S[i];
        v.x = to_tf32_rn(v.x); v.y = to_tf32_rn(v.y);
        v.z = to_tf32_rn(v.z); v.w = to_tf32_rn(v.w);
        D[i] = v;
    }
}

// ---------------------------------------------------------------------------
// Weight transpose + round: Wt[n][k] = tf32(W[k][n])
// ---------------------------------------------------------------------------
struct WPtrs { const float* s[4]; float* d[4]; };

__global__ __launch_bounds__(256) void transpose_k(WPtrs p) {
    __shared__ float tile[32][33];
    const float* S = p.s[blockIdx.z];
    float*       D = p.d[blockIdx.z];
    int x0 = blockIdx.x * 32, y0 = blockIdx.y * 32;
    int tx = threadIdx.x, ty = threadIdx.y;          // (32, 8)
    #pragma unroll
    for (int j = 0; j < 32; j += 8)
        tile[ty + j][tx] = S[(size_t)(y0 + ty + j) * DMODEL + x0 + tx];
    __syncthreads();
    #pragma unroll
    for (int j = 0; j < 32; j += 8)
        D[(size_t)(x0 + ty + j) * DMODEL + y0 + tx] = to_tf32_rn(tile[tx][ty + j]);
}

// ---------------------------------------------------------------------------
// tf32 tensor-core GEMM (cp.async 3-stage): C[M,N=1024] = A[M,K] * Bt[N,K]^T
// All operands pre-rounded to tf32 in gmem. ROUND: round C (for Q/K/V).
// ---------------------------------------------------------------------------
#define BM 128
#define BN 128
#define BK 32
#define KT_GEMM (DMODEL / BK)          // 32
#define ROWP 36
#define TILE_F (128 * ROWP)            // 4608 floats per operand tile
#define GSTG 3
#define SM_GEMM_BYTES (GSTG * 2 * TILE_F * 4)   // 110592 B

template<bool ROUND>
__global__ __launch_bounds__(256, 2) void gemm_tf32_kernel(const float* __restrict__ A,
                                                           const float* __restrict__ Bt,
                                                           float* __restrict__ C) {
    extern __shared__ float sm[];
    const uint32_t sb = smem_u32(sm);

    const int t     = threadIdx.x;
    const int wid   = t >> 5;
    const int lane  = t & 31;
    const int wm    = wid & 1;
    const int wn    = wid >> 1;
    const int lane4 = lane >> 2;
    const int lanek = lane & 3;
    const int m0 = blockIdx.y * BM;
    const int n0 = blockIdx.x * BN;
    const int lrow = t >> 3, lc4 = t & 7;   // loader coords

    float acc[4][4][4];
    #pragma unroll
    for (int mi = 0; mi < 4; mi++)
        #pragma unroll
        for (int ni = 0; ni < 4; ni++)
            #pragma unroll
            for (int f = 0; f < 4; f++) acc[mi][ni][f] = 0.f;

    auto issue = [&](int kt, int s) {
        const float* Ap = A  + (size_t)m0 * DMODEL + kt * BK;
        const float* Bp = Bt + (size_t)n0 * DMODEL + kt * BK;
        #pragma unroll
        for (int i = 0; i < 4; i++) {
            int row = lrow + i * 32;
            cp16(sb + (uint32_t)((s * 2 * TILE_F + row * ROWP + lc4 * 4) * 4),
                 Ap + (size_t)row * DMODEL + lc4 * 4);
            cp16(sb + (uint32_t)((s * 2 * TILE_F + TILE_F + row * ROWP + lc4 * 4) * 4),
                 Bp + (size_t)row * DMODEL + lc4 * 4);
        }
        CP_COMMIT();
    };

    issue(0, 0);
    issue(1, 1);

    for (int kt = 0; kt < KT_GEMM; kt++) {
        const int s = kt % 3;
        if (kt < KT_GEMM - 1) CP_WAIT1(); else CP_WAIT0();
        __syncthreads();
        if (kt + 2 < KT_GEMM) issue(kt + 2, (kt + 2) % 3);   // overlaps compute

        const float* Atile = sm + s * 2 * TILE_F;
        const float* Btile = Atile + TILE_F;
        #pragma unroll
        for (int ks = 0; ks < 4; ks++) {
            const int kc = ks * 8 + lanek;
            uint32_t a[4][4], b[4][2];
            #pragma unroll
            for (int mi = 0; mi < 4; mi++) {
                int r = wm * 64 + mi * 16 + lane4;
                a[mi][0] = __float_as_uint(Atile[(r    ) * ROWP + kc    ]);
                a[mi][1] = __float_as_uint(Atile[(r + 8) * ROWP + kc    ]);
                a[mi][2] = __float_as_uint(Atile[(r    ) * ROWP + kc + 4]);
                a[mi][3] = __float_as_uint(Atile[(r + 8) * ROWP + kc + 4]);
            }
            #pragma unroll
            for (int ni = 0; ni < 4; ni++) {
                int r = wn * 32 + ni * 8 + lane4;
                b[ni][0] = __float_as_uint(Btile[r * ROWP + kc    ]);
                b[ni][1] = __float_as_uint(Btile[r * ROWP + kc + 4]);
            }
            #pragma unroll
            for (int mi = 0; mi < 4; mi++)
                #pragma unroll
                for (int ni = 0; ni < 4; ni++)
                    mma_tf32(acc[mi][ni], a[mi], b[ni]);
        }
        __syncthreads();
    }

    #pragma unroll
    for (int mi = 0; mi < 4; mi++) {
        #pragma unroll
        for (int ni = 0; ni < 4; ni++) {
            int row = m0 + wm * 64 + mi * 16 + lane4;
            int col = n0 + wn * 32 + ni * 8 + 2 * lanek;
            float v0 = acc[mi][ni][0], v1 = acc[mi][ni][1];
            float v2 = acc[mi][ni][2], v3 = acc[mi][ni][3];
            if (ROUND) {
                v0 = to_tf32_rn(v0); v1 = to_tf32_rn(v1);
                v2 = to_tf32_rn(v2); v3 = to_tf32_rn(v3);
            }
            *(float2*)(C + (size_t)row * DMODEL + col)       = make_float2(v0, v1);
            *(float2*)(C + (size_t)(row + 8) * DMODEL + col) = make_float2(v2, v3);
        }
    }
}

// ---------------------------------------------------------------------------
// Tensor-core flash attention (cp.async double-buffered K/V, pre-rounded Q/K/V)
// CTA: 128 q-rows of one (b,h); 8 warps x 16 rows; KV tiles of 64.
// ---------------------------------------------------------------------------
#define ATT_BQ   128
#define ATT_BKV  64
#define APAD     68
#define ATT_KV_F (2 * ATT_BKV * APAD)                 // per stage (K+V) = 8704 floats
#define ATT_P_OFF (2 * ATT_KV_F)                      // 17408
#define ATT_MSK_OFF (ATT_P_OFF + 8 * 16 * APAD)       // 26112
#define ATT_SMEM ((ATT_MSK_OFF + SEQ) * 4)            // 112640 B

__global__ __launch_bounds__(256, 2) void attn_mma_kernel(const int* __restrict__ masks) {
    extern __shared__ float smf[];
    const uint32_t sb = smem_u32(smf);
    float* Ps  = smf + ATT_P_OFF;
    float* msf = smf + ATT_MSK_OFF;

    const int t    = threadIdx.x;
    const int w    = t >> 5;
    const int lane = t & 31;
    const int gid  = lane >> 2;
    const int tid4 = lane & 3;
    const int b  = blockIdx.z;
    const int h  = blockIdx.y;
    const int q0 = blockIdx.x * ATT_BQ;

    // Whole-sequence mask biases, loaded once
    for (int i = t; i < SEQ; i += 256)
        msf[i] = masks[b * SEQ + i] ? 0.f : -1e30f;

    // Q fragments (g_Q pre-rounded tf32; *0.125 is exact)
    uint32_t aQ[8][4];
    {
        const float* Qb = g_Q + ((size_t)(b * SEQ + q0 + w * 16)) * DMODEL + h * DH;
        #pragma unroll
        for (int kk = 0; kk < 8; kk++) {
            int c = kk * 8 + tid4;
            aQ[kk][0] = __float_as_uint(0.125f * Qb[(size_t)gid       * DMODEL + c    ]);
            aQ[kk][1] = __float_as_uint(0.125f * Qb[(size_t)(gid + 8) * DMODEL + c    ]);
            aQ[kk][2] = __float_as_uint(0.125f * Qb[(size_t)gid       * DMODEL + c + 4]);
            aQ[kk][3] = __float_as_uint(0.125f * Qb[(size_t)(gid + 8) * DMODEL + c + 4]);
        }
    }

    float Oa[8][4];
    #pragma unroll
    for (int nb = 0; nb < 8; nb++)
        #pragma unroll
        for (int f = 0; f < 4; f++) Oa[nb][f] = 0.f;
    float m0 = -1e30f, m1 = -1e30f, l0 = 0.f, l1 = 0.f;

    float* Pw = Ps + w * 16 * APAD;

    auto issue_kv = [&](int kv0, int s) {
        const float* Kb = g_K + ((size_t)(b * SEQ + kv0)) * DMODEL + h * DH;
        const float* Vb = g_V + ((size_t)(b * SEQ + kv0)) * DMODEL + h * DH;
        #pragma unroll
        for (int i = 0; i < 4; i++) {
            int idx = i * 256 + t;
            int row = idx >> 4, c4 = (idx & 15) * 4;
            cp16(sb + (uint32_t)((s * ATT_KV_F + row * APAD + c4) * 4),
                 Kb + (size_t)row * DMODEL + c4);
            cp16(sb + (uint32_t)((s * ATT_KV_F + ATT_BKV * APAD + row * APAD + c4) * 4),
                 Vb + (size_t)row * DMODEL + c4);
        }
        CP_COMMIT();
    };

    issue_kv(0, 0);

    for (int kv0 = 0; kv0 < SEQ; kv0 += ATT_BKV) {
        const int s = (kv0 >> 6) & 1;
        CP_WAIT0();
        __syncthreads();
        if (kv0 + ATT_BKV < SEQ) issue_kv(kv0 + ATT_BKV, s ^ 1);  // overlaps compute

        const float* Ks = smf + s * ATT_KV_F;
        const float* Vs = Ks + ATT_BKV * APAD;

        // S = (Q/8) . K^T
        float sc[8][4];
        #pragma unroll
        for (int nb = 0; nb < 8; nb++) {
            sc[nb][0] = sc[nb][1] = sc[nb][2] = sc[nb][3] = 0.f;
            const float* Kr = Ks + (nb * 8 + gid) * APAD + tid4;
            #pragma unroll
            for (int kk = 0; kk < 8; kk++) {
                uint32_t bk[2];
                bk[0] = __float_as_uint(Kr[kk * 8    ]);
                bk[1] = __float_as_uint(Kr[kk * 8 + 4]);
                mma_tf32(sc[nb], aQ[kk], bk);
            }
        }

        // Mask bias + tile row max
        float tm0 = -1e30f, tm1 = -1e30f;
        #pragma unroll
        for (int nb = 0; nb < 8; nb++) {
            float2 mm = *(const float2*)(msf + kv0 + nb * 8 + 2 * tid4);
            sc[nb][0] += mm.x; sc[nb][1] += mm.y;
            sc[nb][2] += mm.x; sc[nb][3] += mm.y;
            tm0 = fmaxf(tm0, fmaxf(sc[nb][0], sc[nb][1]));
            tm1 = fmaxf(tm1, fmaxf(sc[nb][2], sc[nb][3]));
        }
        tm0 = fmaxf(tm0, __shfl_xor_sync(0xffffffffu, tm0, 1));
        tm0 = fmaxf(tm0, __shfl_xor_sync(0xffffffffu, tm0, 2));
        tm1 = fmaxf(tm1, __shfl_xor_sync(0xffffffffu, tm1, 1));
        tm1 = fmaxf(tm1, __shfl_xor_sync(0xffffffffu, tm1, 2));

        float mn0 = fmaxf(m0, tm0), mn1 = fmaxf(m1, tm1);
        float al0 = fexp(m0 - mn0), al1 = fexp(m1 - mn1);
        m0 = mn0; m1 = mn1;

        // P = exp(S - m) -> warp-private smem (tf32); partial row sums
        float lp0 = 0.f, lp1 = 0.f;
        #pragma unroll
        for (int nb = 0; nb < 8; nb++) {
            float p0 = fexp(sc[nb][0] - m0);
            float p1 = fexp(sc[nb][1] - m0);
            float p2 = fexp(sc[nb][2] - m1);
            float p3 = fexp(sc[nb][3] - m1);
            lp0 += p0 + p1; lp1 += p2 + p3;
            *(float2*)(Pw + gid * APAD + nb * 8 + 2 * tid4) =
                make_float2(to_tf32_rn(p0), to_tf32_rn(p1));
            *(float2*)(Pw + (gid + 8) * APAD + nb * 8 + 2 * tid4) =
                make_float2(to_tf32_rn(p2), to_tf32_rn(p3));
        }
        l0 = l0 * al0 + lp0;
        l1 = l1 * al1 + lp1;
        #pragma unroll
        for (int nb = 0; nb < 8; nb++) {
            Oa[nb][0] *= al0; Oa[nb][1] *= al0;
            Oa[nb][2] *= al1; Oa[nb][3] *= al1;
        }
        __syncwarp();

        // O += P . V
        #pragma unroll
        for (int kk = 0; kk < 8; kk++) {
            uint32_t aP[4];
            const float* Pr = Pw + gid * APAD + kk * 8 + tid4;
            aP[0] = __float_as_uint(Pr[0]);
            aP[1] = __float_as_uint(Pr[8 * APAD]);
            aP[2] = __float_as_uint(Pr[4]);
            aP[3] = __float_as_uint(Pr[8 * APAD + 4]);
            const float* Vr = Vs + (kk * 8 + tid4) * APAD + gid;
            #pragma unroll
            for (int nb = 0; nb < 8; nb++) {
                uint32_t bv[2];
                bv[0] = __float_as_uint(Vr[nb * 8]);
                bv[1] = __float_as_uint(Vr[4 * APAD + nb * 8]);
                mma_tf32(Oa[nb], aP, bv);
            }
        }
        __syncwarp();
    }

    // Finalize: row sums, normalize, store O rounded (A of final GEMM)
    l0 += __shfl_xor_sync(0xffffffffu, l0, 1);
    l0 += __shfl_xor_sync(0xffffffffu, l0, 2);
    l1 += __shfl_xor_sync(0xffffffffu, l1, 1);
    l1 += __shfl_xor_sync(0xffffffffu, l1, 2);
    float inv0 = 1.f / l0, inv1 = 1.f / l1;

    float* Ob = g_O + ((size_t)(b * SEQ + q0 + w * 16)) * DMODEL + h * DH;
    #pragma unroll
    for (int nb = 0; nb < 8; nb++) {
        *(float2*)(Ob + (size_t)gid * DMODEL + nb * 8 + 2 * tid4) =
            make_float2(to_tf32_rn(Oa[nb][0] * inv0), to_tf32_rn(Oa[nb][1] * inv0));
        *(float2*)(Ob + (size_t)(gid + 8) * DMODEL + nb * 8 + 2 * tid4) =
            make_float2(to_tf32_rn(Oa[nb][2] * inv1), to_tf32_rn(Oa[nb][3] * inv1));
    }
}

// ---------------------------------------------------------------------------
// Launch:  inputs 0=queries 1=keys 2=values 3=masks 4=Wq 5=Wk 6=Wv 7=Wo
// ---------------------------------------------------------------------------
extern "C" void kernel_launch(void* const* d_in, const int* in_sizes, int n_in,
                              void* d_out, int out_size) {
    const int* masks = (const int*)d_in[3];
    float* out = (float*)d_out;

    float *gq, *gk, *gv, *go, *gwt, *gr;
    cudaGetSymbolAddress((void**)&gq,  g_Q);
    cudaGetSymbolAddress((void**)&gk,  g_K);
    cudaGetSymbolAddress((void**)&gv,  g_V);
    cudaGetSymbolAddress((void**)&go,  g_O);
    cudaGetSymbolAddress((void**)&gwt, g_Wt);
    cudaGetSymbolAddress((void**)&gr,  g_R);

    cudaFuncSetAttribute(gemm_tf32_kernel<true>,
                         cudaFuncAttributeMaxDynamicSharedMemorySize, SM_GEMM_BYTES);
    cudaFuncSetAttribute(gemm_tf32_kernel<false>,
                         cudaFuncAttributeMaxDynamicSharedMemorySize, SM_GEMM_BYTES);
    cudaFuncSetAttribute(attn_mma_kernel,
                         cudaFuncAttributeMaxDynamicSharedMemorySize, ATT_SMEM);

    // Round inputs to tf32
    R3 rp;
    for (int i = 0; i < 3; i++) rp.s[i] = (const float4*)d_in[i];
    round3_kernel<<<dim3(512, 1, 3), 256>>>(rp);

    // Transpose + round the 4 weight matrices
    WPtrs wp;
    for (int i = 0; i < 4; i++) {
        wp.s[i] = (const float*)d_in[4 + i];
        wp.d[i] = gwt + (size_t)i * DMODEL * DMODEL;
    }
    transpose_k<<<dim3(32, 32, 4), dim3(32, 8)>>>(wp);

    const size_t NN = (size_t)MTOT * DMODEL;
    dim3 gg(DMODEL / BN, MTOT / BM);   // (8, 32) = 256 CTAs
    gemm_tf32_kernel<true ><<<gg, 256, SM_GEMM_BYTES>>>(gr + 0 * NN, gwt + 0 * (size_t)DMODEL * DMODEL, gq);
    gemm_tf32_kernel<true ><<<gg, 256, SM_GEMM_BYTES>>>(gr + 1 * NN, gwt + 1 * (size_t)DMODEL * DMODEL, gk);
    gemm_tf32_kernel<true ><<<gg, 256, SM_GEMM_BYTES>>>(gr + 2 * NN, gwt + 2 * (size_t)DMODEL * DMODEL, gv);

    dim3 ga(SEQ / ATT_BQ, NH, BATCH);  // (16, 16, 2) = 512 CTAs
    attn_mma_kernel<<<ga, 256, ATT_SMEM>>>(masks);

    gemm_tf32_kernel<false><<<gg, 256, SM_GEMM_BYTES>>>(go, gwt + 3 * (size_t)DMODEL * DMODEL, out);
}

// round 9
// speedup vs baseline: 3.3843x; 1.0120x over previous
#include <cuda_runtime.h>
#include <math_constants.h>
#include <cstdint>

#define SEQ    2048
#define DMODEL 1024
#define NH     16
#define DH     64
#define BATCH  2
#define MTOT   (BATCH*SEQ)   // 4096 rows

// ---------------------------------------------------------------------------
// Device scratch (allocation-free rule)
// ---------------------------------------------------------------------------
__device__ float g_Q[(size_t)MTOT*DMODEL];
__device__ float g_K[(size_t)MTOT*DMODEL];
__device__ float g_V[(size_t)MTOT*DMODEL];
__device__ float g_O[(size_t)MTOT*DMODEL];
__device__ float g_Wt[4][(size_t)DMODEL*DMODEL];   // transposed+rounded weights [N][K]
__device__ float g_R[3][(size_t)MTOT*DMODEL];      // rounded inputs (q,k,v)

// ---------------------------------------------------------------------------
// Helpers
// ---------------------------------------------------------------------------
__device__ __forceinline__ uint32_t smem_u32(const void* p) {
    uint32_t a;
    asm("{ .reg .u64 t; cvta.to.shared.u64 t, %1; cvt.u32.u64 %0, t; }" : "=r"(a) : "l"(p));
    return a;
}
__device__ __forceinline__ float to_tf32_rn(float x) {
    uint32_t r;
    asm("cvt.rna.tf32.f32 %0, %1;" : "=r"(r) : "f"(x));
    return __uint_as_float(r);
}
__device__ __forceinline__ void cp16(uint32_t dst, const void* src) {
    asm volatile("cp.async.cg.shared.global [%0], [%1], 16;" :: "r"(dst), "l"(src));
}
#define CP_COMMIT() asm volatile("cp.async.commit_group;" ::: "memory")
#define CP_WAIT0()  asm volatile("cp.async.wait_group 0;" ::: "memory")
#define CP_WAIT1()  asm volatile("cp.async.wait_group 1;" ::: "memory")

// m16n8k8 tf32 mma (baseline PTX, sm_80+)
__device__ __forceinline__ void mma_tf32(float* c, const uint32_t* a, const uint32_t* b) {
    asm volatile(
        "mma.sync.aligned.m16n8k8.row.col.f32.tf32.tf32.f32 "
        "{%0,%1,%2,%3}, {%4,%5,%6,%7}, {%8,%9}, {%0,%1,%2,%3};"
        : "+f"(c[0]), "+f"(c[1]), "+f"(c[2]), "+f"(c[3])
        : "r"(a[0]), "r"(a[1]), "r"(a[2]), "r"(a[3]), "r"(b[0]), "r"(b[1]));
}

// Fast exp (FFMA-only); args <= 0
__device__ __forceinline__ float fexp(float x) {
    float y = x * 1.4426950408889634f;
    y = fmaxf(y, -126.0f);
    int   e = __float2int_rn(y);
    float f = y - (float)e;
    float p = 1.3333558146e-3f;
    p = fmaf(p, f, 9.6181298421e-3f);
    p = fmaf(p, f, 5.5504108664e-2f);
    p = fmaf(p, f, 2.4022650696e-1f);
    p = fmaf(p, f, 6.9314718056e-1f);
    p = fmaf(p, f, 1.0f);
    return p * __int_as_float((e + 127) << 23);
}

// ---------------------------------------------------------------------------
// Round queries/keys/values to tf32
// ---------------------------------------------------------------------------
struct R3 { const float4* s[3]; };

__global__ __launch_bounds__(256) void round3_kernel(R3 p) {
    const int z = blockIdx.z;
    const float4* S = p.s[z];
    float4* D = (float4*)(g_R[z]);
    const int n4 = MTOT * DMODEL / 4;
    for (int i = blockIdx.x * 256 + threadIdx.x; i < n4; i += gridDim.x * 256) {
        float4 v = S[i];
        v.x = to_tf32_rn(v.x); v.y = to_tf32_rn(v.y);
        v.z = to_tf32_rn(v.z); v.w = to_tf32_rn(v.w);
        D[i] = v;
    }
}

// ---------------------------------------------------------------------------
// Weight transpose + round: Wt[n][k] = tf32(W[k][n])
// ---------------------------------------------------------------------------
struct WPtrs { const float* s[4]; float* d[4]; };

__global__ __launch_bounds__(256) void transpose_k(WPtrs p) {
    __shared__ float tile[32][33];
    const float* S = p.s[blockIdx.z];
    float*       D = p.d[blockIdx.z];
    int x0 = blockIdx.x * 32, y0 = blockIdx.y * 32;
    int tx = threadIdx.x, ty = threadIdx.y;          // (32, 8)
    #pragma unroll
    for (int j = 0; j < 32; j += 8)
        tile[ty + j][tx] = S[(size_t)(y0 + ty + j) * DMODEL + x0 + tx];
    __syncthreads();
    #pragma unroll
    for (int j = 0; j < 32; j += 8)
        D[(size_t)(x0 + ty + j) * DMODEL + y0 + tx] = to_tf32_rn(tile[tx][ty + j]);
}

// ---------------------------------------------------------------------------
// tf32 tensor-core GEMM (cp.async 3-stage, single barrier per K-iter).
// Batched over blockIdx.z: C[z][M,1024] = A[z][M,K] * Bt[z][N,K]^T
// ---------------------------------------------------------------------------
#define BM 128
#define BN 128
#define BK 32
#define KT_GEMM (DMODEL / BK)          // 32
#define ROWP 36
#define TILE_F (128 * ROWP)            // 4608 floats per operand tile
#define GSTG 3
#define SM_GEMM_BYTES (GSTG * 2 * TILE_F * 4)   // 110592 B

struct GemmBatch { const float* A[3]; const float* B[3]; float* C[3]; };

template<bool ROUND>
__global__ __launch_bounds__(256, 2) void gemm_tf32_kernel(GemmBatch gb) {
    extern __shared__ float sm[];
    const uint32_t sb = smem_u32(sm);

    const float* __restrict__ A  = gb.A[blockIdx.z];
    const float* __restrict__ Bt = gb.B[blockIdx.z];
    float* __restrict__ C        = gb.C[blockIdx.z];

    const int t     = threadIdx.x;
    const int wid   = t >> 5;
    const int lane  = t & 31;
    const int wm    = wid & 1;
    const int wn    = wid >> 1;
    const int lane4 = lane >> 2;
    const int lanek = lane & 3;
    const int m0 = blockIdx.y * BM;
    const int n0 = blockIdx.x * BN;
    const int lrow = t >> 3, lc4 = t & 7;   // loader coords

    float acc[4][4][4];
    #pragma unroll
    for (int mi = 0; mi < 4; mi++)
        #pragma unroll
        for (int ni = 0; ni < 4; ni++)
            #pragma unroll
            for (int f = 0; f < 4; f++) acc[mi][ni][f] = 0.f;

    auto issue = [&](int kt, int s) {
        const float* Ap = A  + (size_t)m0 * DMODEL + kt * BK;
        const float* Bp = Bt + (size_t)n0 * DMODEL + kt * BK;
        #pragma unroll
        for (int i = 0; i < 4; i++) {
            int row = lrow + i * 32;
            cp16(sb + (uint32_t)((s * 2 * TILE_F + row * ROWP + lc4 * 4) * 4),
                 Ap + (size_t)row * DMODEL + lc4 * 4);
            cp16(sb + (uint32_t)((s * 2 * TILE_F + TILE_F + row * ROWP + lc4 * 4) * 4),
                 Bp + (size_t)row * DMODEL + lc4 * 4);
        }
        CP_COMMIT();
    };

    issue(0, 0);
    issue(1, 1);

    for (int kt = 0; kt < KT_GEMM; kt++) {
        const int s = kt % 3;
        if (kt < KT_GEMM - 1) CP_WAIT1(); else CP_WAIT0();
        __syncthreads();
        // Single barrier per iteration: overwriting stage (kt+2)%3 == stage
        // (kt-1)%3 is safe because every warp passed the barrier above only
        // after finishing compute of iteration kt-1.
        if (kt + 2 < KT_GEMM) issue(kt + 2, (kt + 2) % 3);

        const float* Atile = sm + s * 2 * TILE_F;
        const float* Btile = Atile + TILE_F;
        #pragma unroll
        for (int ks = 0; ks < 4; ks++) {
            const int kc = ks * 8 + lanek;
            uint32_t a[4][4], b[4][2];
            #pragma unroll
            for (int mi = 0; mi < 4; mi++) {
                int r = wm * 64 + mi * 16 + lane4;
                a[mi][0] = __float_as_uint(Atile[(r    ) * ROWP + kc    ]);
                a[mi][1] = __float_as_uint(Atile[(r + 8) * ROWP + kc    ]);
                a[mi][2] = __float_as_uint(Atile[(r    ) * ROWP + kc + 4]);
                a[mi][3] = __float_as_uint(Atile[(r + 8) * ROWP + kc + 4]);
            }
            #pragma unroll
            for (int ni = 0; ni < 4; ni++) {
                int r = wn * 32 + ni * 8 + lane4;
                b[ni][0] = __float_as_uint(Btile[r * ROWP + kc    ]);
                b[ni][1] = __float_as_uint(Btile[r * ROWP + kc + 4]);
            }
            #pragma unroll
            for (int mi = 0; mi < 4; mi++)
                #pragma unroll
                for (int ni = 0; ni < 4; ni++)
                    mma_tf32(acc[mi][ni], a[mi], b[ni]);
        }
        // no trailing barrier
    }

    #pragma unroll
    for (int mi = 0; mi < 4; mi++) {
        #pragma unroll
        for (int ni = 0; ni < 4; ni++) {
            int row = m0 + wm * 64 + mi * 16 + lane4;
            int col = n0 + wn * 32 + ni * 8 + 2 * lanek;
            float v0 = acc[mi][ni][0], v1 = acc[mi][ni][1];
            float v2 = acc[mi][ni][2], v3 = acc[mi][ni][3];
            if (ROUND) {
                v0 = to_tf32_rn(v0); v1 = to_tf32_rn(v1);
                v2 = to_tf32_rn(v2); v3 = to_tf32_rn(v3);
            }
            *(float2*)(C + (size_t)row * DMODEL + col)       = make_float2(v0, v1);
            *(float2*)(C + (size_t)(row + 8) * DMODEL + col) = make_float2(v2, v3);
        }
    }
}

// ---------------------------------------------------------------------------
// Tensor-core flash attention (unchanged from R7)
// ---------------------------------------------------------------------------
#define ATT_BQ   128
#define ATT_BKV  64
#define APAD     68
#define ATT_KV_F (2 * ATT_BKV * APAD)
#define ATT_P_OFF (2 * ATT_KV_F)
#define ATT_MSK_OFF (ATT_P_OFF + 8 * 16 * APAD)
#define ATT_SMEM ((ATT_MSK_OFF + SEQ) * 4)            // 112640 B

__global__ __launch_bounds__(256, 2) void attn_mma_kernel(const int* __restrict__ masks) {
    extern __shared__ float smf[];
    const uint32_t sb = smem_u32(smf);
    float* Ps  = smf + ATT_P_OFF;
    float* msf = smf + ATT_MSK_OFF;

    const int t    = threadIdx.x;
    const int w    = t >> 5;
    const int lane = t & 31;
    const int gid  = lane >> 2;
    const int tid4 = lane & 3;
    const int b  = blockIdx.z;
    const int h  = blockIdx.y;
    const int q0 = blockIdx.x * ATT_BQ;

    for (int i = t; i < SEQ; i += 256)
        msf[i] = masks[b * SEQ + i] ? 0.f : -1e30f;

    uint32_t aQ[8][4];
    {
        const float* Qb = g_Q + ((size_t)(b * SEQ + q0 + w * 16)) * DMODEL + h * DH;
        #pragma unroll
        for (int kk = 0; kk < 8; kk++) {
            int c = kk * 8 + tid4;
            aQ[kk][0] = __float_as_uint(0.125f * Qb[(size_t)gid       * DMODEL + c    ]);
            aQ[kk][1] = __float_as_uint(0.125f * Qb[(size_t)(gid + 8) * DMODEL + c    ]);
            aQ[kk][2] = __float_as_uint(0.125f * Qb[(size_t)gid       * DMODEL + c + 4]);
            aQ[kk][3] = __float_as_uint(0.125f * Qb[(size_t)(gid + 8) * DMODEL + c + 4]);
        }
    }

    float Oa[8][4];
    #pragma unroll
    for (int nb = 0; nb < 8; nb++)
        #pragma unroll
        for (int f = 0; f < 4; f++) Oa[nb][f] = 0.f;
    float m0 = -1e30f, m1 = -1e30f, l0 = 0.f, l1 = 0.f;

    float* Pw = Ps + w * 16 * APAD;

    auto issue_kv = [&](int kv0, int s) {
        const float* Kb = g_K + ((size_t)(b * SEQ + kv0)) * DMODEL + h * DH;
        const float* Vb = g_V + ((size_t)(b * SEQ + kv0)) * DMODEL + h * DH;
        #pragma unroll
        for (int i = 0; i < 4; i++) {
            int idx = i * 256 + t;
            int row = idx >> 4, c4 = (idx & 15) * 4;
            cp16(sb + (uint32_t)((s * ATT_KV_F + row * APAD + c4) * 4),
                 Kb + (size_t)row * DMODEL + c4);
            cp16(sb + (uint32_t)((s * ATT_KV_F + ATT_BKV * APAD + row * APAD + c4) * 4),
                 Vb + (size_t)row * DMODEL + c4);
        }
        CP_COMMIT();
    };

    issue_kv(0, 0);

    for (int kv0 = 0; kv0 < SEQ; kv0 += ATT_BKV) {
        const int s = (kv0 >> 6) & 1;
        CP_WAIT0();
        __syncthreads();
        if (kv0 + ATT_BKV < SEQ) issue_kv(kv0 + ATT_BKV, s ^ 1);

        const float* Ks = smf + s * ATT_KV_F;
        const float* Vs = Ks + ATT_BKV * APAD;

        float sc[8][4];
        #pragma unroll
        for (int nb = 0; nb < 8; nb++) {
            sc[nb][0] = sc[nb][1] = sc[nb][2] = sc[nb][3] = 0.f;
            const float* Kr = Ks + (nb * 8 + gid) * APAD + tid4;
            #pragma unroll
            for (int kk = 0; kk < 8; kk++) {
                uint32_t bk[2];
                bk[0] = __float_as_uint(Kr[kk * 8    ]);
                bk[1] = __float_as_uint(Kr[kk * 8 + 4]);
                mma_tf32(sc[nb], aQ[kk], bk);
            }
        }

        float tm0 = -1e30f, tm1 = -1e30f;
        #pragma unroll
        for (int nb = 0; nb < 8; nb++) {
            float2 mm = *(const float2*)(msf + kv0 + nb * 8 + 2 * tid4);
            sc[nb][0] += mm.x; sc[nb][1] += mm.y;
            sc[nb][2] += mm.x; sc[nb][3] += mm.y;
            tm0 = fmaxf(tm0, fmaxf(sc[nb][0], sc[nb][1]));
            tm1 = fmaxf(tm1, fmaxf(sc[nb][2], sc[nb][3]));
        }
        tm0 = fmaxf(tm0, __shfl_xor_sync(0xffffffffu, tm0, 1));
        tm0 = fmaxf(tm0, __shfl_xor_sync(0xffffffffu, tm0, 2));
        tm1 = fmaxf(tm1, __shfl_xor_sync(0xffffffffu, tm1, 1));
        tm1 = fmaxf(tm1, __shfl_xor_sync(0xffffffffu, tm1, 2));

        float mn0 = fmaxf(m0, tm0), mn1 = fmaxf(m1, tm1);
        float al0 = fexp(m0 - mn0), al1 = fexp(m1 - mn1);
        m0 = mn0; m1 = mn1;

        float lp0 = 0.f, lp1 = 0.f;
        #pragma unroll
        for (int nb = 0; nb < 8; nb++) {
            float p0 = fexp(sc[nb][0] - m0);
            float p1 = fexp(sc[nb][1] - m0);
            float p2 = fexp(sc[nb][2] - m1);
            float p3 = fexp(sc[nb][3] - m1);
            lp0 += p0 + p1; lp1 += p2 + p3;
            *(float2*)(Pw + gid * APAD + nb * 8 + 2 * tid4) =
                make_float2(to_tf32_rn(p0), to_tf32_rn(p1));
            *(float2*)(Pw + (gid + 8) * APAD + nb * 8 + 2 * tid4) =
                make_float2(to_tf32_rn(p2), to_tf32_rn(p3));
        }
        l0 = l0 * al0 + lp0;
        l1 = l1 * al1 + lp1;
        #pragma unroll
        for (int nb = 0; nb < 8; nb++) {
            Oa[nb][0] *= al0; Oa[nb][1] *= al0;
            Oa[nb][2] *= al1; Oa[nb][3] *= al1;
        }
        __syncwarp();

        #pragma unroll
        for (int kk = 0; kk < 8; kk++) {
            uint32_t aP[4];
            const float* Pr = Pw + gid * APAD + kk * 8 + tid4;
            aP[0] = __float_as_uint(Pr[0]);
            aP[1] = __float_as_uint(Pr[8 * APAD]);
            aP[2] = __float_as_uint(Pr[4]);
            aP[3] = __float_as_uint(Pr[8 * APAD + 4]);
            const float* Vr = Vs + (kk * 8 + tid4) * APAD + gid;
            #pragma unroll
            for (int nb = 0; nb < 8; nb++) {
                uint32_t bv[2];
                bv[0] = __float_as_uint(Vr[nb * 8]);
                bv[1] = __float_as_uint(Vr[4 * APAD + nb * 8]);
                mma_tf32(Oa[nb], aP, bv);
            }
        }
        __syncwarp();
    }

    l0 += __shfl_xor_sync(0xffffffffu, l0, 1);
    l0 += __shfl_xor_sync(0xffffffffu, l0, 2);
    l1 += __shfl_xor_sync(0xffffffffu, l1, 1);
    l1 += __shfl_xor_sync(0xffffffffu, l1, 2);
    float inv0 = 1.f / l0, inv1 = 1.f / l1;

    float* Ob = g_O + ((size_t)(b * SEQ + q0 + w * 16)) * DMODEL + h * DH;
    #pragma unroll
    for (int nb = 0; nb < 8; nb++) {
        *(float2*)(Ob + (size_t)gid * DMODEL + nb * 8 + 2 * tid4) =
            make_float2(to_tf32_rn(Oa[nb][0] * inv0), to_tf32_rn(Oa[nb][1] * inv0));
        *(float2*)(Ob + (size_t)(gid + 8) * DMODEL + nb * 8 + 2 * tid4) =
            make_float2(to_tf32_rn(Oa[nb][2] * inv1), to_tf32_rn(Oa[nb][3] * inv1));
    }
}

// ---------------------------------------------------------------------------
// Launch:  inputs 0=queries 1=keys 2=values 3=masks 4=Wq 5=Wk 6=Wv 7=Wo
// ---------------------------------------------------------------------------
extern "C" void kernel_launch(void* const* d_in, const int* in_sizes, int n_in,
                              void* d_out, int out_size) {
    const int* masks = (const int*)d_in[3];
    float* out = (float*)d_out;

    float *gq, *gk, *gv, *go, *gwt, *gr;
    cudaGetSymbolAddress((void**)&gq,  g_Q);
    cudaGetSymbolAddress((void**)&gk,  g_K);
    cudaGetSymbolAddress((void**)&gv,  g_V);
    cudaGetSymbolAddress((void**)&go,  g_O);
    cudaGetSymbolAddress((void**)&gwt, g_Wt);
    cudaGetSymbolAddress((void**)&gr,  g_R);

    cudaFuncSetAttribute(gemm_tf32_kernel<true>,
                         cudaFuncAttributeMaxDynamicSharedMemorySize, SM_GEMM_BYTES);
    cudaFuncSetAttribute(gemm_tf32_kernel<false>,
                         cudaFuncAttributeMaxDynamicSharedMemorySize, SM_GEMM_BYTES);
    cudaFuncSetAttribute(attn_mma_kernel,
                         cudaFuncAttributeMaxDynamicSharedMemorySize, ATT_SMEM);

    // Round inputs to tf32
    R3 rp;
    for (int i = 0; i < 3; i++) rp.s[i] = (const float4*)d_in[i];
    round3_kernel<<<dim3(512, 1, 3), 256>>>(rp);

    // Transpose + round the 4 weight matrices
    WPtrs wp;
    for (int i = 0; i < 4; i++) {
        wp.s[i] = (const float*)d_in[4 + i];
        wp.d[i] = gwt + (size_t)i * DMODEL * DMODEL;
    }
    transpose_k<<<dim3(32, 32, 4), dim3(32, 8)>>>(wp);

    const size_t NN  = (size_t)MTOT * DMODEL;
    const size_t NN2 = (size_t)DMODEL * DMODEL;

    // Fused Q/K/V projections: one launch, blockIdx.z selects matrix
    GemmBatch g1;
    g1.A[0] = gr + 0 * NN; g1.B[0] = gwt + 0 * NN2; g1.C[0] = gq;
    g1.A[1] = gr + 1 * NN; g1.B[1] = gwt + 1 * NN2; g1.C[1] = gk;
    g1.A[2] = gr + 2 * NN; g1.B[2] = gwt + 2 * NN2; g1.C[2] = gv;
    gemm_tf32_kernel<true><<<dim3(DMODEL / BN, MTOT / BM, 3), 256, SM_GEMM_BYTES>>>(g1);

    dim3 ga(SEQ / ATT_BQ, NH, BATCH);  // (16, 16, 2) = 512 CTAs
    attn_mma_kernel<<<ga, 256, ATT_SMEM>>>(masks);

    GemmBatch g2;
    g2.A[0] = go; g2.B[0] = gwt + 3 * NN2; g2.C[0] = out;
    g2.A[1] = g2.A[2] = nullptr; g2.B[1] = g2.B[2] = nullptr; g2.C[1] = g2.C[2] = nullptr;
    gemm_tf32_kernel<false><<<dim3(DMODEL / BN, MTOT / BM, 1), 256, SM_GEMM_BYTES>>>(g2);
}

// round 10
// speedup vs baseline: 3.7167x; 1.0982x over previous
#include <cuda_runtime.h>
#include <math_constants.h>
#include <cstdint>

#define SEQ    2048
#define DMODEL 1024
#define NH     16
#define DH     64
#define BATCH  2
#define MTOT   (BATCH*SEQ)   // 4096 rows

// ---------------------------------------------------------------------------
// Device scratch (allocation-free rule)
// ---------------------------------------------------------------------------
__device__ float g_Q[(size_t)MTOT*DMODEL];
__device__ float g_K[(size_t)MTOT*DMODEL];
__device__ float g_Vt[(size_t)BATCH*NH*DH*SEQ];    // V output, [b,h][d][token]
__device__ float g_O[(size_t)MTOT*DMODEL];
__device__ float g_Wt[4][(size_t)DMODEL*DMODEL];   // transposed+rounded weights [N][K]
__device__ float g_R[3][(size_t)MTOT*DMODEL];      // rounded inputs (q,k,v)

// ---------------------------------------------------------------------------
// Helpers
// ---------------------------------------------------------------------------
__device__ __forceinline__ uint32_t smem_u32(const void* p) {
    uint32_t a;
    asm("{ .reg .u64 t; cvta.to.shared.u64 t, %1; cvt.u32.u64 %0, t; }" : "=r"(a) : "l"(p));
    return a;
}
__device__ __forceinline__ float to_tf32_rn(float x) {
    uint32_t r;
    asm("cvt.rna.tf32.f32 %0, %1;" : "=r"(r) : "f"(x));
    return __uint_as_float(r);
}
__device__ __forceinline__ void cp16(uint32_t dst, const void* src) {
    asm volatile("cp.async.cg.shared.global [%0], [%1], 16;" :: "r"(dst), "l"(src));
}
#define CP_COMMIT() asm volatile("cp.async.commit_group;" ::: "memory")
#define CP_WAIT0()  asm volatile("cp.async.wait_group 0;" ::: "memory")
#define CP_WAIT1()  asm volatile("cp.async.wait_group 1;" ::: "memory")

// ldmatrix x4: four 8x8 b16 tiles == four 8x4 f32 tiles (tf32 fragment layout)
__device__ __forceinline__ void ldsm4(uint32_t& r0, uint32_t& r1, uint32_t& r2,
                                      uint32_t& r3, uint32_t addr) {
    asm volatile("ldmatrix.sync.aligned.m8n8.x4.shared.b16 {%0,%1,%2,%3}, [%4];"
                 : "=r"(r0), "=r"(r1), "=r"(r2), "=r"(r3) : "r"(addr));
}

// m16n8k8 tf32 mma (baseline PTX, sm_80+)
__device__ __forceinline__ void mma_tf32(float* c, const uint32_t* a, const uint32_t* b) {
    asm volatile(
        "mma.sync.aligned.m16n8k8.row.col.f32.tf32.tf32.f32 "
        "{%0,%1,%2,%3}, {%4,%5,%6,%7}, {%8,%9}, {%0,%1,%2,%3};"
        : "+f"(c[0]), "+f"(c[1]), "+f"(c[2]), "+f"(c[3])
        : "r"(a[0]), "r"(a[1]), "r"(a[2]), "r"(a[3]), "r"(b[0]), "r"(b[1]));
}

// Fast exp (FFMA-only); args <= 0
__device__ __forceinline__ float fexp(float x) {
    float y = x * 1.4426950408889634f;
    y = fmaxf(y, -126.0f);
    int   e = __float2int_rn(y);
    float f = y - (float)e;
    float p = 1.3333558146e-3f;
    p = fmaf(p, f, 9.6181298421e-3f);
    p = fmaf(p, f, 5.5504108664e-2f);
    p = fmaf(p, f, 2.4022650696e-1f);
    p = fmaf(p, f, 6.9314718056e-1f);
    p = fmaf(p, f, 1.0f);
    return p * __int_as_float((e + 127) << 23);
}

// ---------------------------------------------------------------------------
// Round queries/keys/values to tf32
// ---------------------------------------------------------------------------
struct R3 { const float4* s[3]; };

__global__ __launch_bounds__(256) void round3_kernel(R3 p) {
    const int z = blockIdx.z;
    const float4* S = p.s[z];
    float4* D = (float4*)(g_R[z]);
    const int n4 = MTOT * DMODEL / 4;
    for (int i = blockIdx.x * 256 + threadIdx.x; i < n4; i += gridDim.x * 256) {
        float4 v = S[i];
        v.x = to_tf32_rn(v.x); v.y = to_tf32_rn(v.y);
        v.z = to_tf32_rn(v.z); v.w = to_tf32_rn(v.w);
        D[i] = v;
    }
}

// ---------------------------------------------------------------------------
// Weight transpose + round: Wt[n][k] = tf32(W[k][n])
// ---------------------------------------------------------------------------
struct WPtrs { const float* s[4]; float* d[4]; };

__global__ __launch_bounds__(256) void transpose_k(WPtrs p) {
    __shared__ float tile[32][33];
    const float* S = p.s[blockIdx.z];
    float*       D = p.d[blockIdx.z];
    int x0 = blockIdx.x * 32, y0 = blockIdx.y * 32;
    int tx = threadIdx.x, ty = threadIdx.y;          // (32, 8)
    #pragma unroll
    for (int j = 0; j < 32; j += 8)
        tile[ty + j][tx] = S[(size_t)(y0 + ty + j) * DMODEL + x0 + tx];
    __syncthreads();
    #pragma unroll
    for (int j = 0; j < 32; j += 8)
        D[(size_t)(x0 + ty + j) * DMODEL + y0 + tx] = to_tf32_rn(tile[tx][ty + j]);
}

// ---------------------------------------------------------------------------
// tf32 tensor-core GEMM (cp.async 3-stage, single barrier per K-iter).
// Batched over blockIdx.z. z==2 (V projection) stores transposed to g_Vt.
// ---------------------------------------------------------------------------
#define BM 128
#define BN 128
#define BK 32
#define KT_GEMM (DMODEL / BK)          // 32
#define ROWP 36
#define TILE_F (128 * ROWP)
#define GSTG 3
#define SM_GEMM_BYTES (GSTG * 2 * TILE_F * 4)   // 110592 B

struct GemmBatch { const float* A[3]; const float* B[3]; float* C[3]; };

template<bool ROUND>
__global__ __launch_bounds__(256, 2) void gemm_tf32_kernel(GemmBatch gb) {
    extern __shared__ float sm[];
    const uint32_t sb = smem_u32(sm);

    const float* __restrict__ A  = gb.A[blockIdx.z];
    const float* __restrict__ Bt = gb.B[blockIdx.z];
    float* __restrict__ C        = gb.C[blockIdx.z];

    const int t     = threadIdx.x;
    const int wid   = t >> 5;
    const int lane  = t & 31;
    const int wm    = wid & 1;
    const int wn    = wid >> 1;
    const int lane4 = lane >> 2;
    const int lanek = lane & 3;
    const int m0 = blockIdx.y * BM;
    const int n0 = blockIdx.x * BN;
    const int lrow = t >> 3, lc4 = t & 7;

    float acc[4][4][4];
    #pragma unroll
    for (int mi = 0; mi < 4; mi++)
        #pragma unroll
        for (int ni = 0; ni < 4; ni++)
            #pragma unroll
            for (int f = 0; f < 4; f++) acc[mi][ni][f] = 0.f;

    auto issue = [&](int kt, int s) {
        const float* Ap = A  + (size_t)m0 * DMODEL + kt * BK;
        const float* Bp = Bt + (size_t)n0 * DMODEL + kt * BK;
        #pragma unroll
        for (int i = 0; i < 4; i++) {
            int row = lrow + i * 32;
            cp16(sb + (uint32_t)((s * 2 * TILE_F + row * ROWP + lc4 * 4) * 4),
                 Ap + (size_t)row * DMODEL + lc4 * 4);
            cp16(sb + (uint32_t)((s * 2 * TILE_F + TILE_F + row * ROWP + lc4 * 4) * 4),
                 Bp + (size_t)row * DMODEL + lc4 * 4);
        }
        CP_COMMIT();
    };

    issue(0, 0);
    issue(1, 1);

    for (int kt = 0; kt < KT_GEMM; kt++) {
        const int s = kt % 3;
        if (kt < KT_GEMM - 1) CP_WAIT1(); else CP_WAIT0();
        __syncthreads();
        if (kt + 2 < KT_GEMM) issue(kt + 2, (kt + 2) % 3);

        const float* Atile = sm + s * 2 * TILE_F;
        const float* Btile = Atile + TILE_F;
        #pragma unroll
        for (int ks = 0; ks < 4; ks++) {
            const int kc = ks * 8 + lanek;
            uint32_t a[4][4], b[4][2];
            #pragma unroll
            for (int mi = 0; mi < 4; mi++) {
                int r = wm * 64 + mi * 16 + lane4;
                a[mi][0] = __float_as_uint(Atile[(r    ) * ROWP + kc    ]);
                a[mi][1] = __float_as_uint(Atile[(r + 8) * ROWP + kc    ]);
                a[mi][2] = __float_as_uint(Atile[(r    ) * ROWP + kc + 4]);
                a[mi][3] = __float_as_uint(Atile[(r + 8) * ROWP + kc + 4]);
            }
            #pragma unroll
            for (int ni = 0; ni < 4; ni++) {
                int r = wn * 32 + ni * 8 + lane4;
                b[ni][0] = __float_as_uint(Btile[r * ROWP + kc    ]);
                b[ni][1] = __float_as_uint(Btile[r * ROWP + kc + 4]);
            }
            #pragma unroll
            for (int mi = 0; mi < 4; mi++)
                #pragma unroll
                for (int ni = 0; ni < 4; ni++)
                    mma_tf32(acc[mi][ni], a[mi], b[ni]);
        }
    }

    const bool vt = ROUND && (blockIdx.z == 2);
    #pragma unroll
    for (int mi = 0; mi < 4; mi++) {
        #pragma unroll
        for (int ni = 0; ni < 4; ni++) {
            int row = m0 + wm * 64 + mi * 16 + lane4;
            int col = n0 + wn * 32 + ni * 8 + 2 * lanek;
            float v0 = acc[mi][ni][0], v1 = acc[mi][ni][1];
            float v2 = acc[mi][ni][2], v3 = acc[mi][ni][3];
            if (ROUND) {
                v0 = to_tf32_rn(v0); v1 = to_tf32_rn(v1);
                v2 = to_tf32_rn(v2); v3 = to_tf32_rn(v3);
            }
            if (vt) {
                // transposed store: g_Vt[(b*NH+h)*DH + dh][token]
                int bb = row >> 11, tok = row & (SEQ - 1);
                int hh = col >> 6,  dh  = col & (DH - 1);
                float* base = g_Vt + ((size_t)(bb * NH + hh) * DH + dh) * SEQ + tok;
                base[0]           = v0;   // (row,   col)
                base[SEQ]         = v1;   // (row,   col+1)  same head (col even)
                base[8]           = v2;   // (row+8, col)
                base[SEQ + 8]     = v3;   // (row+8, col+1)
            } else {
                *(float2*)(C + (size_t)row * DMODEL + col)       = make_float2(v0, v1);
                *(float2*)(C + (size_t)(row + 8) * DMODEL + col) = make_float2(v2, v3);
            }
        }
    }
}

// ---------------------------------------------------------------------------
// Tensor-core flash attention with ldmatrix fragment loads.
// CTA: 128 q-rows of one (b,h); 8 warps x 16 rows; KV tiles of 64.
// K smem [n][k], V smem [d][kv] (from g_Vt) -> both consumed via
// ldmatrix.m8n8.x4.b16 (8x8 b16 tile == 8x4 f32 tf32 fragment).
// ---------------------------------------------------------------------------
#define ATT_BQ   128
#define ATT_BKV  64
#define APAD     68
#define ATT_KV_F (2 * ATT_BKV * APAD)
#define ATT_P_OFF (2 * ATT_KV_F)
#define ATT_MSK_OFF (ATT_P_OFF + 8 * 16 * APAD)
#define ATT_SMEM ((ATT_MSK_OFF + SEQ) * 4)            // 112640 B

__global__ __launch_bounds__(256, 2) void attn_mma_kernel(const int* __restrict__ masks) {
    extern __shared__ float smf[];
    const uint32_t sb = smem_u32(smf);
    float* msf = smf + ATT_MSK_OFF;

    const int t    = threadIdx.x;
    const int w    = t >> 5;
    const int lane = t & 31;
    const int gid  = lane >> 2;
    const int tid4 = lane & 3;
    const int lm   = lane >> 3;    // ldmatrix matrix id 0..3
    const int lr   = lane & 7;     // ldmatrix row within matrix
    const int b  = blockIdx.z;
    const int h  = blockIdx.y;
    const int q0 = blockIdx.x * ATT_BQ;

    for (int i = t; i < SEQ; i += 256)
        msf[i] = masks[b * SEQ + i] ? 0.f : -1e30f;

    // ldmatrix per-lane address components (bytes)
    const uint32_t kCol = (uint32_t)(((lm >> 1) * 8 + (lm & 1) * 4) * 4); // kk-pair sel
    const uint32_t vRow = (uint32_t)(((lm >> 1) * 8 + lr) * APAD * 4);    // nb-pair sel
    const uint32_t vCol = (uint32_t)((lm & 1) * 4 * 4);
    const uint32_t pAdr = sb + (uint32_t)((ATT_P_OFF + (w * 16 + (lm & 1) * 8 + lr) * APAD) * 4)
                        + (uint32_t)((lm >> 1) * 4 * 4);

    // Q fragments (g_Q pre-rounded tf32; *0.125 exact)
    uint32_t aQ[8][4];
    {
        const float* Qb = g_Q + ((size_t)(b * SEQ + q0 + w * 16)) * DMODEL + h * DH;
        #pragma unroll
        for (int kk = 0; kk < 8; kk++) {
            int c = kk * 8 + tid4;
            aQ[kk][0] = __float_as_uint(0.125f * Qb[(size_t)gid       * DMODEL + c    ]);
            aQ[kk][1] = __float_as_uint(0.125f * Qb[(size_t)(gid + 8) * DMODEL + c    ]);
            aQ[kk][2] = __float_as_uint(0.125f * Qb[(size_t)gid       * DMODEL + c + 4]);
            aQ[kk][3] = __float_as_uint(0.125f * Qb[(size_t)(gid + 8) * DMODEL + c + 4]);
        }
    }

    float Oa[8][4];
    #pragma unroll
    for (int nb = 0; nb < 8; nb++)
        #pragma unroll
        for (int f = 0; f < 4; f++) Oa[nb][f] = 0.f;
    float m0 = -1e30f, m1 = -1e30f, l0 = 0.f, l1 = 0.f;

    float* Pw = smf + ATT_P_OFF + w * 16 * APAD;

    auto issue_kv = [&](int kv0, int s) {
        const float* Kb  = g_K  + ((size_t)(b * SEQ + kv0)) * DMODEL + h * DH;
        const float* Vtb = g_Vt + ((size_t)(b * NH + h) * DH) * SEQ + kv0;
        #pragma unroll
        for (int i = 0; i < 4; i++) {
            int idx = i * 256 + t;
            int row = idx >> 4, c4 = (idx & 15) * 4;
            cp16(sb + (uint32_t)((s * ATT_KV_F + row * APAD + c4) * 4),
                 Kb + (size_t)row * DMODEL + c4);
            cp16(sb + (uint32_t)((s * ATT_KV_F + ATT_BKV * APAD + row * APAD + c4) * 4),
                 Vtb + (size_t)row * SEQ + c4);
        }
        CP_COMMIT();
    };

    issue_kv(0, 0);

    for (int kv0 = 0; kv0 < SEQ; kv0 += ATT_BKV) {
        const int s = (kv0 >> 6) & 1;
        CP_WAIT0();
        __syncthreads();
        if (kv0 + ATT_BKV < SEQ) issue_kv(kv0 + ATT_BKV, s ^ 1);

        const uint32_t ksAdr = sb + (uint32_t)(s * ATT_KV_F * 4);
        const uint32_t vsAdr = ksAdr + (uint32_t)(ATT_BKV * APAD * 4);

        // S = (Q/8) . K^T  -- K fragments via ldmatrix
        float sc[8][4];
        #pragma unroll
        for (int nb = 0; nb < 8; nb++) {
            sc[nb][0] = sc[nb][1] = sc[nb][2] = sc[nb][3] = 0.f;
            uint32_t bk[16];
            const uint32_t rowAdr = ksAdr + (uint32_t)(((nb * 8 + lr) * APAD) * 4) + kCol;
            #pragma unroll
            for (int i = 0; i < 4; i++)
                ldsm4(bk[4*i], bk[4*i+1], bk[4*i+2], bk[4*i+3], rowAdr + i * 64);
            #pragma unroll
            for (int kk = 0; kk < 8; kk++)
                mma_tf32(sc[nb], aQ[kk], &bk[4 * (kk >> 1) + 2 * (kk & 1)]);
        }

        // Mask bias + tile row max
        float tm0 = -1e30f, tm1 = -1e30f;
        #pragma unroll
        for (int nb = 0; nb < 8; nb++) {
            float2 mm = *(const float2*)(msf + kv0 + nb * 8 + 2 * tid4);
            sc[nb][0] += mm.x; sc[nb][1] += mm.y;
            sc[nb][2] += mm.x; sc[nb][3] += mm.y;
            tm0 = fmaxf(tm0, fmaxf(sc[nb][0], sc[nb][1]));
            tm1 = fmaxf(tm1, fmaxf(sc[nb][2], sc[nb][3]));
        }
        tm0 = fmaxf(tm0, __shfl_xor_sync(0xffffffffu, tm0, 1));
        tm0 = fmaxf(tm0, __shfl_xor_sync(0xffffffffu, tm0, 2));
        tm1 = fmaxf(tm1, __shfl_xor_sync(0xffffffffu, tm1, 1));
        tm1 = fmaxf(tm1, __shfl_xor_sync(0xffffffffu, tm1, 2));

        float mn0 = fmaxf(m0, tm0), mn1 = fmaxf(m1, tm1);
        float al0 = fexp(m0 - mn0), al1 = fexp(m1 - mn1);
        m0 = mn0; m1 = mn1;

        // P = exp(S - m) -> warp-private smem (tf32); partial row sums
        float lp0 = 0.f, lp1 = 0.f;
        #pragma unroll
        for (int nb = 0; nb < 8; nb++) {
            float p0 = fexp(sc[nb][0] - m0);
            float p1 = fexp(sc[nb][1] - m0);
            float p2 = fexp(sc[nb][2] - m1);
            float p3 = fexp(sc[nb][3] - m1);
            lp0 += p0 + p1; lp1 += p2 + p3;
            *(float2*)(Pw + gid * APAD + nb * 8 + 2 * tid4) =
                make_float2(to_tf32_rn(p0), to_tf32_rn(p1));
            *(float2*)(Pw + (gid + 8) * APAD + nb * 8 + 2 * tid4) =
                make_float2(to_tf32_rn(p2), to_tf32_rn(p3));
        }
        l0 = l0 * al0 + lp0;
        l1 = l1 * al1 + lp1;
        #pragma unroll
        for (int nb = 0; nb < 8; nb++) {
            Oa[nb][0] *= al0; Oa[nb][1] *= al0;
            Oa[nb][2] *= al1; Oa[nb][3] *= al1;
        }
        __syncwarp();

        // O += P . V  -- P (A-frag) and Vt (B-frag) via ldmatrix
        #pragma unroll
        for (int kk = 0; kk < 8; kk++) {
            uint32_t aP[4];
            ldsm4(aP[0], aP[1], aP[2], aP[3], pAdr + kk * 32);
            uint32_t bv[16];
            const uint32_t vAdr = vsAdr + vRow + vCol + (uint32_t)(kk * 32);
            #pragma unroll
            for (int j = 0; j < 4; j++)
                ldsm4(bv[4*j], bv[4*j+1], bv[4*j+2], bv[4*j+3],
                      vAdr + (uint32_t)(j * 16 * APAD * 4));
            #pragma unroll
            for (int nb = 0; nb < 8; nb++)
                mma_tf32(Oa[nb], aP, &bv[4 * (nb >> 1) + 2 * (nb & 1)]);
        }
        __syncwarp();
    }

    l0 += __shfl_xor_sync(0xffffffffu, l0, 1);
    l0 += __shfl_xor_sync(0xffffffffu, l0, 2);
    l1 += __shfl_xor_sync(0xffffffffu, l1, 1);
    l1 += __shfl_xor_sync(0xffffffffu, l1, 2);
    float inv0 = 1.f / l0, inv1 = 1.f / l1;

    float* Ob = g_O + ((size_t)(b * SEQ + q0 + w * 16)) * DMODEL + h * DH;
    #pragma unroll
    for (int nb = 0; nb < 8; nb++) {
        *(float2*)(Ob + (size_t)gid * DMODEL + nb * 8 + 2 * tid4) =
            make_float2(to_tf32_rn(Oa[nb][0] * inv0), to_tf32_rn(Oa[nb][1] * inv0));
        *(float2*)(Ob + (size_t)(gid + 8) * DMODEL + nb * 8 + 2 * tid4) =
            make_float2(to_tf32_rn(Oa[nb][2] * inv1), to_tf32_rn(Oa[nb][3] * inv1));
    }
}

// ---------------------------------------------------------------------------
// Launch:  inputs 0=queries 1=keys 2=values 3=masks 4=Wq 5=Wk 6=Wv 7=Wo
// ---------------------------------------------------------------------------
extern "C" void kernel_launch(void* const* d_in, const int* in_sizes, int n_in,
                              void* d_out, int out_size) {
    const int* masks = (const int*)d_in[3];
    float* out = (float*)d_out;

    float *gq, *gk, *gvt, *go, *gwt, *gr;
    cudaGetSymbolAddress((void**)&gq,  g_Q);
    cudaGetSymbolAddress((void**)&gk,  g_K);
    cudaGetSymbolAddress((void**)&gvt, g_Vt);
    cudaGetSymbolAddress((void**)&go,  g_O);
    cudaGetSymbolAddress((void**)&gwt, g_Wt);
    cudaGetSymbolAddress((void**)&gr,  g_R);

    cudaFuncSetAttribute(gemm_tf32_kernel<true>,
                         cudaFuncAttributeMaxDynamicSharedMemorySize, SM_GEMM_BYTES);
    cudaFuncSetAttribute(gemm_tf32_kernel<false>,
                         cudaFuncAttributeMaxDynamicSharedMemorySize, SM_GEMM_BYTES);
    cudaFuncSetAttribute(attn_mma_kernel,
                         cudaFuncAttributeMaxDynamicSharedMemorySize, ATT_SMEM);

    // Round inputs to tf32
    R3 rp;
    for (int i = 0; i < 3; i++) rp.s[i] = (const float4*)d_in[i];
    round3_kernel<<<dim3(512, 1, 3), 256>>>(rp);

    // Transpose + round the 4 weight matrices
    WPtrs wp;
    for (int i = 0; i < 4; i++) {
        wp.s[i] = (const float*)d_in[4 + i];
        wp.d[i] = gwt + (size_t)i * DMODEL * DMODEL;
    }
    transpose_k<<<dim3(32, 32, 4), dim3(32, 8)>>>(wp);

    const size_t NN  = (size_t)MTOT * DMODEL;
    const size_t NN2 = (size_t)DMODEL * DMODEL;

    // Fused Q/K/V projections (z==2 stores V transposed)
    GemmBatch g1;
    g1.A[0] = gr + 0 * NN; g1.B[0] = gwt + 0 * NN2; g1.C[0] = gq;
    g1.A[1] = gr + 1 * NN; g1.B[1] = gwt + 1 * NN2; g1.C[1] = gk;
    g1.A[2] = gr + 2 * NN; g1.B[2] = gwt + 2 * NN2; g1.C[2] = gvt;  // C unused for z==2
    gemm_tf32_kernel<true><<<dim3(DMODEL / BN, MTOT / BM, 3), 256, SM_GEMM_BYTES>>>(g1);

    dim3 ga(SEQ / ATT_BQ, NH, BATCH);  // (16, 16, 2) = 512 CTAs
    attn_mma_kernel<<<ga, 256, ATT_SMEM>>>(masks);

    GemmBatch g2;
    g2.A[0] = go; g2.B[0] = gwt + 3 * NN2; g2.C[0] = out;
    g2.A[1] = g2.A[2] = nullptr; g2.B[1] = g2.B[2] = nullptr; g2.C[1] = g2.C[2] = nullptr;
    gemm_tf32_kernel<false><<<dim3(DMODEL / BN, MTOT / BM, 1), 256, SM_GEMM_BYTES>>>(g2);
}

// round 11
// speedup vs baseline: 4.1030x; 1.1039x over previous
#include <cuda_runtime.h>
#include <math_constants.h>
#include <cstdint>

#define SEQ    2048
#define DMODEL 1024
#define NH     16
#define DH     64
#define BATCH  2
#define MTOT   (BATCH*SEQ)   // 4096 rows

// ---------------------------------------------------------------------------
// Device scratch (allocation-free rule)
// ---------------------------------------------------------------------------
__device__ float g_Q[(size_t)MTOT*DMODEL];
__device__ float g_K[(size_t)MTOT*DMODEL];
__device__ float g_Vt[(size_t)BATCH*NH*DH*SEQ];    // V output, [b,h][d][token]
__device__ float g_O[(size_t)MTOT*DMODEL];
__device__ float g_Wt[4][(size_t)DMODEL*DMODEL];   // transposed+rounded weights [N][K]
__device__ float g_R[3][(size_t)MTOT*DMODEL];      // rounded inputs (q,k,v)

// ---------------------------------------------------------------------------
// Helpers
// ---------------------------------------------------------------------------
__device__ __forceinline__ uint32_t smem_u32(const void* p) {
    uint32_t a;
    asm("{ .reg .u64 t; cvta.to.shared.u64 t, %1; cvt.u32.u64 %0, t; }" : "=r"(a) : "l"(p));
    return a;
}
__device__ __forceinline__ float to_tf32_rn(float x) {
    uint32_t r;
    asm("cvt.rna.tf32.f32 %0, %1;" : "=r"(r) : "f"(x));
    return __uint_as_float(r);
}
__device__ __forceinline__ float ex2f(float y) {    // 2^y via MUFU
    float r;
    asm("ex2.approx.f32 %0, %1;" : "=f"(r) : "f"(y));
    return r;
}
__device__ __forceinline__ void cp16(uint32_t dst, const void* src) {
    asm volatile("cp.async.cg.shared.global [%0], [%1], 16;" :: "r"(dst), "l"(src));
}
#define CP_COMMIT() asm volatile("cp.async.commit_group;" ::: "memory")
#define CP_WAIT0()  asm volatile("cp.async.wait_group 0;" ::: "memory")
#define CP_WAIT1()  asm volatile("cp.async.wait_group 1;" ::: "memory")

// ldmatrix x4: four 8x8 b16 tiles == four 8x4 f32 tiles (tf32 fragment layout)
__device__ __forceinline__ void ldsm4(uint32_t& r0, uint32_t& r1, uint32_t& r2,
                                      uint32_t& r3, uint32_t addr) {
    asm volatile("ldmatrix.sync.aligned.m8n8.x4.shared.b16 {%0,%1,%2,%3}, [%4];"
                 : "=r"(r0), "=r"(r1), "=r"(r2), "=r"(r3) : "r"(addr));
}

// m16n8k8 tf32 mma (baseline PTX, sm_80+)
__device__ __forceinline__ void mma_tf32(float* c, const uint32_t* a, const uint32_t* b) {
    asm volatile(
        "mma.sync.aligned.m16n8k8.row.col.f32.tf32.tf32.f32 "
        "{%0,%1,%2,%3}, {%4,%5,%6,%7}, {%8,%9}, {%0,%1,%2,%3};"
        : "+f"(c[0]), "+f"(c[1]), "+f"(c[2]), "+f"(c[3])
        : "r"(a[0]), "r"(a[1]), "r"(a[2]), "r"(a[3]), "r"(b[0]), "r"(b[1]));
}

// ---------------------------------------------------------------------------
// Round queries/keys/values to tf32
// ---------------------------------------------------------------------------
struct R3 { const float4* s[3]; };

__global__ __launch_bounds__(256) void round3_kernel(R3 p) {
    const int z = blockIdx.z;
    const float4* S = p.s[z];
    float4* D = (float4*)(g_R[z]);
    const int n4 = MTOT * DMODEL / 4;
    for (int i = blockIdx.x * 256 + threadIdx.x; i < n4; i += gridDim.x * 256) {
        float4 v = S[i];
        v.x = to_tf32_rn(v.x); v.y = to_tf32_rn(v.y);
        v.z = to_tf32_rn(v.z); v.w = to_tf32_rn(v.w);
        D[i] = v;
    }
}

// ---------------------------------------------------------------------------
// Weight transpose + round: Wt[n][k] = tf32(W[k][n])
// ---------------------------------------------------------------------------
struct WPtrs { const float* s[4]; float* d[4]; };

__global__ __launch_bounds__(256) void transpose_k(WPtrs p) {
    __shared__ float tile[32][33];
    const float* S = p.s[blockIdx.z];
    float*       D = p.d[blockIdx.z];
    int x0 = blockIdx.x * 32, y0 = blockIdx.y * 32;
    int tx = threadIdx.x, ty = threadIdx.y;          // (32, 8)
    #pragma unroll
    for (int j = 0; j < 32; j += 8)
        tile[ty + j][tx] = S[(size_t)(y0 + ty + j) * DMODEL + x0 + tx];
    __syncthreads();
    #pragma unroll
    for (int j = 0; j < 32; j += 8)
        D[(size_t)(x0 + ty + j) * DMODEL + y0 + tx] = to_tf32_rn(tile[tx][ty + j]);
}

// ---------------------------------------------------------------------------
// tf32 tensor-core GEMM (cp.async 3-stage, ldmatrix fragments).
// Batched over blockIdx.z. z==2 (V projection) stores transposed to g_Vt.
// ---------------------------------------------------------------------------
#define BM 128
#define BN 128
#define BK 32
#define KT_GEMM (DMODEL / BK)          // 32
#define ROWP 36
#define ROWB (ROWP * 4)                // 144 bytes per row
#define TILE_F (128 * ROWP)
#define GSTG 3
#define SM_GEMM_BYTES (GSTG * 2 * TILE_F * 4)   // 110592 B

struct GemmBatch { const float* A[3]; const float* B[3]; float* C[3]; };

template<bool ROUND>
__global__ __launch_bounds__(256, 2) void gemm_tf32_kernel(GemmBatch gb) {
    extern __shared__ float sm[];
    const uint32_t sb = smem_u32(sm);

    const float* __restrict__ A  = gb.A[blockIdx.z];
    const float* __restrict__ Bt = gb.B[blockIdx.z];
    float* __restrict__ C        = gb.C[blockIdx.z];

    const int t     = threadIdx.x;
    const int wid   = t >> 5;
    const int lane  = t & 31;
    const int wm    = wid & 1;
    const int wn    = wid >> 1;
    const int lane4 = lane >> 2;
    const int lanek = lane & 3;
    const int lm    = lane >> 3;      // ldmatrix matrix id
    const int lr    = lane & 7;       // ldmatrix row
    const int m0 = blockIdx.y * BM;
    const int n0 = blockIdx.x * BN;
    const int lrow = t >> 3, lc4 = t & 7;

    // Per-lane ldmatrix base offsets (bytes, within a tile)
    const uint32_t aOff = (uint32_t)((wm * 64 + (lm & 1) * 8 + lr) * ROWB + (lm >> 1) * 16);
    const uint32_t bOff = (uint32_t)((wn * 32 + (lm >> 1) * 8 + lr) * ROWB + (lm & 1) * 16);

    float acc[4][4][4];
    #pragma unroll
    for (int mi = 0; mi < 4; mi++)
        #pragma unroll
        for (int ni = 0; ni < 4; ni++)
            #pragma unroll
            for (int f = 0; f < 4; f++) acc[mi][ni][f] = 0.f;

    auto issue = [&](int kt, int s) {
        const float* Ap = A  + (size_t)m0 * DMODEL + kt * BK;
        const float* Bp = Bt + (size_t)n0 * DMODEL + kt * BK;
        #pragma unroll
        for (int i = 0; i < 4; i++) {
            int row = lrow + i * 32;
            cp16(sb + (uint32_t)((s * 2 * TILE_F + row * ROWP + lc4 * 4) * 4),
                 Ap + (size_t)row * DMODEL + lc4 * 4);
            cp16(sb + (uint32_t)((s * 2 * TILE_F + TILE_F + row * ROWP + lc4 * 4) * 4),
                 Bp + (size_t)row * DMODEL + lc4 * 4);
        }
        CP_COMMIT();
    };

    issue(0, 0);
    issue(1, 1);

    for (int kt = 0; kt < KT_GEMM; kt++) {
        const int s = kt % 3;
        if (kt < KT_GEMM - 1) CP_WAIT1(); else CP_WAIT0();
        __syncthreads();
        if (kt + 2 < KT_GEMM) issue(kt + 2, (kt + 2) % 3);

        const uint32_t aAdr = sb + (uint32_t)(s * 2 * TILE_F * 4) + aOff;
        const uint32_t bAdr = aAdr - aOff + (uint32_t)(TILE_F * 4) + bOff;
        #pragma unroll
        for (int ks = 0; ks < 4; ks++) {
            uint32_t a[4][4], b[4][2];
            #pragma unroll
            for (int mi = 0; mi < 4; mi++)
                ldsm4(a[mi][0], a[mi][1], a[mi][2], a[mi][3],
                      aAdr + (uint32_t)(mi * 16 * ROWB + ks * 32));
            ldsm4(b[0][0], b[0][1], b[1][0], b[1][1], bAdr + (uint32_t)(ks * 32));
            ldsm4(b[2][0], b[2][1], b[3][0], b[3][1],
                  bAdr + (uint32_t)(16 * ROWB + ks * 32));
            #pragma unroll
            for (int mi = 0; mi < 4; mi++)
                #pragma unroll
                for (int ni = 0; ni < 4; ni++)
                    mma_tf32(acc[mi][ni], a[mi], b[ni]);
        }
    }

    const bool vt = ROUND && (blockIdx.z == 2);
    #pragma unroll
    for (int mi = 0; mi < 4; mi++) {
        #pragma unroll
        for (int ni = 0; ni < 4; ni++) {
            int row = m0 + wm * 64 + mi * 16 + lane4;
            int col = n0 + wn * 32 + ni * 8 + 2 * lanek;
            float v0 = acc[mi][ni][0], v1 = acc[mi][ni][1];
            float v2 = acc[mi][ni][2], v3 = acc[mi][ni][3];
            if (ROUND) {
                v0 = to_tf32_rn(v0); v1 = to_tf32_rn(v1);
                v2 = to_tf32_rn(v2); v3 = to_tf32_rn(v3);
            }
            if (vt) {
                int bb = row >> 11, tok = row & (SEQ - 1);
                int hh = col >> 6,  dh  = col & (DH - 1);
                float* base = g_Vt + ((size_t)(bb * NH + hh) * DH + dh) * SEQ + tok;
                base[0]       = v0;
                base[SEQ]     = v1;
                base[8]       = v2;
                base[SEQ + 8] = v3;
            } else {
                *(float2*)(C + (size_t)row * DMODEL + col)       = make_float2(v0, v1);
                *(float2*)(C + (size_t)(row + 8) * DMODEL + col) = make_float2(v2, v3);
            }
        }
    }
}

// ---------------------------------------------------------------------------
// Tensor-core flash attention, base-2 softmax domain (ex2 on MUFU).
// Q pre-scaled by log2(e)/8 (tf32-rounded) so p = ex2(s - m) directly.
// ---------------------------------------------------------------------------
#define ATT_BQ   128
#define ATT_BKV  64
#define APAD     68
#define ATT_KV_F (2 * ATT_BKV * APAD)
#define ATT_P_OFF (2 * ATT_KV_F)
#define ATT_MSK_OFF (ATT_P_OFF + 8 * 16 * APAD)
#define ATT_SMEM ((ATT_MSK_OFF + SEQ) * 4)            // 112640 B

__global__ __launch_bounds__(256, 2) void attn_mma_kernel(const int* __restrict__ masks) {
    extern __shared__ float smf[];
    const uint32_t sb = smem_u32(smf);
    float* msf = smf + ATT_MSK_OFF;

    const int t    = threadIdx.x;
    const int w    = t >> 5;
    const int lane = t & 31;
    const int gid  = lane >> 2;
    const int tid4 = lane & 3;
    const int lm   = lane >> 3;
    const int lr   = lane & 7;
    const int b  = blockIdx.z;
    const int h  = blockIdx.y;
    const int q0 = blockIdx.x * ATT_BQ;

    for (int i = t; i < SEQ; i += 256)
        msf[i] = masks[b * SEQ + i] ? 0.f : -1e30f;

    const uint32_t kCol = (uint32_t)(((lm >> 1) * 8 + (lm & 1) * 4) * 4);
    const uint32_t vRow = (uint32_t)(((lm >> 1) * 8 + lr) * APAD * 4);
    const uint32_t vCol = (uint32_t)((lm & 1) * 4 * 4);
    const uint32_t pAdr = sb + (uint32_t)((ATT_P_OFF + (w * 16 + (lm & 1) * 8 + lr) * APAD) * 4)
                        + (uint32_t)((lm >> 1) * 4 * 4);

    // Q fragments scaled by log2(e)/8, re-rounded to tf32 (rna, unbiased)
    const float qs = 0.125f * 1.4426950408889634f;
    uint32_t aQ[8][4];
    {
        const float* Qb = g_Q + ((size_t)(b * SEQ + q0 + w * 16)) * DMODEL + h * DH;
        #pragma unroll
        for (int kk = 0; kk < 8; kk++) {
            int c = kk * 8 + tid4;
            aQ[kk][0] = __float_as_uint(to_tf32_rn(qs * Qb[(size_t)gid       * DMODEL + c    ]));
            aQ[kk][1] = __float_as_uint(to_tf32_rn(qs * Qb[(size_t)(gid + 8) * DMODEL + c    ]));
            aQ[kk][2] = __float_as_uint(to_tf32_rn(qs * Qb[(size_t)gid       * DMODEL + c + 4]));
            aQ[kk][3] = __float_as_uint(to_tf32_rn(qs * Qb[(size_t)(gid + 8) * DMODEL + c + 4]));
        }
    }

    float Oa[8][4];
    #pragma unroll
    for (int nb = 0; nb < 8; nb++)
        #pragma unroll
        for (int f = 0; f < 4; f++) Oa[nb][f] = 0.f;
    float m0 = -1e30f, m1 = -1e30f, l0 = 0.f, l1 = 0.f;

    float* Pw = smf + ATT_P_OFF + w * 16 * APAD;

    auto issue_kv = [&](int kv0, int s) {
        const float* Kb  = g_K  + ((size_t)(b * SEQ + kv0)) * DMODEL + h * DH;
        const float* Vtb = g_Vt + ((size_t)(b * NH + h) * DH) * SEQ + kv0;
        #pragma unroll
        for (int i = 0; i < 4; i++) {
            int idx = i * 256 + t;
            int row = idx >> 4, c4 = (idx & 15) * 4;
            cp16(sb + (uint32_t)((s * ATT_KV_F + row * APAD + c4) * 4),
                 Kb + (size_t)row * DMODEL + c4);
            cp16(sb + (uint32_t)((s * ATT_KV_F + ATT_BKV * APAD + row * APAD + c4) * 4),
                 Vtb + (size_t)row * SEQ + c4);
        }
        CP_COMMIT();
    };

    issue_kv(0, 0);

    for (int kv0 = 0; kv0 < SEQ; kv0 += ATT_BKV) {
        const int s = (kv0 >> 6) & 1;
        CP_WAIT0();
        __syncthreads();
        if (kv0 + ATT_BKV < SEQ) issue_kv(kv0 + ATT_BKV, s ^ 1);

        const uint32_t ksAdr = sb + (uint32_t)(s * ATT_KV_F * 4);
        const uint32_t vsAdr = ksAdr + (uint32_t)(ATT_BKV * APAD * 4);

        // S2 = (Q*log2e/8) . K^T  (log2-domain scores)
        float sc[8][4];
        #pragma unroll
        for (int nb = 0; nb < 8; nb++) {
            sc[nb][0] = sc[nb][1] = sc[nb][2] = sc[nb][3] = 0.f;
            uint32_t bk[16];
            const uint32_t rowAdr = ksAdr + (uint32_t)(((nb * 8 + lr) * APAD) * 4) + kCol;
            #pragma unroll
            for (int i = 0; i < 4; i++)
                ldsm4(bk[4*i], bk[4*i+1], bk[4*i+2], bk[4*i+3], rowAdr + i * 64);
            #pragma unroll
            for (int kk = 0; kk < 8; kk++)
                mma_tf32(sc[nb], aQ[kk], &bk[4 * (kk >> 1) + 2 * (kk & 1)]);
        }

        // Mask bias + tile row max
        float tm0 = -1e30f, tm1 = -1e30f;
        #pragma unroll
        for (int nb = 0; nb < 8; nb++) {
            float2 mm = *(const float2*)(msf + kv0 + nb * 8 + 2 * tid4);
            sc[nb][0] += mm.x; sc[nb][1] += mm.y;
            sc[nb][2] += mm.x; sc[nb][3] += mm.y;
            tm0 = fmaxf(tm0, fmaxf(sc[nb][0], sc[nb][1]));
            tm1 = fmaxf(tm1, fmaxf(sc[nb][2], sc[nb][3]));
        }
        tm0 = fmaxf(tm0, __shfl_xor_sync(0xffffffffu, tm0, 1));
        tm0 = fmaxf(tm0, __shfl_xor_sync(0xffffffffu, tm0, 2));
        tm1 = fmaxf(tm1, __shfl_xor_sync(0xffffffffu, tm1, 1));
        tm1 = fmaxf(tm1, __shfl_xor_sync(0xffffffffu, tm1, 2));

        float mn0 = fmaxf(m0, tm0), mn1 = fmaxf(m1, tm1);
        float al0 = ex2f(m0 - mn0), al1 = ex2f(m1 - mn1);
        m0 = mn0; m1 = mn1;

        // P = 2^(S2 - m) via MUFU; partial row sums
        float lp0 = 0.f, lp1 = 0.f;
        #pragma unroll
        for (int nb = 0; nb < 8; nb++) {
            float p0 = ex2f(sc[nb][0] - m0);
            float p1 = ex2f(sc[nb][1] - m0);
            float p2 = ex2f(sc[nb][2] - m1);
            float p3 = ex2f(sc[nb][3] - m1);
            lp0 += p0 + p1; lp1 += p2 + p3;
            *(float2*)(Pw + gid * APAD + nb * 8 + 2 * tid4) =
                make_float2(to_tf32_rn(p0), to_tf32_rn(p1));
            *(float2*)(Pw + (gid + 8) * APAD + nb * 8 + 2 * tid4) =
                make_float2(to_tf32_rn(p2), to_tf32_rn(p3));
        }
        l0 = l0 * al0 + lp0;
        l1 = l1 * al1 + lp1;
        #pragma unroll
        for (int nb = 0; nb < 8; nb++) {
            Oa[nb][0] *= al0; Oa[nb][1] *= al0;
            Oa[nb][2] *= al1; Oa[nb][3] *= al1;
        }
        __syncwarp();

        // O += P . V
        #pragma unroll
        for (int kk = 0; kk < 8; kk++) {
            uint32_t aP[4];
            ldsm4(aP[0], aP[1], aP[2], aP[3], pAdr + kk * 32);
            uint32_t bv[16];
            const uint32_t vAdr = vsAdr + vRow + vCol + (uint32_t)(kk * 32);
            #pragma unroll
            for (int j = 0; j < 4; j++)
                ldsm4(bv[4*j], bv[4*j+1], bv[4*j+2], bv[4*j+3],
                      vAdr + (uint32_t)(j * 16 * APAD * 4));
            #pragma unroll
            for (int nb = 0; nb < 8; nb++)
                mma_tf32(Oa[nb], aP, &bv[4 * (nb >> 1) + 2 * (nb & 1)]);
        }
        __syncwarp();
    }

    l0 += __shfl_xor_sync(0xffffffffu, l0, 1);
    l0 += __shfl_xor_sync(0xffffffffu, l0, 2);
    l1 += __shfl_xor_sync(0xffffffffu, l1, 1);
    l1 += __shfl_xor_sync(0xffffffffu, l1, 2);
    float inv0 = 1.f / l0, inv1 = 1.f / l1;

    float* Ob = g_O + ((size_t)(b * SEQ + q0 + w * 16)) * DMODEL + h * DH;
    #pragma unroll
    for (int nb = 0; nb < 8; nb++) {
        *(float2*)(Ob + (size_t)gid * DMODEL + nb * 8 + 2 * tid4) =
            make_float2(to_tf32_rn(Oa[nb][0] * inv0), to_tf32_rn(Oa[nb][1] * inv0));
        *(float2*)(Ob + (size_t)(gid + 8) * DMODEL + nb * 8 + 2 * tid4) =
            make_float2(to_tf32_rn(Oa[nb][2] * inv1), to_tf32_rn(Oa[nb][3] * inv1));
    }
}

// ---------------------------------------------------------------------------
// Launch:  inputs 0=queries 1=keys 2=values 3=masks 4=Wq 5=Wk 6=Wv 7=Wo
// ---------------------------------------------------------------------------
extern "C" void kernel_launch(void* const* d_in, const int* in_sizes, int n_in,
                              void* d_out, int out_size) {
    const int* masks = (const int*)d_in[3];
    float* out = (float*)d_out;

    float *gq, *gk, *gvt, *go, *gwt, *gr;
    cudaGetSymbolAddress((void**)&gq,  g_Q);
    cudaGetSymbolAddress((void**)&gk,  g_K);
    cudaGetSymbolAddress((void**)&gvt, g_Vt);
    cudaGetSymbolAddress((void**)&go,  g_O);
    cudaGetSymbolAddress((void**)&gwt, g_Wt);
    cudaGetSymbolAddress((void**)&gr,  g_R);

    cudaFuncSetAttribute(gemm_tf32_kernel<true>,
                         cudaFuncAttributeMaxDynamicSharedMemorySize, SM_GEMM_BYTES);
    cudaFuncSetAttribute(gemm_tf32_kernel<false>,
                         cudaFuncAttributeMaxDynamicSharedMemorySize, SM_GEMM_BYTES);
    cudaFuncSetAttribute(attn_mma_kernel,
                         cudaFuncAttributeMaxDynamicSharedMemorySize, ATT_SMEM);

    R3 rp;
    for (int i = 0; i < 3; i++) rp.s[i] = (const float4*)d_in[i];
    round3_kernel<<<dim3(512, 1, 3), 256>>>(rp);

    WPtrs wp;
    for (int i = 0; i < 4; i++) {
        wp.s[i] = (const float*)d_in[4 + i];
        wp.d[i] = gwt + (size_t)i * DMODEL * DMODEL;
    }
    transpose_k<<<dim3(32, 32, 4), dim3(32, 8)>>>(wp);

    const size_t NN  = (size_t)MTOT * DMODEL;
    const size_t NN2 = (size_t)DMODEL * DMODEL;

    GemmBatch g1;
    g1.A[0] = gr + 0 * NN; g1.B[0] = gwt + 0 * NN2; g1.C[0] = gq;
    g1.A[1] = gr + 1 * NN; g1.B[1] = gwt + 1 * NN2; g1.C[1] = gk;
    g1.A[2] = gr + 2 * NN; g1.B[2] = gwt + 2 * NN2; g1.C[2] = gvt;
    gemm_tf32_kernel<true><<<dim3(DMODEL / BN, MTOT / BM, 3), 256, SM_GEMM_BYTES>>>(g1);

    dim3 ga(SEQ / ATT_BQ, NH, BATCH);  // (16, 16, 2) = 512 CTAs
    attn_mma_kernel<<<ga, 256, ATT_SMEM>>>(masks);

    GemmBatch g2;
    g2.A[0] = go; g2.B[0] = gwt + 3 * NN2; g2.C[0] = out;
    g2.A[1] = g2.A[2] = nullptr; g2.B[1] = g2.B[2] = nullptr; g2.C[1] = g2.C[2] = nullptr;
    gemm_tf32_kernel<false><<<dim3(DMODEL / BN, MTOT / BM, 1), 256, SM_GEMM_BYTES>>>(g2);
}

// round 12
// speedup vs baseline: 4.2557x; 1.0372x over previous
#include <cuda_runtime.h>
#include <math_constants.h>
#include <cstdint>

#define SEQ    2048
#define DMODEL 1024
#define NH     16
#define DH     64
#define BATCH  2
#define MTOT   (BATCH*SEQ)   // 4096 rows

// ---------------------------------------------------------------------------
// Device scratch (allocation-free rule)
// ---------------------------------------------------------------------------
__device__ float g_Q[(size_t)MTOT*DMODEL];
__device__ float g_K[(size_t)MTOT*DMODEL];
__device__ float g_Vt[(size_t)BATCH*NH*DH*SEQ];    // V output, [b,h][d][token]
__device__ float g_O[(size_t)MTOT*DMODEL];
__device__ float g_Wt[4][(size_t)DMODEL*DMODEL];   // transposed+rounded weights [N][K]
__device__ float g_R[3][(size_t)MTOT*DMODEL];      // rounded inputs (q,k,v)

// ---------------------------------------------------------------------------
// Helpers
// ---------------------------------------------------------------------------
__device__ __forceinline__ uint32_t smem_u32(const void* p) {
    uint32_t a;
    asm("{ .reg .u64 t; cvta.to.shared.u64 t, %1; cvt.u32.u64 %0, t; }" : "=r"(a) : "l"(p));
    return a;
}
__device__ __forceinline__ float to_tf32_rn(float x) {
    uint32_t r;
    asm("cvt.rna.tf32.f32 %0, %1;" : "=r"(r) : "f"(x));
    return __uint_as_float(r);
}
__device__ __forceinline__ float ex2f(float y) {    // 2^y via MUFU
    float r;
    asm("ex2.approx.f32 %0, %1;" : "=f"(r) : "f"(y));
    return r;
}
__device__ __forceinline__ void cp16(uint32_t dst, const void* src) {
    asm volatile("cp.async.cg.shared.global [%0], [%1], 16;" :: "r"(dst), "l"(src));
}
#define CP_COMMIT() asm volatile("cp.async.commit_group;" ::: "memory")
#define CP_WAIT0()  asm volatile("cp.async.wait_group 0;" ::: "memory")
#define CP_WAIT1()  asm volatile("cp.async.wait_group 1;" ::: "memory")

// ldmatrix x4: four 8x8 b16 tiles == four 8x4 f32 tiles (tf32 fragment layout)
__device__ __forceinline__ void ldsm4(uint32_t& r0, uint32_t& r1, uint32_t& r2,
                                      uint32_t& r3, uint32_t addr) {
    asm volatile("ldmatrix.sync.aligned.m8n8.x4.shared.b16 {%0,%1,%2,%3}, [%4];"
                 : "=r"(r0), "=r"(r1), "=r"(r2), "=r"(r3) : "r"(addr));
}

// m16n8k8 tf32 mma (baseline PTX, sm_80+)
__device__ __forceinline__ void mma_tf32(float* c, const uint32_t* a, const uint32_t* b) {
    asm volatile(
        "mma.sync.aligned.m16n8k8.row.col.f32.tf32.tf32.f32 "
        "{%0,%1,%2,%3}, {%4,%5,%6,%7}, {%8,%9}, {%0,%1,%2,%3};"
        : "+f"(c[0]), "+f"(c[1]), "+f"(c[2]), "+f"(c[3])
        : "r"(a[0]), "r"(a[1]), "r"(a[2]), "r"(a[3]), "r"(b[0]), "r"(b[1]));
}

// ---------------------------------------------------------------------------
// Round queries/keys/values to tf32
// ---------------------------------------------------------------------------
struct R3 { const float4* s[3]; };

__global__ __launch_bounds__(256) void round3_kernel(R3 p) {
    const int z = blockIdx.z;
    const float4* S = p.s[z];
    float4* D = (float4*)(g_R[z]);
    const int n4 = MTOT * DMODEL / 4;
    for (int i = blockIdx.x * 256 + threadIdx.x; i < n4; i += gridDim.x * 256) {
        float4 v = S[i];
        v.x = to_tf32_rn(v.x); v.y = to_tf32_rn(v.y);
        v.z = to_tf32_rn(v.z); v.w = to_tf32_rn(v.w);
        D[i] = v;
    }
}

// ---------------------------------------------------------------------------
// Weight transpose + round: Wt[n][k] = tf32(W[k][n])
// ---------------------------------------------------------------------------
struct WPtrs { const float* s[4]; float* d[4]; };

__global__ __launch_bounds__(256) void transpose_k(WPtrs p) {
    __shared__ float tile[32][33];
    const float* S = p.s[blockIdx.z];
    float*       D = p.d[blockIdx.z];
    int x0 = blockIdx.x * 32, y0 = blockIdx.y * 32;
    int tx = threadIdx.x, ty = threadIdx.y;          // (32, 8)
    #pragma unroll
    for (int j = 0; j < 32; j += 8)
        tile[ty + j][tx] = S[(size_t)(y0 + ty + j) * DMODEL + x0 + tx];
    __syncthreads();
    #pragma unroll
    for (int j = 0; j < 32; j += 8)
        D[(size_t)(x0 + ty + j) * DMODEL + y0 + tx] = to_tf32_rn(tile[tx][ty + j]);
}

// ---------------------------------------------------------------------------
// tf32 tensor-core GEMM (cp.async 3-stage, ldmatrix fragments). Unchanged R10.
// Batched over blockIdx.z. z==2 (V projection) stores transposed to g_Vt.
// ---------------------------------------------------------------------------
#define BM 128
#define BN 128
#define BK 32
#define KT_GEMM (DMODEL / BK)          // 32
#define ROWP 36
#define ROWB (ROWP * 4)                // 144 bytes per row
#define TILE_F (128 * ROWP)
#define GSTG 3
#define SM_GEMM_BYTES (GSTG * 2 * TILE_F * 4)   // 110592 B

struct GemmBatch { const float* A[3]; const float* B[3]; float* C[3]; };

template<bool ROUND>
__global__ __launch_bounds__(256, 2) void gemm_tf32_kernel(GemmBatch gb) {
    extern __shared__ float sm[];
    const uint32_t sb = smem_u32(sm);

    const float* __restrict__ A  = gb.A[blockIdx.z];
    const float* __restrict__ Bt = gb.B[blockIdx.z];
    float* __restrict__ C        = gb.C[blockIdx.z];

    const int t     = threadIdx.x;
    const int wid   = t >> 5;
    const int lane  = t & 31;
    const int wm    = wid & 1;
    const int wn    = wid >> 1;
    const int lane4 = lane >> 2;
    const int lanek = lane & 3;
    const int lm    = lane >> 3;
    const int lr    = lane & 7;
    const int m0 = blockIdx.y * BM;
    const int n0 = blockIdx.x * BN;
    const int lrow = t >> 3, lc4 = t & 7;

    const uint32_t aOff = (uint32_t)((wm * 64 + (lm & 1) * 8 + lr) * ROWB + (lm >> 1) * 16);
    const uint32_t bOff = (uint32_t)((wn * 32 + (lm >> 1) * 8 + lr) * ROWB + (lm & 1) * 16);

    float acc[4][4][4];
    #pragma unroll
    for (int mi = 0; mi < 4; mi++)
        #pragma unroll
        for (int ni = 0; ni < 4; ni++)
            #pragma unroll
            for (int f = 0; f < 4; f++) acc[mi][ni][f] = 0.f;

    auto issue = [&](int kt, int s) {
        const float* Ap = A  + (size_t)m0 * DMODEL + kt * BK;
        const float* Bp = Bt + (size_t)n0 * DMODEL + kt * BK;
        #pragma unroll
        for (int i = 0; i < 4; i++) {
            int row = lrow + i * 32;
            cp16(sb + (uint32_t)((s * 2 * TILE_F + row * ROWP + lc4 * 4) * 4),
                 Ap + (size_t)row * DMODEL + lc4 * 4);
            cp16(sb + (uint32_t)((s * 2 * TILE_F + TILE_F + row * ROWP + lc4 * 4) * 4),
                 Bp + (size_t)row * DMODEL + lc4 * 4);
        }
        CP_COMMIT();
    };

    issue(0, 0);
    issue(1, 1);

    for (int kt = 0; kt < KT_GEMM; kt++) {
        const int s = kt % 3;
        if (kt < KT_GEMM - 1) CP_WAIT1(); else CP_WAIT0();
        __syncthreads();
        if (kt + 2 < KT_GEMM) issue(kt + 2, (kt + 2) % 3);

        const uint32_t aAdr = sb + (uint32_t)(s * 2 * TILE_F * 4) + aOff;
        const uint32_t bAdr = aAdr - aOff + (uint32_t)(TILE_F * 4) + bOff;
        #pragma unroll
        for (int ks = 0; ks < 4; ks++) {
            uint32_t a[4][4], b[4][2];
            #pragma unroll
            for (int mi = 0; mi < 4; mi++)
                ldsm4(a[mi][0], a[mi][1], a[mi][2], a[mi][3],
                      aAdr + (uint32_t)(mi * 16 * ROWB + ks * 32));
            ldsm4(b[0][0], b[0][1], b[1][0], b[1][1], bAdr + (uint32_t)(ks * 32));
            ldsm4(b[2][0], b[2][1], b[3][0], b[3][1],
                  bAdr + (uint32_t)(16 * ROWB + ks * 32));
            #pragma unroll
            for (int mi = 0; mi < 4; mi++)
                #pragma unroll
                for (int ni = 0; ni < 4; ni++)
                    mma_tf32(acc[mi][ni], a[mi], b[ni]);
        }
    }

    const bool vt = ROUND && (blockIdx.z == 2);
    #pragma unroll
    for (int mi = 0; mi < 4; mi++) {
        #pragma unroll
        for (int ni = 0; ni < 4; ni++) {
            int row = m0 + wm * 64 + mi * 16 + lane4;
            int col = n0 + wn * 32 + ni * 8 + 2 * lanek;
            float v0 = acc[mi][ni][0], v1 = acc[mi][ni][1];
            float v2 = acc[mi][ni][2], v3 = acc[mi][ni][3];
            if (ROUND) {
                v0 = to_tf32_rn(v0); v1 = to_tf32_rn(v1);
                v2 = to_tf32_rn(v2); v3 = to_tf32_rn(v3);
            }
            if (vt) {
                int bb = row >> 11, tok = row & (SEQ - 1);
                int hh = col >> 6,  dh  = col & (DH - 1);
                float* base = g_Vt + ((size_t)(bb * NH + hh) * DH + dh) * SEQ + tok;
                base[0]       = v0;
                base[SEQ]     = v1;
                base[8]       = v2;
                base[SEQ + 8] = v3;
            } else {
                *(float2*)(C + (size_t)row * DMODEL + col)       = make_float2(v0, v1);
                *(float2*)(C + (size_t)(row + 8) * DMODEL + col) = make_float2(v2, v3);
            }
        }
    }
}

// ---------------------------------------------------------------------------
// Tensor-core flash attention, 32 q-rows per warp (K/V fragments amortized
// over two 16-row m-blocks). 4 warps / 128 threads per CTA; BQ=128; KV=64.
// Base-2 softmax (ex2 on MUFU); ldmatrix for all fragments.
// ---------------------------------------------------------------------------
#define ATT_BQ   128
#define ATT_BKV  64
#define APAD     68
#define ATT_KV_F (2 * ATT_BKV * APAD)
#define ATT_P_OFF (2 * ATT_KV_F)
#define ATT_MSK_OFF (ATT_P_OFF + ATT_BQ * APAD)
#define ATT_SMEM ((ATT_MSK_OFF + SEQ) * 4)            // 112640 B

__global__ __launch_bounds__(128, 2) void attn_mma_kernel(const int* __restrict__ masks) {
    extern __shared__ float smf[];
    const uint32_t sb = smem_u32(smf);
    float* msf = smf + ATT_MSK_OFF;

    const int t    = threadIdx.x;
    const int w    = t >> 5;       // 0..3, each warp: 32 q-rows
    const int lane = t & 31;
    const int gid  = lane >> 2;
    const int tid4 = lane & 3;
    const int lm   = lane >> 3;
    const int lr   = lane & 7;
    const int b  = blockIdx.z;
    const int h  = blockIdx.y;
    const int q0 = blockIdx.x * ATT_BQ;

    for (int i = t; i < SEQ; i += 128)
        msf[i] = masks[b * SEQ + i] ? 0.f : -1e30f;

    const uint32_t kCol = (uint32_t)(((lm >> 1) * 8 + (lm & 1) * 4) * 4);
    const uint32_t vRow = (uint32_t)(((lm >> 1) * 8 + lr) * APAD * 4);
    const uint32_t vCol = (uint32_t)((lm & 1) * 16);
    uint32_t pAdrM[2];
    #pragma unroll
    for (int mi = 0; mi < 2; mi++)
        pAdrM[mi] = sb + (uint32_t)((ATT_P_OFF + (w * 32 + mi * 16 + (lm & 1) * 8 + lr) * APAD) * 4)
                  + (uint32_t)((lm >> 1) * 16);

    // Q fragments for both m-blocks, scaled by log2(e)/8 (tf32 rna)
    const float qs = 0.125f * 1.4426950408889634f;
    uint32_t aQ[2][8][4];
    {
        const float* Qb = g_Q + ((size_t)(b * SEQ + q0 + w * 32)) * DMODEL + h * DH;
        #pragma unroll
        for (int mi = 0; mi < 2; mi++) {
            const float* Qm = Qb + (size_t)(mi * 16) * DMODEL;
            #pragma unroll
            for (int kk = 0; kk < 8; kk++) {
                int c = kk * 8 + tid4;
                aQ[mi][kk][0] = __float_as_uint(to_tf32_rn(qs * Qm[(size_t)gid       * DMODEL + c    ]));
                aQ[mi][kk][1] = __float_as_uint(to_tf32_rn(qs * Qm[(size_t)(gid + 8) * DMODEL + c    ]));
                aQ[mi][kk][2] = __float_as_uint(to_tf32_rn(qs * Qm[(size_t)gid       * DMODEL + c + 4]));
                aQ[mi][kk][3] = __float_as_uint(to_tf32_rn(qs * Qm[(size_t)(gid + 8) * DMODEL + c + 4]));
            }
        }
    }

    float Oa[2][8][4];
    #pragma unroll
    for (int mi = 0; mi < 2; mi++)
        #pragma unroll
        for (int nb = 0; nb < 8; nb++)
            #pragma unroll
            for (int f = 0; f < 4; f++) Oa[mi][nb][f] = 0.f;
    float mx[2][2] = {{-1e30f, -1e30f}, {-1e30f, -1e30f}};
    float ls[2][2] = {{0.f, 0.f}, {0.f, 0.f}};

    float* Pw = smf + ATT_P_OFF + w * 32 * APAD;

    auto issue_kv = [&](int kv0, int s) {
        const float* Kb  = g_K  + ((size_t)(b * SEQ + kv0)) * DMODEL + h * DH;
        const float* Vtb = g_Vt + ((size_t)(b * NH + h) * DH) * SEQ + kv0;
        #pragma unroll
        for (int i = 0; i < 8; i++) {
            int idx = i * 128 + t;
            int row = idx >> 4, c4 = (idx & 15) * 4;
            cp16(sb + (uint32_t)((s * ATT_KV_F + row * APAD + c4) * 4),
                 Kb + (size_t)row * DMODEL + c4);
            cp16(sb + (uint32_t)((s * ATT_KV_F + ATT_BKV * APAD + row * APAD + c4) * 4),
                 Vtb + (size_t)row * SEQ + c4);
        }
        CP_COMMIT();
    };

    issue_kv(0, 0);

    for (int kv0 = 0; kv0 < SEQ; kv0 += ATT_BKV) {
        const int s = (kv0 >> 6) & 1;
        CP_WAIT0();
        __syncthreads();
        if (kv0 + ATT_BKV < SEQ) issue_kv(kv0 + ATT_BKV, s ^ 1);

        const uint32_t ksAdr = sb + (uint32_t)(s * ATT_KV_F * 4);
        const uint32_t vsAdr = ksAdr + (uint32_t)(ATT_BKV * APAD * 4);

        // S phase: K fragments loaded ONCE per nb, used by both m-blocks
        float sc[2][8][4];
        #pragma unroll
        for (int nb = 0; nb < 8; nb++) {
            uint32_t bk[16];
            const uint32_t rowAdr = ksAdr + (uint32_t)(((nb * 8 + lr) * APAD) * 4) + kCol;
            #pragma unroll
            for (int i = 0; i < 4; i++)
                ldsm4(bk[4*i], bk[4*i+1], bk[4*i+2], bk[4*i+3], rowAdr + i * 64);
            #pragma unroll
            for (int f = 0; f < 4; f++) { sc[0][nb][f] = 0.f; sc[1][nb][f] = 0.f; }
            #pragma unroll
            for (int kk = 0; kk < 8; kk++) {
                const uint32_t* bp = &bk[4 * (kk >> 1) + 2 * (kk & 1)];
                mma_tf32(sc[0][nb], aQ[0][kk], bp);
                mma_tf32(sc[1][nb], aQ[1][kk], bp);
            }
        }

        // Softmax per m-block
        #pragma unroll
        for (int mi = 0; mi < 2; mi++) {
            float tm0 = -1e30f, tm1 = -1e30f;
            #pragma unroll
            for (int nb = 0; nb < 8; nb++) {
                float2 mm = *(const float2*)(msf + kv0 + nb * 8 + 2 * tid4);
                sc[mi][nb][0] += mm.x; sc[mi][nb][1] += mm.y;
                sc[mi][nb][2] += mm.x; sc[mi][nb][3] += mm.y;
                tm0 = fmaxf(tm0, fmaxf(sc[mi][nb][0], sc[mi][nb][1]));
                tm1 = fmaxf(tm1, fmaxf(sc[mi][nb][2], sc[mi][nb][3]));
            }
            tm0 = fmaxf(tm0, __shfl_xor_sync(0xffffffffu, tm0, 1));
            tm0 = fmaxf(tm0, __shfl_xor_sync(0xffffffffu, tm0, 2));
            tm1 = fmaxf(tm1, __shfl_xor_sync(0xffffffffu, tm1, 1));
            tm1 = fmaxf(tm1, __shfl_xor_sync(0xffffffffu, tm1, 2));

            float mn0 = fmaxf(mx[mi][0], tm0), mn1 = fmaxf(mx[mi][1], tm1);
            float al0 = ex2f(mx[mi][0] - mn0), al1 = ex2f(mx[mi][1] - mn1);
            mx[mi][0] = mn0; mx[mi][1] = mn1;

            float lp0 = 0.f, lp1 = 0.f;
            #pragma unroll
            for (int nb = 0; nb < 8; nb++) {
                float p0 = ex2f(sc[mi][nb][0] - mn0);
                float p1 = ex2f(sc[mi][nb][1] - mn0);
                float p2 = ex2f(sc[mi][nb][2] - mn1);
                float p3 = ex2f(sc[mi][nb][3] - mn1);
                lp0 += p0 + p1; lp1 += p2 + p3;
                *(float2*)(Pw + (mi * 16 + gid) * APAD + nb * 8 + 2 * tid4) =
                    make_float2(to_tf32_rn(p0), to_tf32_rn(p1));
                *(float2*)(Pw + (mi * 16 + gid + 8) * APAD + nb * 8 + 2 * tid4) =
                    make_float2(to_tf32_rn(p2), to_tf32_rn(p3));
            }
            ls[mi][0] = ls[mi][0] * al0 + lp0;
            ls[mi][1] = ls[mi][1] * al1 + lp1;
            #pragma unroll
            for (int nb = 0; nb < 8; nb++) {
                Oa[mi][nb][0] *= al0; Oa[mi][nb][1] *= al0;
                Oa[mi][nb][2] *= al1; Oa[mi][nb][3] *= al1;
            }
        }
        __syncwarp();

        // PV phase: V fragments loaded ONCE per kk, used by both m-blocks
        #pragma unroll
        for (int kk = 0; kk < 8; kk++) {
            uint32_t aP0[4], aP1[4];
            ldsm4(aP0[0], aP0[1], aP0[2], aP0[3], pAdrM[0] + kk * 32);
            ldsm4(aP1[0], aP1[1], aP1[2], aP1[3], pAdrM[1] + kk * 32);
            uint32_t bv[16];
            const uint32_t vAdr = vsAdr + vRow + vCol + (uint32_t)(kk * 32);
            #pragma unroll
            for (int j = 0; j < 4; j++)
                ldsm4(bv[4*j], bv[4*j+1], bv[4*j+2], bv[4*j+3],
                      vAdr + (uint32_t)(j * 16 * APAD * 4));
            #pragma unroll
            for (int nb = 0; nb < 8; nb++) {
                const uint32_t* bp = &bv[4 * (nb >> 1) + 2 * (nb & 1)];
                mma_tf32(Oa[0][nb], aP0, bp);
                mma_tf32(Oa[1][nb], aP1, bp);
            }
        }
        __syncwarp();
    }

    // Finalize both m-blocks
    #pragma unroll
    for (int mi = 0; mi < 2; mi++) {
        float l0 = ls[mi][0], l1 = ls[mi][1];
        l0 += __shfl_xor_sync(0xffffffffu, l0, 1);
        l0 += __shfl_xor_sync(0xffffffffu, l0, 2);
        l1 += __shfl_xor_sync(0xffffffffu, l1, 1);
        l1 += __shfl_xor_sync(0xffffffffu, l1, 2);
        float inv0 = 1.f / l0, inv1 = 1.f / l1;

        float* Ob = g_O + ((size_t)(b * SEQ + q0 + w * 32 + mi * 16)) * DMODEL + h * DH;
        #pragma unroll
        for (int nb = 0; nb < 8; nb++) {
            *(float2*)(Ob + (size_t)gid * DMODEL + nb * 8 + 2 * tid4) =
                make_float2(to_tf32_rn(Oa[mi][nb][0] * inv0), to_tf32_rn(Oa[mi][nb][1] * inv0));
            *(float2*)(Ob + (size_t)(gid + 8) * DMODEL + nb * 8 + 2 * tid4) =
                make_float2(to_tf32_rn(Oa[mi][nb][2] * inv1), to_tf32_rn(Oa[mi][nb][3] * inv1));
        }
    }
}

// ---------------------------------------------------------------------------
// Launch:  inputs 0=queries 1=keys 2=values 3=masks 4=Wq 5=Wk 6=Wv 7=Wo
// ---------------------------------------------------------------------------
extern "C" void kernel_launch(void* const* d_in, const int* in_sizes, int n_in,
                              void* d_out, int out_size) {
    const int* masks = (const int*)d_in[3];
    float* out = (float*)d_out;

    float *gq, *gk, *gvt, *go, *gwt, *gr;
    cudaGetSymbolAddress((void**)&gq,  g_Q);
    cudaGetSymbolAddress((void**)&gk,  g_K);
    cudaGetSymbolAddress((void**)&gvt, g_Vt);
    cudaGetSymbolAddress((void**)&go,  g_O);
    cudaGetSymbolAddress((void**)&gwt, g_Wt);
    cudaGetSymbolAddress((void**)&gr,  g_R);

    cudaFuncSetAttribute(gemm_tf32_kernel<true>,
                         cudaFuncAttributeMaxDynamicSharedMemorySize, SM_GEMM_BYTES);
    cudaFuncSetAttribute(gemm_tf32_kernel<false>,
                         cudaFuncAttributeMaxDynamicSharedMemorySize, SM_GEMM_BYTES);
    cudaFuncSetAttribute(attn_mma_kernel,
                         cudaFuncAttributeMaxDynamicSharedMemorySize, ATT_SMEM);

    R3 rp;
    for (int i = 0; i < 3; i++) rp.s[i] = (const float4*)d_in[i];
    round3_kernel<<<dim3(512, 1, 3), 256>>>(rp);

    WPtrs wp;
    for (int i = 0; i < 4; i++) {
        wp.s[i] = (const float*)d_in[4 + i];
        wp.d[i] = gwt + (size_t)i * DMODEL * DMODEL;
    }
    transpose_k<<<dim3(32, 32, 4), dim3(32, 8)>>>(wp);

    const size_t NN  = (size_t)MTOT * DMODEL;
    const size_t NN2 = (size_t)DMODEL * DMODEL;

    GemmBatch g1;
    g1.A[0] = gr + 0 * NN; g1.B[0] = gwt + 0 * NN2; g1.C[0] = gq;
    g1.A[1] = gr + 1 * NN; g1.B[1] = gwt + 1 * NN2; g1.C[1] = gk;
    g1.A[2] = gr + 2 * NN; g1.B[2] = gwt + 2 * NN2; g1.C[2] = gvt;
    gemm_tf32_kernel<true><<<dim3(DMODEL / BN, MTOT / BM, 3), 256, SM_GEMM_BYTES>>>(g1);

    dim3 ga(SEQ / ATT_BQ, NH, BATCH);  // (16, 16, 2) = 512 CTAs, 128 threads
    attn_mma_kernel<<<ga, 128, ATT_SMEM>>>(masks);

    GemmBatch g2;
    g2.A[0] = go; g2.B[0] = gwt + 3 * NN2; g2.C[0] = out;
    g2.A[1] = g2.A[2] = nullptr; g2.B[1] = g2.B[2] = nullptr; g2.C[1] = g2.C[2] = nullptr;
    gemm_tf32_kernel<false><<<dim3(DMODEL / BN, MTOT / BM, 1), 256, SM_GEMM_BYTES>>>(g2);
}

// round 13
// speedup vs baseline: 5.2802x; 1.2407x over previous
#include <cuda_runtime.h>
#include <math_constants.h>
#include <cstdint>

#define SEQ    2048
#define DMODEL 1024
#define NH     16
#define DH     64
#define BATCH  2
#define MTOT   (BATCH*SEQ)   // 4096 rows

// ---------------------------------------------------------------------------
// Device scratch (allocation-free rule)
// ---------------------------------------------------------------------------
__device__ float g_Q[(size_t)MTOT*DMODEL];
__device__ float g_K[(size_t)MTOT*DMODEL];
__device__ float g_Kc[(size_t)MTOT*DMODEL];        // compacted K (kept keys first)
__device__ float g_Vt[(size_t)BATCH*NH*DH*SEQ];    // V output, [b,h][d][token]
__device__ float g_Vtc[(size_t)BATCH*NH*DH*SEQ];   // compacted Vt
__device__ float g_O[(size_t)MTOT*DMODEL];
__device__ float g_Wt[4][(size_t)DMODEL*DMODEL];   // transposed+rounded weights [N][K]
__device__ float g_R[3][(size_t)MTOT*DMODEL];      // rounded inputs (q,k,v)
__device__ int   g_idx[BATCH*SEQ];                 // kept-token old indices
__device__ int   g_nkeep[BATCH];

// ---------------------------------------------------------------------------
// Helpers
// ---------------------------------------------------------------------------
__device__ __forceinline__ uint32_t smem_u32(const void* p) {
    uint32_t a;
    asm("{ .reg .u64 t; cvta.to.shared.u64 t, %1; cvt.u32.u64 %0, t; }" : "=r"(a) : "l"(p));
    return a;
}
__device__ __forceinline__ float to_tf32_rn(float x) {
    uint32_t r;
    asm("cvt.rna.tf32.f32 %0, %1;" : "=r"(r) : "f"(x));
    return __uint_as_float(r);
}
__device__ __forceinline__ float ex2f(float y) {    // 2^y via MUFU
    float r;
    asm("ex2.approx.f32 %0, %1;" : "=f"(r) : "f"(y));
    return r;
}
__device__ __forceinline__ void cp16(uint32_t dst, const void* src) {
    asm volatile("cp.async.cg.shared.global [%0], [%1], 16;" :: "r"(dst), "l"(src));
}
#define CP_COMMIT() asm volatile("cp.async.commit_group;" ::: "memory")
#define CP_WAIT0()  asm volatile("cp.async.wait_group 0;" ::: "memory")
#define CP_WAIT1()  asm volatile("cp.async.wait_group 1;" ::: "memory")

// ldmatrix x4: four 8x8 b16 tiles == four 8x4 f32 tiles (tf32 fragment layout)
__device__ __forceinline__ void ldsm4(uint32_t& r0, uint32_t& r1, uint32_t& r2,
                                      uint32_t& r3, uint32_t addr) {
    asm volatile("ldmatrix.sync.aligned.m8n8.x4.shared.b16 {%0,%1,%2,%3}, [%4];"
                 : "=r"(r0), "=r"(r1), "=r"(r2), "=r"(r3) : "r"(addr));
}

// m16n8k8 tf32 mma (baseline PTX, sm_80+)
__device__ __forceinline__ void mma_tf32(float* c, const uint32_t* a, const uint32_t* b) {
    asm volatile(
        "mma.sync.aligned.m16n8k8.row.col.f32.tf32.tf32.f32 "
        "{%0,%1,%2,%3}, {%4,%5,%6,%7}, {%8,%9}, {%0,%1,%2,%3};"
        : "+f"(c[0]), "+f"(c[1]), "+f"(c[2]), "+f"(c[3])
        : "r"(a[0]), "r"(a[1]), "r"(a[2]), "r"(a[3]), "r"(b[0]), "r"(b[1]));
}

// ---------------------------------------------------------------------------
// Round queries/keys/values to tf32
// ---------------------------------------------------------------------------
struct R3 { const float4* s[3]; };

__global__ __launch_bounds__(256) void round3_kernel(R3 p) {
    const int z = blockIdx.z;
    const float4* S = p.s[z];
    float4* D = (float4*)(g_R[z]);
    const int n4 = MTOT * DMODEL / 4;
    for (int i = blockIdx.x * 256 + threadIdx.x; i < n4; i += gridDim.x * 256) {
        float4 v = S[i];
        v.x = to_tf32_rn(v.x); v.y = to_tf32_rn(v.y);
        v.z = to_tf32_rn(v.z); v.w = to_tf32_rn(v.w);
        D[i] = v;
    }
}

// ---------------------------------------------------------------------------
// Weight transpose + round: Wt[n][k] = tf32(W[k][n])
// ---------------------------------------------------------------------------
struct WPtrs { const float* s[4]; float* d[4]; };

__global__ __launch_bounds__(256) void transpose_k(WPtrs p) {
    __shared__ float tile[32][33];
    const float* S = p.s[blockIdx.z];
    float*       D = p.d[blockIdx.z];
    int x0 = blockIdx.x * 32, y0 = blockIdx.y * 32;
    int tx = threadIdx.x, ty = threadIdx.y;          // (32, 8)
    #pragma unroll
    for (int j = 0; j < 32; j += 8)
        tile[ty + j][tx] = S[(size_t)(y0 + ty + j) * DMODEL + x0 + tx];
    __syncthreads();
    #pragma unroll
    for (int j = 0; j < 32; j += 8)
        D[(size_t)(x0 + ty + j) * DMODEL + y0 + tx] = to_tf32_rn(tile[tx][ty + j]);
}

// ---------------------------------------------------------------------------
// Mask compaction: per batch, list of kept token indices + count
// ---------------------------------------------------------------------------
__global__ void compact_idx_kernel(const int* __restrict__ masks) {
    const int b = blockIdx.x;
    const int lane = threadIdx.x;   // 32 threads
    int off = 0;
    for (int c = 0; c < SEQ; c += 32) {
        int m = masks[b * SEQ + c + lane];
        unsigned bal = __ballot_sync(0xffffffffu, m != 0);
        int pre = __popc(bal & ((1u << lane) - 1));
        if (m) g_idx[b * SEQ + off + pre] = c + lane;
        off += __popc(bal);
    }
    if (lane == 0) g_nkeep[b] = off;
}

// Compact K rows: g_Kc[b][j][:] = g_K[b][idx[j]][:]; zero-pad to 64-boundary
__global__ __launch_bounds__(256) void gather_k_kernel() {
    const int row = blockIdx.x;          // 0..MTOT-1
    const int b = row >> 11;             // /SEQ
    const int j = row & (SEQ - 1);
    const int nk = g_nkeep[b];
    const int pad = (nk + 63) & ~63;
    if (j >= pad) return;
    float4* dst = (float4*)(g_Kc + (size_t)row * DMODEL);
    if (j < nk) {
        const float4* src = (const float4*)(g_K +
            ((size_t)(b * SEQ + g_idx[b * SEQ + j])) * DMODEL);
        dst[threadIdx.x] = src[threadIdx.x];
    } else {
        dst[threadIdx.x] = make_float4(0.f, 0.f, 0.f, 0.f);
    }
}

// Compact Vt columns: g_Vtc[row][j] = g_Vt[row][idx[j]]; zero-pad tail
__global__ __launch_bounds__(256) void gather_vt_kernel() {
    const int row = blockIdx.y;                       // 0..BATCH*NH*DH-1
    const int b = row >> 10;                          // /(NH*DH)
    const int j = blockIdx.x * 256 + threadIdx.x;     // 0..SEQ-1
    const int nk = g_nkeep[b];
    const int pad = (nk + 63) & ~63;
    if (j >= pad) return;
    float v = 0.f;
    if (j < nk) v = g_Vt[(size_t)row * SEQ + g_idx[b * SEQ + j]];
    g_Vtc[(size_t)row * SEQ + j] = v;
}

// ---------------------------------------------------------------------------
// tf32 tensor-core GEMM (cp.async 3-stage, ldmatrix fragments). Unchanged.
// Batched over blockIdx.z. z==2 (V projection) stores transposed to g_Vt.
// ---------------------------------------------------------------------------
#define BM 128
#define BN 128
#define BK 32
#define KT_GEMM (DMODEL / BK)          // 32
#define ROWP 36
#define ROWB (ROWP * 4)                // 144 bytes per row
#define TILE_F (128 * ROWP)
#define GSTG 3
#define SM_GEMM_BYTES (GSTG * 2 * TILE_F * 4)   // 110592 B

struct GemmBatch { const float* A[3]; const float* B[3]; float* C[3]; };

template<bool ROUND>
__global__ __launch_bounds__(256, 2) void gemm_tf32_kernel(GemmBatch gb) {
    extern __shared__ float sm[];
    const uint32_t sb = smem_u32(sm);

    const float* __restrict__ A  = gb.A[blockIdx.z];
    const float* __restrict__ Bt = gb.B[blockIdx.z];
    float* __restrict__ C        = gb.C[blockIdx.z];

    const int t     = threadIdx.x;
    const int wid   = t >> 5;
    const int lane  = t & 31;
    const int wm    = wid & 1;
    const int wn    = wid >> 1;
    const int lane4 = lane >> 2;
    const int lanek = lane & 3;
    const int lm    = lane >> 3;
    const int lr    = lane & 7;
    const int m0 = blockIdx.y * BM;
    const int n0 = blockIdx.x * BN;
    const int lrow = t >> 3, lc4 = t & 7;

    const uint32_t aOff = (uint32_t)((wm * 64 + (lm & 1) * 8 + lr) * ROWB + (lm >> 1) * 16);
    const uint32_t bOff = (uint32_t)((wn * 32 + (lm >> 1) * 8 + lr) * ROWB + (lm & 1) * 16);

    float acc[4][4][4];
    #pragma unroll
    for (int mi = 0; mi < 4; mi++)
        #pragma unroll
        for (int ni = 0; ni < 4; ni++)
            #pragma unroll
            for (int f = 0; f < 4; f++) acc[mi][ni][f] = 0.f;

    auto issue = [&](int kt, int s) {
        const float* Ap = A  + (size_t)m0 * DMODEL + kt * BK;
        const float* Bp = Bt + (size_t)n0 * DMODEL + kt * BK;
        #pragma unroll
        for (int i = 0; i < 4; i++) {
            int row = lrow + i * 32;
            cp16(sb + (uint32_t)((s * 2 * TILE_F + row * ROWP + lc4 * 4) * 4),
                 Ap + (size_t)row * DMODEL + lc4 * 4);
            cp16(sb + (uint32_t)((s * 2 * TILE_F + TILE_F + row * ROWP + lc4 * 4) * 4),
                 Bp + (size_t)row * DMODEL + lc4 * 4);
        }
        CP_COMMIT();
    };

    issue(0, 0);
    issue(1, 1);

    for (int kt = 0; kt < KT_GEMM; kt++) {
        const int s = kt % 3;
        if (kt < KT_GEMM - 1) CP_WAIT1(); else CP_WAIT0();
        __syncthreads();
        if (kt + 2 < KT_GEMM) issue(kt + 2, (kt + 2) % 3);

        const uint32_t aAdr = sb + (uint32_t)(s * 2 * TILE_F * 4) + aOff;
        const uint32_t bAdr = aAdr - aOff + (uint32_t)(TILE_F * 4) + bOff;
        #pragma unroll
        for (int ks = 0; ks < 4; ks++) {
            uint32_t a[4][4], b[4][2];
            #pragma unroll
            for (int mi = 0; mi < 4; mi++)
                ldsm4(a[mi][0], a[mi][1], a[mi][2], a[mi][3],
                      aAdr + (uint32_t)(mi * 16 * ROWB + ks * 32));
            ldsm4(b[0][0], b[0][1], b[1][0], b[1][1], bAdr + (uint32_t)(ks * 32));
            ldsm4(b[2][0], b[2][1], b[3][0], b[3][1],
                  bAdr + (uint32_t)(16 * ROWB + ks * 32));
            #pragma unroll
            for (int mi = 0; mi < 4; mi++)
                #pragma unroll
                for (int ni = 0; ni < 4; ni++)
                    mma_tf32(acc[mi][ni], a[mi], b[ni]);
        }
    }

    const bool vt = ROUND && (blockIdx.z == 2);
    #pragma unroll
    for (int mi = 0; mi < 4; mi++) {
        #pragma unroll
        for (int ni = 0; ni < 4; ni++) {
            int row = m0 + wm * 64 + mi * 16 + lane4;
            int col = n0 + wn * 32 + ni * 8 + 2 * lanek;
            float v0 = acc[mi][ni][0], v1 = acc[mi][ni][1];
            float v2 = acc[mi][ni][2], v3 = acc[mi][ni][3];
            if (ROUND) {
                v0 = to_tf32_rn(v0); v1 = to_tf32_rn(v1);
                v2 = to_tf32_rn(v2); v3 = to_tf32_rn(v3);
            }
            if (vt) {
                int bb = row >> 11, tok = row & (SEQ - 1);
                int hh = col >> 6,  dh  = col & (DH - 1);
                float* base = g_Vt + ((size_t)(bb * NH + hh) * DH + dh) * SEQ + tok;
                base[0]       = v0;
                base[SEQ]     = v1;
                base[8]       = v2;
                base[SEQ + 8] = v3;
            } else {
                *(float2*)(C + (size_t)row * DMODEL + col)       = make_float2(v0, v1);
                *(float2*)(C + (size_t)(row + 8) * DMODEL + col) = make_float2(v2, v3);
            }
        }
    }
}

// ---------------------------------------------------------------------------
// Tensor-core flash attention over COMPACTED KV (~half the tiles).
// 32 q-rows per warp; 4 warps/CTA; base-2 softmax; ldmatrix everywhere.
// Tail tile gets -1e30 bias for j >= nkeep (zero-padded K/V rows).
// ---------------------------------------------------------------------------
#define ATT_BQ   128
#define ATT_BKV  64
#define APAD     68
#define ATT_KV_F (2 * ATT_BKV * APAD)
#define ATT_P_OFF (2 * ATT_KV_F)
#define ATT_MSK_OFF (ATT_P_OFF + ATT_BQ * APAD)
#define ATT_SMEM ((ATT_MSK_OFF + SEQ) * 4)            // 112640 B

__global__ __launch_bounds__(128, 2) void attn_mma_kernel() {
    extern __shared__ float smf[];
    const uint32_t sb = smem_u32(smf);
    float* msf = smf + ATT_MSK_OFF;

    const int t    = threadIdx.x;
    const int w    = t >> 5;
    const int lane = t & 31;
    const int gid  = lane >> 2;
    const int tid4 = lane & 3;
    const int lm   = lane >> 3;
    const int lr   = lane & 7;
    const int b  = blockIdx.z;
    const int h  = blockIdx.y;
    const int q0 = blockIdx.x * ATT_BQ;

    const int nk  = g_nkeep[b];
    const int pad = (nk + 63) & ~63;

    for (int i = t; i < pad; i += 128)
        msf[i] = (i < nk) ? 0.f : -1e30f;

    const uint32_t kCol = (uint32_t)(((lm >> 1) * 8 + (lm & 1) * 4) * 4);
    const uint32_t vRow = (uint32_t)(((lm >> 1) * 8 + lr) * APAD * 4);
    const uint32_t vCol = (uint32_t)((lm & 1) * 16);
    uint32_t pAdrM[2];
    #pragma unroll
    for (int mi = 0; mi < 2; mi++)
        pAdrM[mi] = sb + (uint32_t)((ATT_P_OFF + (w * 32 + mi * 16 + (lm & 1) * 8 + lr) * APAD) * 4)
                  + (uint32_t)((lm >> 1) * 16);

    const float qs = 0.125f * 1.4426950408889634f;
    uint32_t aQ[2][8][4];
    {
        const float* Qb = g_Q + ((size_t)(b * SEQ + q0 + w * 32)) * DMODEL + h * DH;
        #pragma unroll
        for (int mi = 0; mi < 2; mi++) {
            const float* Qm = Qb + (size_t)(mi * 16) * DMODEL;
            #pragma unroll
            for (int kk = 0; kk < 8; kk++) {
                int c = kk * 8 + tid4;
                aQ[mi][kk][0] = __float_as_uint(to_tf32_rn(qs * Qm[(size_t)gid       * DMODEL + c    ]));
                aQ[mi][kk][1] = __float_as_uint(to_tf32_rn(qs * Qm[(size_t)(gid + 8) * DMODEL + c    ]));
                aQ[mi][kk][2] = __float_as_uint(to_tf32_rn(qs * Qm[(size_t)gid       * DMODEL + c + 4]));
                aQ[mi][kk][3] = __float_as_uint(to_tf32_rn(qs * Qm[(size_t)(gid + 8) * DMODEL + c + 4]));
            }
        }
    }

    float Oa[2][8][4];
    #pragma unroll
    for (int mi = 0; mi < 2; mi++)
        #pragma unroll
        for (int nb = 0; nb < 8; nb++)
            #pragma unroll
            for (int f = 0; f < 4; f++) Oa[mi][nb][f] = 0.f;
    float mx[2][2] = {{-1e30f, -1e30f}, {-1e30f, -1e30f}};
    float ls[2][2] = {{0.f, 0.f}, {0.f, 0.f}};

    float* Pw = smf + ATT_P_OFF + w * 32 * APAD;

    auto issue_kv = [&](int kv0, int s) {
        const float* Kb  = g_Kc  + ((size_t)(b * SEQ + kv0)) * DMODEL + h * DH;
        const float* Vtb = g_Vtc + ((size_t)(b * NH + h) * DH) * SEQ + kv0;
        #pragma unroll
        for (int i = 0; i < 8; i++) {
            int idx = i * 128 + t;
            int row = idx >> 4, c4 = (idx & 15) * 4;
            cp16(sb + (uint32_t)((s * ATT_KV_F + row * APAD + c4) * 4),
                 Kb + (size_t)row * DMODEL + c4);
            cp16(sb + (uint32_t)((s * ATT_KV_F + ATT_BKV * APAD + row * APAD + c4) * 4),
                 Vtb + (size_t)row * SEQ + c4);
        }
        CP_COMMIT();
    };

    if (pad > 0) issue_kv(0, 0);

    for (int kv0 = 0; kv0 < pad; kv0 += ATT_BKV) {
        const int s = (kv0 >> 6) & 1;
        CP_WAIT0();
        __syncthreads();
        if (kv0 + ATT_BKV < pad) issue_kv(kv0 + ATT_BKV, s ^ 1);

        const uint32_t ksAdr = sb + (uint32_t)(s * ATT_KV_F * 4);
        const uint32_t vsAdr = ksAdr + (uint32_t)(ATT_BKV * APAD * 4);

        // S phase: K fragments loaded ONCE per nb, used by both m-blocks
        float sc[2][8][4];
        #pragma unroll
        for (int nb = 0; nb < 8; nb++) {
            uint32_t bk[16];
            const uint32_t rowAdr = ksAdr + (uint32_t)(((nb * 8 + lr) * APAD) * 4) + kCol;
            #pragma unroll
            for (int i = 0; i < 4; i++)
                ldsm4(bk[4*i], bk[4*i+1], bk[4*i+2], bk[4*i+3], rowAdr + i * 64);
            #pragma unroll
            for (int f = 0; f < 4; f++) { sc[0][nb][f] = 0.f; sc[1][nb][f] = 0.f; }
            #pragma unroll
            for (int kk = 0; kk < 8; kk++) {
                const uint32_t* bp = &bk[4 * (kk >> 1) + 2 * (kk & 1)];
                mma_tf32(sc[0][nb], aQ[0][kk], bp);
                mma_tf32(sc[1][nb], aQ[1][kk], bp);
            }
        }

        // Tail tile only: apply -1e30 bias for padded columns
        if (kv0 + ATT_BKV > nk) {
            #pragma unroll
            for (int mi = 0; mi < 2; mi++)
                #pragma unroll
                for (int nb = 0; nb < 8; nb++) {
                    float2 mm = *(const float2*)(msf + kv0 + nb * 8 + 2 * tid4);
                    sc[mi][nb][0] += mm.x; sc[mi][nb][1] += mm.y;
                    sc[mi][nb][2] += mm.x; sc[mi][nb][3] += mm.y;
                }
        }

        // Softmax per m-block
        #pragma unroll
        for (int mi = 0; mi < 2; mi++) {
            float tm0 = -1e30f, tm1 = -1e30f;
            #pragma unroll
            for (int nb = 0; nb < 8; nb++) {
                tm0 = fmaxf(tm0, fmaxf(sc[mi][nb][0], sc[mi][nb][1]));
                tm1 = fmaxf(tm1, fmaxf(sc[mi][nb][2], sc[mi][nb][3]));
            }
            tm0 = fmaxf(tm0, __shfl_xor_sync(0xffffffffu, tm0, 1));
            tm0 = fmaxf(tm0, __shfl_xor_sync(0xffffffffu, tm0, 2));
            tm1 = fmaxf(tm1, __shfl_xor_sync(0xffffffffu, tm1, 1));
            tm1 = fmaxf(tm1, __shfl_xor_sync(0xffffffffu, tm1, 2));

            float mn0 = fmaxf(mx[mi][0], tm0), mn1 = fmaxf(mx[mi][1], tm1);
            float al0 = ex2f(mx[mi][0] - mn0), al1 = ex2f(mx[mi][1] - mn1);
            mx[mi][0] = mn0; mx[mi][1] = mn1;

            float lp0 = 0.f, lp1 = 0.f;
            #pragma unroll
            for (int nb = 0; nb < 8; nb++) {
                float p0 = ex2f(sc[mi][nb][0] - mn0);
                float p1 = ex2f(sc[mi][nb][1] - mn0);
                float p2 = ex2f(sc[mi][nb][2] - mn1);
                float p3 = ex2f(sc[mi][nb][3] - mn1);
                lp0 += p0 + p1; lp1 += p2 + p3;
                *(float2*)(Pw + (mi * 16 + gid) * APAD + nb * 8 + 2 * tid4) =
                    make_float2(to_tf32_rn(p0), to_tf32_rn(p1));
                *(float2*)(Pw + (mi * 16 + gid + 8) * APAD + nb * 8 + 2 * tid4) =
                    make_float2(to_tf32_rn(p2), to_tf32_rn(p3));
            }
            ls[mi][0] = ls[mi][0] * al0 + lp0;
            ls[mi][1] = ls[mi][1] * al1 + lp1;
            #pragma unroll
            for (int nb = 0; nb < 8; nb++) {
                Oa[mi][nb][0] *= al0; Oa[mi][nb][1] *= al0;
                Oa[mi][nb][2] *= al1; Oa[mi][nb][3] *= al1;
            }
        }
        __syncwarp();

        // PV phase: V fragments loaded ONCE per kk, used by both m-blocks
        #pragma unroll
        for (int kk = 0; kk < 8; kk++) {
            uint32_t aP0[4], aP1[4];
            ldsm4(aP0[0], aP0[1], aP0[2], aP0[3], pAdrM[0] + kk * 32);
            ldsm4(aP1[0], aP1[1], aP1[2], aP1[3], pAdrM[1] + kk * 32);
            uint32_t bv[16];
            const uint32_t vAdr = vsAdr + vRow + vCol + (uint32_t)(kk * 32);
            #pragma unroll
            for (int j = 0; j < 4; j++)
                ldsm4(bv[4*j], bv[4*j+1], bv[4*j+2], bv[4*j+3],
                      vAdr + (uint32_t)(j * 16 * APAD * 4));
            #pragma unroll
            for (int nb = 0; nb < 8; nb++) {
                const uint32_t* bp = &bv[4 * (nb >> 1) + 2 * (nb & 1)];
                mma_tf32(Oa[0][nb], aP0, bp);
                mma_tf32(Oa[1][nb], aP1, bp);
            }
        }
        __syncwarp();
    }

    // Finalize both m-blocks
    #pragma unroll
    for (int mi = 0; mi < 2; mi++) {
        float l0 = ls[mi][0], l1 = ls[mi][1];
        l0 += __shfl_xor_sync(0xffffffffu, l0, 1);
        l0 += __shfl_xor_sync(0xffffffffu, l0, 2);
        l1 += __shfl_xor_sync(0xffffffffu, l1, 1);
        l1 += __shfl_xor_sync(0xffffffffu, l1, 2);
        float inv0 = 1.f / l0, inv1 = 1.f / l1;

        float* Ob = g_O + ((size_t)(b * SEQ + q0 + w * 32 + mi * 16)) * DMODEL + h * DH;
        #pragma unroll
        for (int nb = 0; nb < 8; nb++) {
            *(float2*)(Ob + (size_t)gid * DMODEL + nb * 8 + 2 * tid4) =
                make_float2(to_tf32_rn(Oa[mi][nb][0] * inv0), to_tf32_rn(Oa[mi][nb][1] * inv0));
            *(float2*)(Ob + (size_t)(gid + 8) * DMODEL + nb * 8 + 2 * tid4) =
                make_float2(to_tf32_rn(Oa[mi][nb][2] * inv1), to_tf32_rn(Oa[mi][nb][3] * inv1));
        }
    }
}

// ---------------------------------------------------------------------------
// Launch:  inputs 0=queries 1=keys 2=values 3=masks 4=Wq 5=Wk 6=Wv 7=Wo
// ---------------------------------------------------------------------------
extern "C" void kernel_launch(void* const* d_in, const int* in_sizes, int n_in,
                              void* d_out, int out_size) {
    const int* masks = (const int*)d_in[3];
    float* out = (float*)d_out;

    float *gq, *gk, *gvt, *go, *gwt, *gr;
    cudaGetSymbolAddress((void**)&gq,  g_Q);
    cudaGetSymbolAddress((void**)&gk,  g_K);
    cudaGetSymbolAddress((void**)&gvt, g_Vt);
    cudaGetSymbolAddress((void**)&go,  g_O);
    cudaGetSymbolAddress((void**)&gwt, g_Wt);
    cudaGetSymbolAddress((void**)&gr,  g_R);

    cudaFuncSetAttribute(gemm_tf32_kernel<true>,
                         cudaFuncAttributeMaxDynamicSharedMemorySize, SM_GEMM_BYTES);
    cudaFuncSetAttribute(gemm_tf32_kernel<false>,
                         cudaFuncAttributeMaxDynamicSharedMemorySize, SM_GEMM_BYTES);
    cudaFuncSetAttribute(attn_mma_kernel,
                         cudaFuncAttributeMaxDynamicSharedMemorySize, ATT_SMEM);

    R3 rp;
    for (int i = 0; i < 3; i++) rp.s[i] = (const float4*)d_in[i];
    round3_kernel<<<dim3(512, 1, 3), 256>>>(rp);

    WPtrs wp;
    for (int i = 0; i < 4; i++) {
        wp.s[i] = (const float*)d_in[4 + i];
        wp.d[i] = gwt + (size_t)i * DMODEL * DMODEL;
    }
    transpose_k<<<dim3(32, 32, 4), dim3(32, 8)>>>(wp);

    // Mask compaction index (independent of GEMMs)
    compact_idx_kernel<<<BATCH, 32>>>(masks);

    const size_t NN  = (size_t)MTOT * DMODEL;
    const size_t NN2 = (size_t)DMODEL * DMODEL;

    GemmBatch g1;
    g1.A[0] = gr + 0 * NN; g1.B[0] = gwt + 0 * NN2; g1.C[0] = gq;
    g1.A[1] = gr + 1 * NN; g1.B[1] = gwt + 1 * NN2; g1.C[1] = gk;
    g1.A[2] = gr + 2 * NN; g1.B[2] = gwt + 2 * NN2; g1.C[2] = gvt;
    gemm_tf32_kernel<true><<<dim3(DMODEL / BN, MTOT / BM, 3), 256, SM_GEMM_BYTES>>>(g1);

    // Compact K rows and Vt columns to kept keys only
    gather_k_kernel<<<MTOT, 256>>>();
    gather_vt_kernel<<<dim3(SEQ / 256, BATCH * NH * DH), 256>>>();

    dim3 ga(SEQ / ATT_BQ, NH, BATCH);  // (16, 16, 2) = 512 CTAs, 128 threads
    attn_mma_kernel<<<ga, 128, ATT_SMEM>>>();

    GemmBatch g2;
    g2.A[0] = go; g2.B[0] = gwt + 3 * NN2; g2.C[0] = out;
    g2.A[1] = g2.A[2] = nullptr; g2.B[1] = g2.B[2] = nullptr; g2.C[1] = g2.C[2] = nullptr;
    gemm_tf32_kernel<false><<<dim3(DMODEL / BN, MTOT / BM, 1), 256, SM_GEMM_BYTES>>>(g2);
}

// round 15
// speedup vs baseline: 6.3285x; 1.1985x over previous
#include <cuda_runtime.h>
#include <math_constants.h>
#include <cstdint>

#define SEQ    2048
#define DMODEL 1024
#define NH     16
#define DH     64
#define BATCH  2
#define MTOT   (BATCH*SEQ)   // 4096 rows

// ---------------------------------------------------------------------------
// Device scratch (allocation-free rule)
// ---------------------------------------------------------------------------
__device__ float g_Q[(size_t)MTOT*DMODEL];
__device__ float g_Kc[(size_t)MTOT*DMODEL];        // compacted projected K
__device__ float g_Vtc[(size_t)BATCH*NH*DH*SEQ];   // compacted projected V, transposed
__device__ float g_O[(size_t)MTOT*DMODEL];
__device__ float g_Wt[4][(size_t)DMODEL*DMODEL];   // transposed+rounded weights [N][K]
__device__ float g_R[3][(size_t)MTOT*DMODEL];      // rounded q; compacted+rounded k,v inputs
__device__ int   g_idx[BATCH*SEQ];                 // kept-token old indices
__device__ int   g_nkeep[BATCH];

// ---------------------------------------------------------------------------
// Helpers
// ---------------------------------------------------------------------------
__device__ __forceinline__ uint32_t smem_u32(const void* p) {
    uint32_t a;
    asm("{ .reg .u64 t; cvta.to.shared.u64 t, %1; cvt.u32.u64 %0, t; }" : "=r"(a) : "l"(p));
    return a;
}
__device__ __forceinline__ float to_tf32_rn(float x) {
    uint32_t r;
    asm("cvt.rna.tf32.f32 %0, %1;" : "=r"(r) : "f"(x));
    return __uint_as_float(r);
}
__device__ __forceinline__ float ex2f(float y) {    // 2^y via MUFU
    float r;
    asm("ex2.approx.f32 %0, %1;" : "=f"(r) : "f"(y));
    return r;
}
__device__ __forceinline__ void cp16(uint32_t dst, const void* src) {
    asm volatile("cp.async.cg.shared.global [%0], [%1], 16;" :: "r"(dst), "l"(src));
}
#define CP_COMMIT() asm volatile("cp.async.commit_group;" ::: "memory")
#define CP_WAIT0()  asm volatile("cp.async.wait_group 0;" ::: "memory")
#define CP_WAIT1()  asm volatile("cp.async.wait_group 1;" ::: "memory")

// ldmatrix x4: four 8x8 b16 tiles == four 8x4 f32 tiles (tf32 fragment layout)
__device__ __forceinline__ void ldsm4(uint32_t& r0, uint32_t& r1, uint32_t& r2,
                                      uint32_t& r3, uint32_t addr) {
    asm volatile("ldmatrix.sync.aligned.m8n8.x4.shared.b16 {%0,%1,%2,%3}, [%4];"
                 : "=r"(r0), "=r"(r1), "=r"(r2), "=r"(r3) : "r"(addr));
}

// m16n8k8 tf32 mma (baseline PTX, sm_80+)
__device__ __forceinline__ void mma_tf32(float* c, const uint32_t* a, const uint32_t* b) {
    asm volatile(
        "mma.sync.aligned.m16n8k8.row.col.f32.tf32.tf32.f32 "
        "{%0,%1,%2,%3}, {%4,%5,%6,%7}, {%8,%9}, {%0,%1,%2,%3};"
        : "+f"(c[0]), "+f"(c[1]), "+f"(c[2]), "+f"(c[3])
        : "r"(a[0]), "r"(a[1]), "r"(a[2]), "r"(a[3]), "r"(b[0]), "r"(b[1]));
}

// ---------------------------------------------------------------------------
// Round queries to tf32 (keys/values are rounded inside compact_in)
// ---------------------------------------------------------------------------
__global__ __launch_bounds__(256) void roundq_kernel(const float4* __restrict__ S) {
    float4* D = (float4*)(g_R[0]);
    const int n4 = MTOT * DMODEL / 4;
    for (int i = blockIdx.x * 256 + threadIdx.x; i < n4; i += gridDim.x * 256) {
        float4 v = S[i];
        v.x = to_tf32_rn(v.x); v.y = to_tf32_rn(v.y);
        v.z = to_tf32_rn(v.z); v.w = to_tf32_rn(v.w);
        D[i] = v;
    }
}

// ---------------------------------------------------------------------------
// Weight transpose + round: Wt[n][k] = tf32(W[k][n])
// ---------------------------------------------------------------------------
struct WPtrs { const float* s[4]; float* d[4]; };

__global__ __launch_bounds__(256) void transpose_k(WPtrs p) {
    __shared__ float tile[32][33];
    const float* S = p.s[blockIdx.z];
    float*       D = p.d[blockIdx.z];
    int x0 = blockIdx.x * 32, y0 = blockIdx.y * 32;
    int tx = threadIdx.x, ty = threadIdx.y;          // (32, 8)
    #pragma unroll
    for (int j = 0; j < 32; j += 8)
        tile[ty + j][tx] = S[(size_t)(y0 + ty + j) * DMODEL + x0 + tx];
    __syncthreads();
    #pragma unroll
    for (int j = 0; j < 32; j += 8)
        D[(size_t)(x0 + ty + j) * DMODEL + y0 + tx] = to_tf32_rn(tile[tx][ty + j]);
}

// ---------------------------------------------------------------------------
// Mask compaction: per batch, list of kept token indices + count
// ---------------------------------------------------------------------------
__global__ void compact_idx_kernel(const int* __restrict__ masks) {
    const int b = blockIdx.x;
    const int lane = threadIdx.x;   // 32 threads
    int off = 0;
    for (int c = 0; c < SEQ; c += 32) {
        int m = masks[b * SEQ + c + lane];
        unsigned bal = __ballot_sync(0xffffffffu, m != 0);
        int pre = __popc(bal & ((1u << lane) - 1));
        if (m) g_idx[b * SEQ + off + pre] = c + lane;
        off += __popc(bal);
    }
    if (lane == 0) g_nkeep[b] = off;
}

// Compact + round INPUT key/value rows (z: 0=keys->g_R[1], 1=values->g_R[2]).
// Zero-pads up to 128-row (GEMM tile) boundary.
struct C2 { const float* s[2]; };

__global__ __launch_bounds__(256) void compact_in_kernel(C2 p) {
    const int z = blockIdx.z;
    const int row = blockIdx.x;          // 0..MTOT-1
    const int b = row >> 11;
    const int j = row & (SEQ - 1);
    const int nk = g_nkeep[b];
    const int pad = (nk + 127) & ~127;
    if (j >= pad) return;
    float4* dst = (float4*)(g_R[1 + z] + (size_t)row * DMODEL);
    if (j < nk) {
        const float4* src = (const float4*)(p.s[z] +
            ((size_t)(b * SEQ + g_idx[b * SEQ + j])) * DMODEL);
        float4 v = src[threadIdx.x];
        v.x = to_tf32_rn(v.x); v.y = to_tf32_rn(v.y);
        v.z = to_tf32_rn(v.z); v.w = to_tf32_rn(v.w);
        dst[threadIdx.x] = v;
    } else {
        dst[threadIdx.x] = make_float4(0.f, 0.f, 0.f, 0.f);
    }
}

// ---------------------------------------------------------------------------
// tf32 tensor-core GEMM (cp.async 3-stage, ldmatrix fragments).
// Batched over blockIdx.z. z==2 (V projection) stores transposed to g_Vtc.
// COMPACT: z>=1 CTAs early-exit beyond the batch's padded keep count.
// ---------------------------------------------------------------------------
#define BM 128
#define BN 128
#define BK 32
#define KT_GEMM (DMODEL / BK)          // 32
#define ROWP 36
#define ROWB (ROWP * 4)                // 144 bytes per row
#define TILE_F (128 * ROWP)
#define GSTG 3
#define SM_GEMM_BYTES (GSTG * 2 * TILE_F * 4)   // 110592 B

struct GemmBatch { const float* A[3]; const float* B[3]; float* C[3]; };

template<bool COMPACT>
__global__ __launch_bounds__(256, 2) void gemm_tf32_kernel(GemmBatch gb) {
    extern __shared__ float sm[];
    const uint32_t sb = smem_u32(sm);

    const int m0 = blockIdx.y * BM;
    if (COMPACT && blockIdx.z != 0) {
        const int b = m0 >> 11;
        const int pad = (g_nkeep[b] + 127) & ~127;
        if ((m0 & (SEQ - 1)) >= pad) return;   // tile entirely beyond kept rows
    }

    const float* __restrict__ A  = gb.A[blockIdx.z];
    const float* __restrict__ Bt = gb.B[blockIdx.z];
    float* __restrict__ C        = gb.C[blockIdx.z];

    const int t     = threadIdx.x;
    const int wid   = t >> 5;
    const int lane  = t & 31;
    const int wm    = wid & 1;
    const int wn    = wid >> 1;
    const int lane4 = lane >> 2;
    const int lanek = lane & 3;
    const int lm    = lane >> 3;
    const int lr    = lane & 7;
    const int n0 = blockIdx.x * BN;
    const int lrow = t >> 3, lc4 = t & 7;

    const uint32_t aOff = (uint32_t)((wm * 64 + (lm & 1) * 8 + lr) * ROWB + (lm >> 1) * 16);
    const uint32_t bOff = (uint32_t)((wn * 32 + (lm >> 1) * 8 + lr) * ROWB + (lm & 1) * 16);

    float acc[4][4][4];
    #pragma unroll
    for (int mi = 0; mi < 4; mi++)
        #pragma unroll
        for (int ni = 0; ni < 4; ni++)
            #pragma unroll
            for (int f = 0; f < 4; f++) acc[mi][ni][f] = 0.f;

    auto issue = [&](int kt, int s) {
        const float* Ap = A  + (size_t)m0 * DMODEL + kt * BK;
        const float* Bp = Bt + (size_t)n0 * DMODEL + kt * BK;
        #pragma unroll
        for (int i = 0; i < 4; i++) {
            int row = lrow + i * 32;
            cp16(sb + (uint32_t)((s * 2 * TILE_F + row * ROWP + lc4 * 4) * 4),
                 Ap + (size_t)row * DMODEL + lc4 * 4);
            cp16(sb + (uint32_t)((s * 2 * TILE_F + TILE_F + row * ROWP + lc4 * 4) * 4),
                 Bp + (size_t)row * DMODEL + lc4 * 4);
        }
        CP_COMMIT();
    };

    issue(0, 0);
    issue(1, 1);

    for (int kt = 0; kt < KT_GEMM; kt++) {
        const int s = kt % 3;
        if (kt < KT_GEMM - 1) CP_WAIT1(); else CP_WAIT0();
        __syncthreads();
        if (kt + 2 < KT_GEMM) issue(kt + 2, (kt + 2) % 3);

        const uint32_t aAdr = sb + (uint32_t)(s * 2 * TILE_F * 4) + aOff;
        const uint32_t bAdr = aAdr - aOff + (uint32_t)(TILE_F * 4) + bOff;
        #pragma unroll
        for (int ks = 0; ks < 4; ks++) {
            uint32_t a[4][4], b[4][2];
            #pragma unroll
            for (int mi = 0; mi < 4; mi++)
                ldsm4(a[mi][0], a[mi][1], a[mi][2], a[mi][3],
                      aAdr + (uint32_t)(mi * 16 * ROWB + ks * 32));
            ldsm4(b[0][0], b[0][1], b[1][0], b[1][1], bAdr + (uint32_t)(ks * 32));
            ldsm4(b[2][0], b[2][1], b[3][0], b[3][1],
                  bAdr + (uint32_t)(16 * ROWB + ks * 32));
            #pragma unroll
            for (int mi = 0; mi < 4; mi++)
                #pragma unroll
                for (int ni = 0; ni < 4; ni++)
                    mma_tf32(acc[mi][ni], a[mi], b[ni]);
        }
    }

    const bool vt = COMPACT && (blockIdx.z == 2);
    #pragma unroll
    for (int mi = 0; mi < 4; mi++) {
        #pragma unroll
        for (int ni = 0; ni < 4; ni++) {
            int row = m0 + wm * 64 + mi * 16 + lane4;
            int col = n0 + wn * 32 + ni * 8 + 2 * lanek;
            float v0 = acc[mi][ni][0], v1 = acc[mi][ni][1];
            float v2 = acc[mi][ni][2], v3 = acc[mi][ni][3];
            if (COMPACT) {
                v0 = to_tf32_rn(v0); v1 = to_tf32_rn(v1);
                v2 = to_tf32_rn(v2); v3 = to_tf32_rn(v3);
            }
            if (vt) {
                int bb = row >> 11, tok = row & (SEQ - 1);   // compacted token idx
                int hh = col >> 6,  dh  = col & (DH - 1);
                float* base = g_Vtc + ((size_t)(bb * NH + hh) * DH + dh) * SEQ + tok;
                base[0]       = v0;
                base[SEQ]     = v1;
                base[8]       = v2;
                base[SEQ + 8] = v3;
            } else {
                *(float2*)(C + (size_t)row * DMODEL + col)       = make_float2(v0, v1);
                *(float2*)(C + (size_t)(row + 8) * DMODEL + col) = make_float2(v2, v3);
            }
        }
    }
}

// ---------------------------------------------------------------------------
// Tensor-core flash attention over COMPACTED KV (unchanged from R12).
// ---------------------------------------------------------------------------
#define ATT_BQ   128
#define ATT_BKV  64
#define APAD     68
#define ATT_KV_F (2 * ATT_BKV * APAD)
#define ATT_P_OFF (2 * ATT_KV_F)
#define ATT_MSK_OFF (ATT_P_OFF + ATT_BQ * APAD)
#define ATT_SMEM ((ATT_MSK_OFF + SEQ) * 4)            // 112640 B

__global__ __launch_bounds__(128, 2) void attn_mma_kernel() {
    extern __shared__ float smf[];
    const uint32_t sb = smem_u32(smf);
    float* msf = smf + ATT_MSK_OFF;

    const int t    = threadIdx.x;
    const int w    = t >> 5;
    const int lane = t & 31;
    const int gid  = lane >> 2;
    const int tid4 = lane & 3;
    const int lm   = lane >> 3;
    const int lr   = lane & 7;
    const int b  = blockIdx.z;
    const int h  = blockIdx.y;
    const int q0 = blockIdx.x * ATT_BQ;

    const int nk  = g_nkeep[b];
    const int pad = (nk + 63) & ~63;

    for (int i = t; i < pad; i += 128)
        msf[i] = (i < nk) ? 0.f : -1e30f;

    const uint32_t kCol = (uint32_t)(((lm >> 1) * 8 + (lm & 1) * 4) * 4);
    const uint32_t vRow = (uint32_t)(((lm >> 1) * 8 + lr) * APAD * 4);
    const uint32_t vCol = (uint32_t)((lm & 1) * 16);
    uint32_t pAdrM[2];
    #pragma unroll
    for (int mi = 0; mi < 2; mi++)
        pAdrM[mi] = sb + (uint32_t)((ATT_P_OFF + (w * 32 + mi * 16 + (lm & 1) * 8 + lr) * APAD) * 4)
                  + (uint32_t)((lm >> 1) * 16);

    const float qs = 0.125f * 1.4426950408889634f;
    uint32_t aQ[2][8][4];
    {
        const float* Qb = g_Q + ((size_t)(b * SEQ + q0 + w * 32)) * DMODEL + h * DH;
        #pragma unroll
        for (int mi = 0; mi < 2; mi++) {
            const float* Qm = Qb + (size_t)(mi * 16) * DMODEL;
            #pragma unroll
            for (int kk = 0; kk < 8; kk++) {
                int c = kk * 8 + tid4;
                aQ[mi][kk][0] = __float_as_uint(to_tf32_rn(qs * Qm[(size_t)gid       * DMODEL + c    ]));
                aQ[mi][kk][1] = __float_as_uint(to_tf32_rn(qs * Qm[(size_t)(gid + 8) * DMODEL + c    ]));
                aQ[mi][kk][2] = __float_as_uint(to_tf32_rn(qs * Qm[(size_t)gid       * DMODEL + c + 4]));
                aQ[mi][kk][3] = __float_as_uint(to_tf32_rn(qs * Qm[(size_t)(gid + 8) * DMODEL + c + 4]));
            }
        }
    }

    float Oa[2][8][4];
    #pragma unroll
    for (int mi = 0; mi < 2; mi++)
        #pragma unroll
        for (int nb = 0; nb < 8; nb++)
            #pragma unroll
            for (int f = 0; f < 4; f++) Oa[mi][nb][f] = 0.f;
    float mx[2][2] = {{-1e30f, -1e30f}, {-1e30f, -1e30f}};
    float ls[2][2] = {{0.f, 0.f}, {0.f, 0.f}};

    float* Pw = smf + ATT_P_OFF + w * 32 * APAD;

    auto issue_kv = [&](int kv0, int s) {
        const float* Kb  = g_Kc  + ((size_t)(b * SEQ + kv0)) * DMODEL + h * DH;
        const float* Vtb = g_Vtc + ((size_t)(b * NH + h) * DH) * SEQ + kv0;
        #pragma unroll
        for (int i = 0; i < 8; i++) {
            int idx = i * 128 + t;
            int row = idx >> 4, c4 = (idx & 15) * 4;
            cp16(sb + (uint32_t)((s * ATT_KV_F + row * APAD + c4) * 4),
                 Kb + (size_t)row * DMODEL + c4);
            cp16(sb + (uint32_t)((s * ATT_KV_F + ATT_BKV * APAD + row * APAD + c4) * 4),
                 Vtb + (size_t)row * SEQ + c4);
        }
        CP_COMMIT();
    };

    if (pad > 0) issue_kv(0, 0);

    for (int kv0 = 0; kv0 < pad; kv0 += ATT_BKV) {
        const int s = (kv0 >> 6) & 1;
        CP_WAIT0();
        __syncthreads();
        if (kv0 + ATT_BKV < pad) issue_kv(kv0 + ATT_BKV, s ^ 1);

        const uint32_t ksAdr = sb + (uint32_t)(s * ATT_KV_F * 4);
        const uint32_t vsAdr = ksAdr + (uint32_t)(ATT_BKV * APAD * 4);

        // S phase
        float sc[2][8][4];
        #pragma unroll
        for (int nb = 0; nb < 8; nb++) {
            uint32_t bk[16];
            const uint32_t rowAdr = ksAdr + (uint32_t)(((nb * 8 + lr) * APAD) * 4) + kCol;
            #pragma unroll
            for (int i = 0; i < 4; i++)
                ldsm4(bk[4*i], bk[4*i+1], bk[4*i+2], bk[4*i+3], rowAdr + i * 64);
            #pragma unroll
            for (int f = 0; f < 4; f++) { sc[0][nb][f] = 0.f; sc[1][nb][f] = 0.f; }
            #pragma unroll
            for (int kk = 0; kk < 8; kk++) {
                const uint32_t* bp = &bk[4 * (kk >> 1) + 2 * (kk & 1)];
                mma_tf32(sc[0][nb], aQ[0][kk], bp);
                mma_tf32(sc[1][nb], aQ[1][kk], bp);
            }
        }

        // Tail tile only: -1e30 bias for padded columns
        if (kv0 + ATT_BKV > nk) {
            #pragma unroll
            for (int mi = 0; mi < 2; mi++)
                #pragma unroll
                for (int nb = 0; nb < 8; nb++) {
                    float2 mm = *(const float2*)(msf + kv0 + nb * 8 + 2 * tid4);
                    sc[mi][nb][0] += mm.x; sc[mi][nb][1] += mm.y;
                    sc[mi][nb][2] += mm.x; sc[mi][nb][3] += mm.y;
                }
        }

        // Softmax per m-block
        #pragma unroll
        for (int mi = 0; mi < 2; mi++) {
            float tm0 = -1e30f, tm1 = -1e30f;
            #pragma unroll
            for (int nb = 0; nb < 8; nb++) {
                tm0 = fmaxf(tm0, fmaxf(sc[mi][nb][0], sc[mi][nb][1]));
                tm1 = fmaxf(tm1, fmaxf(sc[mi][nb][2], sc[mi][nb][3]));
            }
            tm0 = fmaxf(tm0, __shfl_xor_sync(0xffffffffu, tm0, 1));
            tm0 = fmaxf(tm0, __shfl_xor_sync(0xffffffffu, tm0, 2));
            tm1 = fmaxf(tm1, __shfl_xor_sync(0xffffffffu, tm1, 1));
            tm1 = fmaxf(tm1, __shfl_xor_sync(0xffffffffu, tm1, 2));

            float mn0 = fmaxf(mx[mi][0], tm0), mn1 = fmaxf(mx[mi][1], tm1);
            float al0 = ex2f(mx[mi][0] - mn0), al1 = ex2f(mx[mi][1] - mn1);
            mx[mi][0] = mn0; mx[mi][1] = mn1;

            float lp0 = 0.f, lp1 = 0.f;
            #pragma unroll
            for (int nb = 0; nb < 8; nb++) {
                float p0 = ex2f(sc[mi][nb][0] - mn0);
                float p1 = ex2f(sc[mi][nb][1] - mn0);
                float p2 = ex2f(sc[mi][nb][2] - mn1);
                float p3 = ex2f(sc[mi][nb][3] - mn1);
                lp0 += p0 + p1; lp1 += p2 + p3;
                *(float2*)(Pw + (mi * 16 + gid) * APAD + nb * 8 + 2 * tid4) =
                    make_float2(to_tf32_rn(p0), to_tf32_rn(p1));
                *(float2*)(Pw + (mi * 16 + gid + 8) * APAD + nb * 8 + 2 * tid4) =
                    make_float2(to_tf32_rn(p2), to_tf32_rn(p3));
            }
            ls[mi][0] = ls[mi][0] * al0 + lp0;
            ls[mi][1] = ls[mi][1] * al1 + lp1;
            #pragma unroll
            for (int nb = 0; nb < 8; nb++) {
                Oa[mi][nb][0] *= al0; Oa[mi][nb][1] *= al0;
                Oa[mi][nb][2] *= al1; Oa[mi][nb][3] *= al1;
            }
        }
        __syncwarp();

        // PV phase
        #pragma unroll
        for (int kk = 0; kk < 8; kk++) {
            uint32_t aP0[4], aP1[4];
            ldsm4(aP0[0], aP0[1], aP0[2], aP0[3], pAdrM[0] + kk * 32);
            ldsm4(aP1[0], aP1[1], aP1[2], aP1[3], pAdrM[1] + kk * 32);
            uint32_t bv[16];
            const uint32_t vAdr = vsAdr + vRow + vCol + (uint32_t)(kk * 32);
            #pragma unroll
            for (int j = 0; j < 4; j++)
                ldsm4(bv[4*j], bv[4*j+1], bv[4*j+2], bv[4*j+3],
                      vAdr + (uint32_t)(j * 16 * APAD * 4));
            #pragma unroll
            for (int nb = 0; nb < 8; nb++) {
                const uint32_t* bp = &bv[4 * (nb >> 1) + 2 * (nb & 1)];
                mma_tf32(Oa[0][nb], aP0, bp);
                mma_tf32(Oa[1][nb], aP1, bp);
            }
        }
        __syncwarp();
    }

    // Finalize
    #pragma unroll
    for (int mi = 0; mi < 2; mi++) {
        float l0 = ls[mi][0], l1 = ls[mi][1];
        l0 += __shfl_xor_sync(0xffffffffu, l0, 1);
        l0 += __shfl_xor_sync(0xffffffffu, l0, 2);
        l1 += __shfl_xor_sync(0xffffffffu, l1, 1);
        l1 += __shfl_xor_sync(0xffffffffu, l1, 2);
        float inv0 = 1.f / l0, inv1 = 1.f / l1;

        float* Ob = g_O + ((size_t)(b * SEQ + q0 + w * 32 + mi * 16)) * DMODEL + h * DH;
        #pragma unroll
        for (int nb = 0; nb < 8; nb++) {
            *(float2*)(Ob + (size_t)gid * DMODEL + nb * 8 + 2 * tid4) =
                make_float2(to_tf32_rn(Oa[mi][nb][0] * inv0), to_tf32_rn(Oa[mi][nb][1] * inv0));
            *(float2*)(Ob + (size_t)(gid + 8) * DMODEL + nb * 8 + 2 * tid4) =
                make_float2(to_tf32_rn(Oa[mi][nb][2] * inv1), to_tf32_rn(Oa[mi][nb][3] * inv1));
        }
    }
}

// ---------------------------------------------------------------------------
// Launch:  inputs 0=queries 1=keys 2=values 3=masks 4=Wq 5=Wk 6=Wv 7=Wo
// ---------------------------------------------------------------------------
extern "C" void kernel_launch(void* const* d_in, const int* in_sizes, int n_in,
                              void* d_out, int out_size) {
    const int* masks = (const int*)d_in[3];
    float* out = (float*)d_out;

    float *gq, *gkc, *go, *gwt, *gr;
    cudaGetSymbolAddress((void**)&gq,  g_Q);
    cudaGetSymbolAddress((void**)&gkc, g_Kc);
    cudaGetSymbolAddress((void**)&go,  g_O);
    cudaGetSymbolAddress((void**)&gwt, g_Wt);
    cudaGetSymbolAddress((void**)&gr,  g_R);

    cudaFuncSetAttribute(gemm_tf32_kernel<true>,
                         cudaFuncAttributeMaxDynamicSharedMemorySize, SM_GEMM_BYTES);
    cudaFuncSetAttribute(gemm_tf32_kernel<false>,
                         cudaFuncAttributeMaxDynamicSharedMemorySize, SM_GEMM_BYTES);
    cudaFuncSetAttribute(attn_mma_kernel,
                         cudaFuncAttributeMaxDynamicSharedMemorySize, ATT_SMEM);

    roundq_kernel<<<512, 256>>>((const float4*)d_in[0]);

    WPtrs wp;
    for (int i = 0; i < 4; i++) {
        wp.s[i] = (const float*)d_in[4 + i];
        wp.d[i] = gwt + (size_t)i * DMODEL * DMODEL;
    }
    transpose_k<<<dim3(32, 32, 4), dim3(32, 8)>>>(wp);

    // Compaction: index, then compact+round key/value INPUT rows
    compact_idx_kernel<<<BATCH, 32>>>(masks);
    C2 c2;
    c2.s[0] = (const float*)d_in[1];
    c2.s[1] = (const float*)d_in[2];
    compact_in_kernel<<<dim3(MTOT, 1, 2), 256>>>(c2);

    const size_t NN  = (size_t)MTOT * DMODEL;
    const size_t NN2 = (size_t)DMODEL * DMODEL;

    // Fused Q/K/V projections; z>=1 operate on compacted rows (early-exit rest)
    GemmBatch g1;
    g1.A[0] = gr + 0 * NN; g1.B[0] = gwt + 0 * NN2; g1.C[0] = gq;
    g1.A[1] = gr + 1 * NN; g1.B[1] = gwt + 1 * NN2; g1.C[1] = gkc;
    g1.A[2] = gr + 2 * NN; g1.B[2] = gwt + 2 * NN2; g1.C[2] = nullptr;  // vt store
    gemm_tf32_kernel<true><<<dim3(DMODEL / BN, MTOT / BM, 3), 256, SM_GEMM_BYTES>>>(g1);

    dim3 ga(SEQ / ATT_BQ, NH, BATCH);  // (16, 16, 2) = 512 CTAs, 128 threads
    attn_mma_kernel<<<ga, 128, ATT_SMEM>>>();

    GemmBatch g2;
    g2.A[0] = go; g2.B[0] = gwt + 3 * NN2; g2.C[0] = out;
    g2.A[1] = g2.A[2] = nullptr; g2.B[1] = g2.B[2] = nullptr; g2.C[1] = g2.C[2] = nullptr;
    gemm_tf32_kernel<false><<<dim3(DMODEL / BN, MTOT / BM, 1), 256, SM_GEMM_BYTES>>>(g2);
}